// round 2
// baseline (speedup 1.0000x reference)
#include <cuda_runtime.h>

// Problem constants
#define PB 8
#define PS 1024
#define PD 1024
#define PH 16
#define PHD 64
#define PM (PB * PS)   // 8192 rows

// Scratch (device globals: no allocation allowed)
__device__ float g_Q[PM * PD];
__device__ float g_K[PM * PD];
__device__ float g_V[PM * PD];
__device__ float g_Hd[PM * PD];

// ---------------------------------------------------------------------------
// GEMM: C[M x N] = A[M x K] @ W[K x N] + bias[N]
// BM=BN=128, BK=16, 256 threads, 8x8 micro-tile (4+4 split at offset 64).
// A tile stored k-major in smem with XOR swizzle (row ^ (k<<2)) to avoid
// transpose-store bank conflicts. B tile stored naturally.
// M, N given by grid (blockIdx.y * 128, blockIdx.x * 128); K passed in.
// ---------------------------------------------------------------------------
__global__ __launch_bounds__(256, 2) void gemm_bias_kernel(
    const float* __restrict__ A, int lda,
    const float* __restrict__ W, int ldw,
    const float* __restrict__ bias,
    float* __restrict__ C, int ldc, int Kdim)
{
    __shared__ float As[16 * 128];
    __shared__ float Bs[16 * 128];

    const int tid = threadIdx.x;
    const int tx = tid & 15;        // col group 0..15
    const int ty = tid >> 4;        // row group 0..15
    const int m0 = blockIdx.y * 128;
    const int n0 = blockIdx.x * 128;

    float acc[8][8];
#pragma unroll
    for (int i = 0; i < 8; i++)
#pragma unroll
        for (int j = 0; j < 8; j++) acc[i][j] = 0.f;

    for (int k0 = 0; k0 < Kdim; k0 += 16) {
        // Load A tile [128 rows x 16 k], store transposed (k-major) + swizzle
#pragma unroll
        for (int i = 0; i < 2; i++) {
            int idx = tid + 256 * i;
            int row = idx >> 2;            // 0..127
            int kq  = (idx & 3) << 2;      // 0,4,8,12
            float4 v = *reinterpret_cast<const float4*>(
                A + (m0 + row) * lda + k0 + kq);
            As[(kq + 0) * 128 + (row ^ ((kq + 0) << 2))] = v.x;
            As[(kq + 1) * 128 + (row ^ ((kq + 1) << 2))] = v.y;
            As[(kq + 2) * 128 + (row ^ ((kq + 2) << 2))] = v.z;
            As[(kq + 3) * 128 + (row ^ ((kq + 3) << 2))] = v.w;
        }
        // Load B tile [16 k x 128 n]
#pragma unroll
        for (int i = 0; i < 2; i++) {
            int idx = tid + 256 * i;
            int krow = idx >> 5;           // 0..15
            int nq = (idx & 31) << 2;      // 0..124
            *reinterpret_cast<float4*>(&Bs[krow * 128 + nq]) =
                *reinterpret_cast<const float4*>(W + (k0 + krow) * ldw + n0 + nq);
        }
        __syncthreads();

#pragma unroll
        for (int kk = 0; kk < 16; kk++) {
            const int sw = kk << 2;
            float a[8], b[8];
            *reinterpret_cast<float4*>(&a[0]) =
                *reinterpret_cast<const float4*>(&As[kk * 128 + ((ty * 4) ^ sw)]);
            *reinterpret_cast<float4*>(&a[4]) =
                *reinterpret_cast<const float4*>(&As[kk * 128 + ((64 + ty * 4) ^ sw)]);
            *reinterpret_cast<float4*>(&b[0]) =
                *reinterpret_cast<const float4*>(&Bs[kk * 128 + tx * 4]);
            *reinterpret_cast<float4*>(&b[4]) =
                *reinterpret_cast<const float4*>(&Bs[kk * 128 + 64 + tx * 4]);
#pragma unroll
            for (int i2 = 0; i2 < 8; i2++)
#pragma unroll
                for (int j = 0; j < 8; j++) acc[i2][j] += a[i2] * b[j];
        }
        __syncthreads();
    }

    // Epilogue: add bias, write C
    float4 bi0 = *reinterpret_cast<const float4*>(bias + n0 + tx * 4);
    float4 bi1 = *reinterpret_cast<const float4*>(bias + n0 + 64 + tx * 4);
#pragma unroll
    for (int i = 0; i < 8; i++) {
        int row = m0 + ((i < 4) ? (ty * 4 + i) : (64 + ty * 4 + (i - 4)));
        float* Cr = C + row * ldc + n0;
        float4 o0 = make_float4(acc[i][0] + bi0.x, acc[i][1] + bi0.y,
                                acc[i][2] + bi0.z, acc[i][3] + bi0.w);
        float4 o1 = make_float4(acc[i][4] + bi1.x, acc[i][5] + bi1.y,
                                acc[i][6] + bi1.z, acc[i][7] + bi1.w);
        *reinterpret_cast<float4*>(Cr + tx * 4) = o0;
        *reinterpret_cast<float4*>(Cr + 64 + tx * 4) = o1;
    }
}

// ---------------------------------------------------------------------------
// Flash attention: one block per (b, h, 64-query tile). 256 threads.
// S tile = 64q x 64k, 4x4 micro-tile per thread (tx=cols, ty=rows).
// Row groups = 16 consecutive lanes -> intra-warp shfl reductions.
// smem: Qs (natural [q][d]), Ks (K transposed [d][k] with swizzle k^(d&60),
//       later reused for V natural [k][d]), Ps (probabilities).
// Exactly 48KB static smem.
// ---------------------------------------------------------------------------
__global__ __launch_bounds__(256) void attn_kernel(
    const float* __restrict__ Qg, const float* __restrict__ Kg,
    const float* __restrict__ Vg, float* __restrict__ Og)
{
    __shared__ float Qs[64 * 64];
    __shared__ float Ks[64 * 64];
    __shared__ float Ps[64 * 64];

    const int tid = threadIdx.x;
    const int tx = tid & 15;
    const int ty = tid >> 4;
    const int qt = blockIdx.x;    // 0..15
    const int h  = blockIdx.y;    // 0..15
    const int b  = blockIdx.z;    // 0..7

    const int qbase = b * PS + qt * 64;   // row offset into [PM] rows
    const int col0  = h * PHD;

    // Load Q tile [64 q][64 d]
#pragma unroll
    for (int i = 0; i < 4; i++) {
        int idx = tid + 256 * i;
        int row = idx >> 4;
        int d4  = (idx & 15) << 2;
        *reinterpret_cast<float4*>(&Qs[row * 64 + d4]) =
            *reinterpret_cast<const float4*>(Qg + (qbase + row) * PD + col0 + d4);
    }

    float m_i[4], l_i[4], o[4][4];
#pragma unroll
    for (int r = 0; r < 4; r++) {
        m_i[r] = -1e30f;
        l_i[r] = 0.f;
#pragma unroll
        for (int c = 0; c < 4; c++) o[r][c] = 0.f;
    }
    const float scale = 0.125f;  // 1/sqrt(64)

    for (int kt = 0; kt < 16; kt++) {
        const int kbase = b * PS + kt * 64;
        __syncthreads();  // Q tile visible (kt=0); prev PV done with Ks (kt>0)

        // Load K tile transposed [d][k] with XOR swizzle k ^ (d & 60)
#pragma unroll
        for (int i = 0; i < 4; i++) {
            int idx = tid + 256 * i;
            int row = idx >> 4;            // key index 0..63
            int d4  = (idx & 15) << 2;     // d, multiple of 4
            float4 v = *reinterpret_cast<const float4*>(
                Kg + (kbase + row) * PD + col0 + d4);
            Ks[(d4 + 0) * 64 + (row ^ d4)] = v.x;
            Ks[(d4 + 1) * 64 + (row ^ d4)] = v.y;
            Ks[(d4 + 2) * 64 + (row ^ d4)] = v.z;
            Ks[(d4 + 3) * 64 + (row ^ d4)] = v.w;
        }
        __syncthreads();

        // S = Q @ K^T (4x4 per thread)
        float s[4][4];
#pragma unroll
        for (int r = 0; r < 4; r++)
#pragma unroll
            for (int c = 0; c < 4; c++) s[r][c] = 0.f;

#pragma unroll 4
        for (int d = 0; d < 64; d++) {
            float kvv[4];
            *reinterpret_cast<float4*>(kvv) =
                *reinterpret_cast<const float4*>(&Ks[d * 64 + ((tx * 4) ^ (d & 60))]);
#pragma unroll
            for (int r = 0; r < 4; r++) {
                float qv = Qs[(ty * 4 + r) * 64 + d];
#pragma unroll
                for (int c = 0; c < 4; c++) s[r][c] += qv * kvv[c];
            }
        }

        // Online softmax update (row-wise; rows owned within 16-lane group)
        float alpha[4];
#pragma unroll
        for (int r = 0; r < 4; r++) {
#pragma unroll
            for (int c = 0; c < 4; c++) s[r][c] *= scale;
            float mx = fmaxf(fmaxf(s[r][0], s[r][1]), fmaxf(s[r][2], s[r][3]));
            mx = fmaxf(mx, __shfl_xor_sync(0xffffffffu, mx, 1));
            mx = fmaxf(mx, __shfl_xor_sync(0xffffffffu, mx, 2));
            mx = fmaxf(mx, __shfl_xor_sync(0xffffffffu, mx, 4));
            mx = fmaxf(mx, __shfl_xor_sync(0xffffffffu, mx, 8));
            float newm = fmaxf(m_i[r], mx);
            alpha[r] = __expf(m_i[r] - newm);
            m_i[r] = newm;
            float rs = 0.f;
#pragma unroll
            for (int c = 0; c < 4; c++) {
                s[r][c] = __expf(s[r][c] - newm);
                rs += s[r][c];
            }
            rs += __shfl_xor_sync(0xffffffffu, rs, 1);
            rs += __shfl_xor_sync(0xffffffffu, rs, 2);
            rs += __shfl_xor_sync(0xffffffffu, rs, 4);
            rs += __shfl_xor_sync(0xffffffffu, rs, 8);
            l_i[r] = l_i[r] * alpha[r] + rs;
#pragma unroll
            for (int c = 0; c < 4; c++) o[r][c] *= alpha[r];
        }

        __syncthreads();  // all threads done reading Ks (K)

        // Write P to smem; load V tile into Ks (natural [k][d])
#pragma unroll
        for (int r = 0; r < 4; r++)
            *reinterpret_cast<float4*>(&Ps[(ty * 4 + r) * 64 + tx * 4]) =
                make_float4(s[r][0], s[r][1], s[r][2], s[r][3]);
#pragma unroll
        for (int i = 0; i < 4; i++) {
            int idx = tid + 256 * i;
            int row = idx >> 4;
            int d4  = (idx & 15) << 2;
            *reinterpret_cast<float4*>(&Ks[row * 64 + d4]) =
                *reinterpret_cast<const float4*>(
                    Vg + (kbase + row) * PD + col0 + d4);
        }
        __syncthreads();

        // O += P @ V
#pragma unroll 4
        for (int k = 0; k < 64; k++) {
            float vvv[4];
            *reinterpret_cast<float4*>(vvv) =
                *reinterpret_cast<const float4*>(&Ks[k * 64 + tx * 4]);
#pragma unroll
            for (int r = 0; r < 4; r++) {
                float pv = Ps[(ty * 4 + r) * 64 + k];
#pragma unroll
                for (int c = 0; c < 4; c++) o[r][c] += pv * vvv[c];
            }
        }
    }

    // Normalize and write heads output [b, s, h*64 + d]
#pragma unroll
    for (int r = 0; r < 4; r++) {
        float inv = 1.f / l_i[r];
        int row = qbase + ty * 4 + r;
        *reinterpret_cast<float4*>(Og + row * PD + col0 + tx * 4) =
            make_float4(o[r][0] * inv, o[r][1] * inv,
                        o[r][2] * inv, o[r][3] * inv);
    }
}

// ---------------------------------------------------------------------------
// Launch: 5 kernels, default stream, graph-capturable.
// Inputs (metadata order): query, value, Wq, bq, Wkv, bkv, Wo, bo
// ---------------------------------------------------------------------------
extern "C" void kernel_launch(void* const* d_in, const int* in_sizes, int n_in,
                              void* d_out, int out_size)
{
    const float* query = (const float*)d_in[0];
    const float* value = (const float*)d_in[1];
    const float* Wq    = (const float*)d_in[2];
    const float* bq    = (const float*)d_in[3];
    const float* Wkv   = (const float*)d_in[4];
    const float* bkv   = (const float*)d_in[5];
    const float* Wo    = (const float*)d_in[6];
    const float* bo    = (const float*)d_in[7];
    float* out = (float*)d_out;

    float *Qb, *Kb, *Vb, *Hb;
    cudaGetSymbolAddress((void**)&Qb, g_Q);
    cudaGetSymbolAddress((void**)&Kb, g_K);
    cudaGetSymbolAddress((void**)&Vb, g_V);
    cudaGetSymbolAddress((void**)&Hb, g_Hd);

    dim3 gemm_grid(PD / 128, PM / 128);   // (8, 64)
    dim3 attn_grid(PS / 64, PH, PB);      // (16, 16, 8)

    // Q = query @ Wq + bq
    gemm_bias_kernel<<<gemm_grid, 256>>>(query, PD, Wq, PD, bq, Qb, PD, PD);
    // K = value @ Wkv[:, :D] + bkv[:D]
    gemm_bias_kernel<<<gemm_grid, 256>>>(value, PD, Wkv, 2 * PD, bkv, Kb, PD, PD);
    // V = value @ Wkv[:, D:] + bkv[D:]
    gemm_bias_kernel<<<gemm_grid, 256>>>(value, PD, Wkv + PD, 2 * PD, bkv + PD,
                                         Vb, PD, PD);
    // heads = softmax(Q K^T / sqrt(hd)) V
    attn_kernel<<<attn_grid, 256>>>(Qb, Kb, Vb, Hb);
    // out = heads @ Wo + bo
    gemm_bias_kernel<<<gemm_grid, 256>>>(Hb, PD, Wo, PD, bo, out, PD, PD);
}

// round 7
// speedup vs baseline: 2.4927x; 2.4927x over previous
#include <cuda_runtime.h>
#include <cstdint>

// Problem constants
#define PB 8
#define PS 1024
#define PD 1024
#define PH 16
#define PHD 64
#define PM (PB * PS)   // 8192 rows

// Scratch (device globals: no allocation allowed)
__device__ float g_Q[PM * PD];
__device__ float g_K[PM * PD];
__device__ float g_V[PM * PD];
__device__ float g_Hd[PM * PD];

// ---------------------------------------------------------------------------
// Helpers (compute_103-safe PTX only: mma.sync, ldmatrix, cp.async)
// ---------------------------------------------------------------------------
__device__ __forceinline__ uint32_t smem_u32(const void* p) {
    uint32_t a;
    asm("{ .reg .u64 t; cvta.to.shared.u64 t, %1; cvt.u32.u64 %0, t; }"
        : "=r"(a) : "l"(p));
    return a;
}

__device__ __forceinline__ void cp_async16(uint32_t saddr, const void* gaddr) {
    asm volatile("cp.async.cg.shared.global [%0], [%1], 16;"
                 :: "r"(saddr), "l"(gaddr));
}
#define CP_COMMIT() asm volatile("cp.async.commit_group;" ::: "memory")
#define CP_WAIT0()  asm volatile("cp.async.wait_group 0;" ::: "memory")

__device__ __forceinline__ void ldm_x4(uint32_t* r, uint32_t addr) {
    asm volatile("ldmatrix.sync.aligned.m8n8.x4.shared.b16 {%0,%1,%2,%3}, [%4];"
                 : "=r"(r[0]), "=r"(r[1]), "=r"(r[2]), "=r"(r[3]) : "r"(addr));
}
__device__ __forceinline__ void ldm_x2(uint32_t* r, uint32_t addr) {
    asm volatile("ldmatrix.sync.aligned.m8n8.x2.shared.b16 {%0,%1}, [%2];"
                 : "=r"(r[0]), "=r"(r[1]) : "r"(addr));
}

// Round-to-nearest fp32 -> tf32 (bits usable directly as mma operand)
__device__ __forceinline__ uint32_t f2tf32(float f) {
    uint32_t r;
    asm("cvt.rna.tf32.f32 %0, %1;" : "=r"(r) : "f"(f));
    return r;
}

__device__ __forceinline__ void mma_tf32(float* d, const uint32_t* a,
                                         const uint32_t* b) {
    asm volatile(
        "mma.sync.aligned.m16n8k8.row.col.f32.tf32.tf32.f32 "
        "{%0,%1,%2,%3}, {%4,%5,%6,%7}, {%8,%9}, {%0,%1,%2,%3};"
        : "+f"(d[0]), "+f"(d[1]), "+f"(d[2]), "+f"(d[3])
        : "r"(a[0]), "r"(a[1]), "r"(a[2]), "r"(a[3]), "r"(b[0]), "r"(b[1]));
}

// ---------------------------------------------------------------------------
// tf32 mma.sync GEMM (split-A for precision):
//   C[M x N] = A[M x K] @ W[K x N] + bias
// CTA tile 128x128, BK=32, 8 warps (2M x 4N), warp tile 64x32.
// A split into hi+lo tf32 terms (RN), B RN-rounded: err ~1.4e-4 per stage.
// Double-buffered; A via cp.async, B via LDG->reg->STS transpose.
// ---------------------------------------------------------------------------
#define ASTRIDE 36                       // floats per padded row
#define TILE_F (128 * ASTRIDE)           // 4608 floats per tile
#define STAGE_F (2 * TILE_F)             // A + B per stage
#define GEMM_SMEM_BYTES (2 * STAGE_F * 4)  // 73728

__global__ __launch_bounds__(256, 1) void gemm_mma_kernel(
    const float* __restrict__ A, int lda,
    const float* __restrict__ W, int ldw,
    const float* __restrict__ bias,
    float* __restrict__ C, int ldc, int Kdim)
{
    extern __shared__ float smem[];
    const uint32_t sb = smem_u32(smem);
    const int tid = threadIdx.x;
    const int lane = tid & 31;
    const int wid = tid >> 5;
    const int wm = wid & 1;          // 0..1  (M)
    const int wn = wid >> 1;         // 0..3  (N)
    const int m0 = blockIdx.y * 128;
    const int n0 = blockIdx.x * 128;

    const int l15 = lane & 15;
    // ldmatrix lane addresses (byte offsets within tile)
    const uint32_t a_lane = (uint32_t)((wm * 64 + l15) * 144 + (lane >> 4) * 16);
    const uint32_t b_lane = (uint32_t)((wn * 32 + (l15 & 7)) * 144 +
                                       ((l15 >> 3) & 1) * 16);

    float acc[4][4][4];
#pragma unroll
    for (int mt = 0; mt < 4; mt++)
#pragma unroll
        for (int nt = 0; nt < 4; nt++)
#pragma unroll
            for (int r = 0; r < 4; r++) acc[mt][nt][r] = 0.f;

    const int niter = Kdim >> 5;

    // ---- prologue: load tile 0 into stage 0 ----
    {
        const int k0 = 0;
#pragma unroll
        for (int t = 0; t < 4; t++) {
            int c = tid + 256 * t;          // 0..1023
            int row = c >> 3;
            int kc = c & 7;
            cp_async16(sb + (uint32_t)(row * 144 + kc * 16),
                       A + (size_t)(m0 + row) * lda + k0 + kc * 4);
        }
        CP_COMMIT();
#pragma unroll
        for (int t = 0; t < 4; t++) {
            int c = tid + 256 * t;
            int n = c & 127;
            int kq = (c >> 7) << 2;         // 0,4,...,28
            const float* wp = W + (size_t)(k0 + kq) * ldw + n0 + n;
            float4 v;
            v.x = wp[0];
            v.y = wp[ldw];
            v.z = wp[2 * ldw];
            v.w = wp[3 * ldw];
            *reinterpret_cast<float4*>(smem + TILE_F + n * ASTRIDE + kq) = v;
        }
    }

    for (int i = 0; i < niter; i++) {
        const int s = i & 1;
        CP_WAIT0();
        __syncthreads();    // tile i (A via cp.async, B via STS) visible

        float4 breg[4];
        const bool more = (i + 1 < niter);
        if (more) {
            const int k0 = (i + 1) << 5;
            const uint32_t soff = (uint32_t)((s ^ 1) * STAGE_F * 4);
#pragma unroll
            for (int t = 0; t < 4; t++) {
                int c = tid + 256 * t;
                int row = c >> 3;
                int kc = c & 7;
                cp_async16(sb + soff + (uint32_t)(row * 144 + kc * 16),
                           A + (size_t)(m0 + row) * lda + k0 + kc * 4);
            }
            CP_COMMIT();
#pragma unroll
            for (int t = 0; t < 4; t++) {
                int c = tid + 256 * t;
                int n = c & 127;
                int kq = (c >> 7) << 2;
                const float* wp = W + (size_t)(k0 + kq) * ldw + n0 + n;
                breg[t].x = wp[0];
                breg[t].y = wp[ldw];
                breg[t].z = wp[2 * ldw];
                breg[t].w = wp[3 * ldw];
            }
        }

        // ---- compute tile i (split-A two-term tf32) ----
        const uint32_t abase = sb + (uint32_t)(s * STAGE_F * 4) + a_lane;
        const uint32_t bbase = sb + (uint32_t)(s * STAGE_F * 4) +
                               (uint32_t)(TILE_F * 4) + b_lane;
#pragma unroll
        for (int ks = 0; ks < 4; ks++) {
            uint32_t araw[4][4];
#pragma unroll
            for (int mt = 0; mt < 4; mt++)
                ldm_x4(araw[mt], abase + mt * (16 * 144) + ks * 32);
            uint32_t braw[4][2];
#pragma unroll
            for (int nt = 0; nt < 4; nt++)
                ldm_x2(braw[nt], bbase + nt * (8 * 144) + ks * 32);

            uint32_t ahi[4][4], alo[4][4], bh[4][2];
#pragma unroll
            for (int mt = 0; mt < 4; mt++)
#pragma unroll
                for (int r = 0; r < 4; r++) {
                    float f = __uint_as_float(araw[mt][r]);
                    uint32_t hi = f2tf32(f);
                    ahi[mt][r] = hi;
                    alo[mt][r] = f2tf32(f - __uint_as_float(hi));
                }
#pragma unroll
            for (int nt = 0; nt < 4; nt++)
#pragma unroll
                for (int r = 0; r < 2; r++)
                    bh[nt][r] = f2tf32(__uint_as_float(braw[nt][r]));

#pragma unroll
            for (int mt = 0; mt < 4; mt++)
#pragma unroll
                for (int nt = 0; nt < 4; nt++) {
                    mma_tf32(acc[mt][nt], ahi[mt], bh[nt]);
                    mma_tf32(acc[mt][nt], alo[mt], bh[nt]);
                }
        }

        if (more) {
            float* bdst = smem + (s ^ 1) * STAGE_F + TILE_F;
#pragma unroll
            for (int t = 0; t < 4; t++) {
                int c = tid + 256 * t;
                int n = c & 127;
                int kq = (c >> 7) << 2;
                *reinterpret_cast<float4*>(bdst + n * ASTRIDE + kq) = breg[t];
            }
        }
    }

    // ---- epilogue: add bias, write C ----
    const int g = lane >> 2;
    const int tig = lane & 3;
    const int row0 = m0 + wm * 64;
    const int col0 = n0 + wn * 32;
#pragma unroll
    for (int nt = 0; nt < 4; nt++) {
        const int ccol = col0 + nt * 8 + 2 * tig;
        const float b0 = bias[ccol];
        const float b1 = bias[ccol + 1];
#pragma unroll
        for (int mt = 0; mt < 4; mt++) {
            const int r = row0 + mt * 16 + g;
            float2 lo = make_float2(acc[mt][nt][0] + b0, acc[mt][nt][1] + b1);
            float2 hi = make_float2(acc[mt][nt][2] + b0, acc[mt][nt][3] + b1);
            *reinterpret_cast<float2*>(C + (size_t)r * ldc + ccol) = lo;
            *reinterpret_cast<float2*>(C + (size_t)(r + 8) * ldc + ccol) = hi;
        }
    }
}

// ---------------------------------------------------------------------------
// Flash attention (known-good FFMA version): block per (b, h, 64-q tile).
// ---------------------------------------------------------------------------
__global__ __launch_bounds__(256) void attn_kernel(
    const float* __restrict__ Qg, const float* __restrict__ Kg,
    const float* __restrict__ Vg, float* __restrict__ Og)
{
    __shared__ float Qs[64 * 64];
    __shared__ float Ks[64 * 64];
    __shared__ float Ps[64 * 64];

    const int tid = threadIdx.x;
    const int tx = tid & 15;
    const int ty = tid >> 4;
    const int qt = blockIdx.x;
    const int h  = blockIdx.y;
    const int b  = blockIdx.z;

    const int qbase = b * PS + qt * 64;
    const int col0  = h * PHD;

#pragma unroll
    for (int i = 0; i < 4; i++) {
        int idx = tid + 256 * i;
        int row = idx >> 4;
        int d4  = (idx & 15) << 2;
        *reinterpret_cast<float4*>(&Qs[row * 64 + d4]) =
            *reinterpret_cast<const float4*>(Qg + (qbase + row) * PD + col0 + d4);
    }

    float m_i[4], l_i[4], o[4][4];
#pragma unroll
    for (int r = 0; r < 4; r++) {
        m_i[r] = -1e30f;
        l_i[r] = 0.f;
#pragma unroll
        for (int c = 0; c < 4; c++) o[r][c] = 0.f;
    }
    const float scale = 0.125f;

    for (int kt = 0; kt < 16; kt++) {
        const int kbase = b * PS + kt * 64;
        __syncthreads();

#pragma unroll
        for (int i = 0; i < 4; i++) {
            int idx = tid + 256 * i;
            int row = idx >> 4;
            int d4  = (idx & 15) << 2;
            float4 v = *reinterpret_cast<const float4*>(
                Kg + (kbase + row) * PD + col0 + d4);
            Ks[(d4 + 0) * 64 + (row ^ d4)] = v.x;
            Ks[(d4 + 1) * 64 + (row ^ d4)] = v.y;
            Ks[(d4 + 2) * 64 + (row ^ d4)] = v.z;
            Ks[(d4 + 3) * 64 + (row ^ d4)] = v.w;
        }
        __syncthreads();

        float s[4][4];
#pragma unroll
        for (int r = 0; r < 4; r++)
#pragma unroll
            for (int c = 0; c < 4; c++) s[r][c] = 0.f;

#pragma unroll 4
        for (int d = 0; d < 64; d++) {
            float kvv[4];
            *reinterpret_cast<float4*>(kvv) =
                *reinterpret_cast<const float4*>(&Ks[d * 64 + ((tx * 4) ^ (d & 60))]);
#pragma unroll
            for (int r = 0; r < 4; r++) {
                float qv = Qs[(ty * 4 + r) * 64 + d];
#pragma unroll
                for (int c = 0; c < 4; c++) s[r][c] += qv * kvv[c];
            }
        }

        float alpha[4];
#pragma unroll
        for (int r = 0; r < 4; r++) {
#pragma unroll
            for (int c = 0; c < 4; c++) s[r][c] *= scale;
            float mx = fmaxf(fmaxf(s[r][0], s[r][1]), fmaxf(s[r][2], s[r][3]));
            mx = fmaxf(mx, __shfl_xor_sync(0xffffffffu, mx, 1));
            mx = fmaxf(mx, __shfl_xor_sync(0xffffffffu, mx, 2));
            mx = fmaxf(mx, __shfl_xor_sync(0xffffffffu, mx, 4));
            mx = fmaxf(mx, __shfl_xor_sync(0xffffffffu, mx, 8));
            float newm = fmaxf(m_i[r], mx);
            alpha[r] = __expf(m_i[r] - newm);
            m_i[r] = newm;
            float rs = 0.f;
#pragma unroll
            for (int c = 0; c < 4; c++) {
                s[r][c] = __expf(s[r][c] - newm);
                rs += s[r][c];
            }
            rs += __shfl_xor_sync(0xffffffffu, rs, 1);
            rs += __shfl_xor_sync(0xffffffffu, rs, 2);
            rs += __shfl_xor_sync(0xffffffffu, rs, 4);
            rs += __shfl_xor_sync(0xffffffffu, rs, 8);
            l_i[r] = l_i[r] * alpha[r] + rs;
#pragma unroll
            for (int c = 0; c < 4; c++) o[r][c] *= alpha[r];
        }

        __syncthreads();

#pragma unroll
        for (int r = 0; r < 4; r++)
            *reinterpret_cast<float4*>(&Ps[(ty * 4 + r) * 64 + tx * 4]) =
                make_float4(s[r][0], s[r][1], s[r][2], s[r][3]);
#pragma unroll
        for (int i = 0; i < 4; i++) {
            int idx = tid + 256 * i;
            int row = idx >> 4;
            int d4  = (idx & 15) << 2;
            *reinterpret_cast<float4*>(&Ks[row * 64 + d4]) =
                *reinterpret_cast<const float4*>(
                    Vg + (kbase + row) * PD + col0 + d4);
        }
        __syncthreads();

#pragma unroll 4
        for (int k = 0; k < 64; k++) {
            float vvv[4];
            *reinterpret_cast<float4*>(vvv) =
                *reinterpret_cast<const float4*>(&Ks[k * 64 + tx * 4]);
#pragma unroll
            for (int r = 0; r < 4; r++) {
                float pv = Ps[(ty * 4 + r) * 64 + k];
#pragma unroll
                for (int c = 0; c < 4; c++) o[r][c] += pv * vvv[c];
            }
        }
    }

#pragma unroll
    for (int r = 0; r < 4; r++) {
        float inv = 1.f / l_i[r];
        int row = qbase + ty * 4 + r;
        *reinterpret_cast<float4*>(Og + row * PD + col0 + tx * 4) =
            make_float4(o[r][0] * inv, o[r][1] * inv,
                        o[r][2] * inv, o[r][3] * inv);
    }
}

// ---------------------------------------------------------------------------
// Launch: 5 kernels, default stream, graph-capturable.
// Inputs: query, value, Wq, bq, Wkv, bkv, Wo, bo
// ---------------------------------------------------------------------------
extern "C" void kernel_launch(void* const* d_in, const int* in_sizes, int n_in,
                              void* d_out, int out_size)
{
    const float* query = (const float*)d_in[0];
    const float* value = (const float*)d_in[1];
    const float* Wq    = (const float*)d_in[2];
    const float* bq    = (const float*)d_in[3];
    const float* Wkv   = (const float*)d_in[4];
    const float* bkv   = (const float*)d_in[5];
    const float* Wo    = (const float*)d_in[6];
    const float* bo    = (const float*)d_in[7];
    float* out = (float*)d_out;

    float *Qb, *Kb, *Vb, *Hb;
    cudaGetSymbolAddress((void**)&Qb, g_Q);
    cudaGetSymbolAddress((void**)&Kb, g_K);
    cudaGetSymbolAddress((void**)&Vb, g_V);
    cudaGetSymbolAddress((void**)&Hb, g_Hd);

    cudaFuncSetAttribute(gemm_mma_kernel,
                         cudaFuncAttributeMaxDynamicSharedMemorySize,
                         GEMM_SMEM_BYTES);

    dim3 gemm_grid(PD / 128, PM / 128);   // (8, 64)
    dim3 attn_grid(PS / 64, PH, PB);      // (16, 16, 8)

    gemm_mma_kernel<<<gemm_grid, 256, GEMM_SMEM_BYTES>>>(
        query, PD, Wq, PD, bq, Qb, PD, PD);
    gemm_mma_kernel<<<gemm_grid, 256, GEMM_SMEM_BYTES>>>(
        value, PD, Wkv, 2 * PD, bkv, Kb, PD, PD);
    gemm_mma_kernel<<<gemm_grid, 256, GEMM_SMEM_BYTES>>>(
        value, PD, Wkv + PD, 2 * PD, bkv + PD, Vb, PD, PD);
    attn_kernel<<<attn_grid, 256>>>(Qb, Kb, Vb, Hb);
    gemm_mma_kernel<<<gemm_grid, 256, GEMM_SMEM_BYTES>>>(
        Hb, PD, Wo, PD, bo, out, PD, PD);
}

// round 9
// speedup vs baseline: 3.1815x; 1.2763x over previous
#include <cuda_runtime.h>
#include <cstdint>

// Problem constants
#define PB 8
#define PS 1024
#define PD 1024
#define PH 16
#define PHD 64
#define PM (PB * PS)   // 8192 rows

// Scratch (device globals: no allocation allowed)
__device__ float g_Q[PM * PD];
__device__ float g_K[PM * PD];
__device__ float g_V[PM * PD];
__device__ float g_Hd[PM * PD];

// ---------------------------------------------------------------------------
// Helpers (compute_103-safe PTX only: mma.sync, ldmatrix, cp.async)
// ---------------------------------------------------------------------------
__device__ __forceinline__ uint32_t smem_u32(const void* p) {
    uint32_t a;
    asm("{ .reg .u64 t; cvta.to.shared.u64 t, %1; cvt.u32.u64 %0, t; }"
        : "=r"(a) : "l"(p));
    return a;
}

__device__ __forceinline__ void cp_async16(uint32_t saddr, const void* gaddr) {
    asm volatile("cp.async.cg.shared.global [%0], [%1], 16;"
                 :: "r"(saddr), "l"(gaddr));
}
#define CP_COMMIT() asm volatile("cp.async.commit_group;" ::: "memory")
#define CP_WAIT0()  asm volatile("cp.async.wait_group 0;" ::: "memory")

__device__ __forceinline__ void ldm_x4(uint32_t* r, uint32_t addr) {
    asm volatile("ldmatrix.sync.aligned.m8n8.x4.shared.b16 {%0,%1,%2,%3}, [%4];"
                 : "=r"(r[0]), "=r"(r[1]), "=r"(r[2]), "=r"(r[3]) : "r"(addr));
}
__device__ __forceinline__ void ldm_x2(uint32_t* r, uint32_t addr) {
    asm volatile("ldmatrix.sync.aligned.m8n8.x2.shared.b16 {%0,%1}, [%2];"
                 : "=r"(r[0]), "=r"(r[1]) : "r"(addr));
}

// Round-to-nearest fp32 -> tf32 (bits usable directly as mma operand)
__device__ __forceinline__ uint32_t f2tf32(float f) {
    uint32_t r;
    asm("cvt.rna.tf32.f32 %0, %1;" : "=r"(r) : "f"(f));
    return r;
}

__device__ __forceinline__ void mma_tf32(float* d, const uint32_t* a,
                                         const uint32_t* b) {
    asm volatile(
        "mma.sync.aligned.m16n8k8.row.col.f32.tf32.tf32.f32 "
        "{%0,%1,%2,%3}, {%4,%5,%6,%7}, {%8,%9}, {%0,%1,%2,%3};"
        : "+f"(d[0]), "+f"(d[1]), "+f"(d[2]), "+f"(d[3])
        : "r"(a[0]), "r"(a[1]), "r"(a[2]), "r"(a[3]), "r"(b[0]), "r"(b[1]));
}

// ---------------------------------------------------------------------------
// tf32 mma.sync GEMM (split-A for precision):
//   C[M x N] = A[M x K] @ W[K x N] + bias
// CTA tile 128x128, BK=32, 8 warps (2M x 4N), warp tile 64x32.
// ---------------------------------------------------------------------------
#define ASTRIDE 36                       // floats per padded row
#define TILE_F (128 * ASTRIDE)           // 4608 floats per tile
#define STAGE_F (2 * TILE_F)             // A + B per stage
#define GEMM_SMEM_BYTES (2 * STAGE_F * 4)  // 73728

__global__ __launch_bounds__(256, 1) void gemm_mma_kernel(
    const float* __restrict__ A, int lda,
    const float* __restrict__ W, int ldw,
    const float* __restrict__ bias,
    float* __restrict__ C, int ldc, int Kdim)
{
    extern __shared__ float smem[];
    const uint32_t sb = smem_u32(smem);
    const int tid = threadIdx.x;
    const int lane = tid & 31;
    const int wid = tid >> 5;
    const int wm = wid & 1;
    const int wn = wid >> 1;
    const int m0 = blockIdx.y * 128;
    const int n0 = blockIdx.x * 128;

    const int l15 = lane & 15;
    const uint32_t a_lane = (uint32_t)((wm * 64 + l15) * 144 + (lane >> 4) * 16);
    const uint32_t b_lane = (uint32_t)((wn * 32 + (l15 & 7)) * 144 +
                                       ((l15 >> 3) & 1) * 16);

    float acc[4][4][4];
#pragma unroll
    for (int mt = 0; mt < 4; mt++)
#pragma unroll
        for (int nt = 0; nt < 4; nt++)
#pragma unroll
            for (int r = 0; r < 4; r++) acc[mt][nt][r] = 0.f;

    const int niter = Kdim >> 5;

    {
        const int k0 = 0;
#pragma unroll
        for (int t = 0; t < 4; t++) {
            int c = tid + 256 * t;
            int row = c >> 3;
            int kc = c & 7;
            cp_async16(sb + (uint32_t)(row * 144 + kc * 16),
                       A + (size_t)(m0 + row) * lda + k0 + kc * 4);
        }
        CP_COMMIT();
#pragma unroll
        for (int t = 0; t < 4; t++) {
            int c = tid + 256 * t;
            int n = c & 127;
            int kq = (c >> 7) << 2;
            const float* wp = W + (size_t)(k0 + kq) * ldw + n0 + n;
            float4 v;
            v.x = wp[0];
            v.y = wp[ldw];
            v.z = wp[2 * ldw];
            v.w = wp[3 * ldw];
            *reinterpret_cast<float4*>(smem + TILE_F + n * ASTRIDE + kq) = v;
        }
    }

    for (int i = 0; i < niter; i++) {
        const int s = i & 1;
        CP_WAIT0();
        __syncthreads();

        float4 breg[4];
        const bool more = (i + 1 < niter);
        if (more) {
            const int k0 = (i + 1) << 5;
            const uint32_t soff = (uint32_t)((s ^ 1) * STAGE_F * 4);
#pragma unroll
            for (int t = 0; t < 4; t++) {
                int c = tid + 256 * t;
                int row = c >> 3;
                int kc = c & 7;
                cp_async16(sb + soff + (uint32_t)(row * 144 + kc * 16),
                           A + (size_t)(m0 + row) * lda + k0 + kc * 4);
            }
            CP_COMMIT();
#pragma unroll
            for (int t = 0; t < 4; t++) {
                int c = tid + 256 * t;
                int n = c & 127;
                int kq = (c >> 7) << 2;
                const float* wp = W + (size_t)(k0 + kq) * ldw + n0 + n;
                breg[t].x = wp[0];
                breg[t].y = wp[ldw];
                breg[t].z = wp[2 * ldw];
                breg[t].w = wp[3 * ldw];
            }
        }

        const uint32_t abase = sb + (uint32_t)(s * STAGE_F * 4) + a_lane;
        const uint32_t bbase = sb + (uint32_t)(s * STAGE_F * 4) +
                               (uint32_t)(TILE_F * 4) + b_lane;
#pragma unroll
        for (int ks = 0; ks < 4; ks++) {
            uint32_t araw[4][4];
#pragma unroll
            for (int mt = 0; mt < 4; mt++)
                ldm_x4(araw[mt], abase + mt * (16 * 144) + ks * 32);
            uint32_t braw[4][2];
#pragma unroll
            for (int nt = 0; nt < 4; nt++)
                ldm_x2(braw[nt], bbase + nt * (8 * 144) + ks * 32);

            uint32_t ahi[4][4], alo[4][4], bh[4][2];
#pragma unroll
            for (int mt = 0; mt < 4; mt++)
#pragma unroll
                for (int r = 0; r < 4; r++) {
                    float f = __uint_as_float(araw[mt][r]);
                    uint32_t hi = f2tf32(f);
                    ahi[mt][r] = hi;
                    alo[mt][r] = f2tf32(f - __uint_as_float(hi));
                }
#pragma unroll
            for (int nt = 0; nt < 4; nt++)
#pragma unroll
                for (int r = 0; r < 2; r++)
                    bh[nt][r] = f2tf32(__uint_as_float(braw[nt][r]));

#pragma unroll
            for (int mt = 0; mt < 4; mt++)
#pragma unroll
                for (int nt = 0; nt < 4; nt++) {
                    mma_tf32(acc[mt][nt], ahi[mt], bh[nt]);
                    mma_tf32(acc[mt][nt], alo[mt], bh[nt]);
                }
        }

        if (more) {
            float* bdst = smem + (s ^ 1) * STAGE_F + TILE_F;
#pragma unroll
            for (int t = 0; t < 4; t++) {
                int c = tid + 256 * t;
                int n = c & 127;
                int kq = (c >> 7) << 2;
                *reinterpret_cast<float4*>(bdst + n * ASTRIDE + kq) = breg[t];
            }
        }
    }

    const int g = lane >> 2;
    const int tig = lane & 3;
    const int row0 = m0 + wm * 64;
    const int col0 = n0 + wn * 32;
#pragma unroll
    for (int nt = 0; nt < 4; nt++) {
        const int ccol = col0 + nt * 8 + 2 * tig;
        const float b0 = bias[ccol];
        const float b1 = bias[ccol + 1];
#pragma unroll
        for (int mt = 0; mt < 4; mt++) {
            const int r = row0 + mt * 16 + g;
            float2 lo = make_float2(acc[mt][nt][0] + b0, acc[mt][nt][1] + b1);
            float2 hi = make_float2(acc[mt][nt][2] + b0, acc[mt][nt][3] + b1);
            *reinterpret_cast<float2*>(C + (size_t)r * ldc + ccol) = lo;
            *reinterpret_cast<float2*>(C + (size_t)(r + 8) * ldc + ccol) = hi;
        }
    }
}

// ---------------------------------------------------------------------------
// Tensor-core flash attention (tf32 mma.sync).
// Block = (b, h, 64-q tile), 128 threads / 4 warps; warp owns 16 q rows.
// FIX vs round 8: K/V tile loader now iterates t<8 (1024 float4s = full
// 64-row tiles). Round 8 loaded only rows 0..31, leaving rows 32..63 of
// Ks/Vs uninitialized -> garbage scores -> rel_err 2.1.
// ---------------------------------------------------------------------------
#define ATS 68                       // floats per padded attn smem row
#define ATT_TILE_F (64 * ATS)        // 4352 floats
#define ATT_SMEM_BYTES (3 * ATT_TILE_F * 4)   // 52224

__global__ __launch_bounds__(128, 3) void attn_mma_kernel(
    const float* __restrict__ Qg, const float* __restrict__ Kg,
    const float* __restrict__ Vg, float* __restrict__ Og)
{
    extern __shared__ float sm[];
    float* Ps = sm;                        // Q tile first, then P tile
    float* Ks = sm + ATT_TILE_F;
    float* Vs = sm + 2 * ATT_TILE_F;
    const uint32_t sb = smem_u32(sm);

    const int tid = threadIdx.x;
    const int lane = tid & 31;
    const int w = tid >> 5;                // warp 0..3 -> q rows [16w,16w+16)
    const int l15 = lane & 15;
    const int g = lane >> 2;               // row group in quad
    const int t4 = lane & 3;

    const int qt = blockIdx.x;             // 0..15
    const int h  = blockIdx.y;
    const int b  = blockIdx.z;
    const int qbase = b * PS + qt * 64;
    const int col0  = h * PHD;

    // ---- load Q tile [64 q][64 d] into Ps region ----
#pragma unroll
    for (int t = 0; t < 8; t++) {
        int idx = tid + 128 * t;           // 0..1023 float4s
        int row = idx >> 4;
        int d4  = (idx & 15) << 2;
        *reinterpret_cast<float4*>(&Ps[row * ATS + d4]) =
            *reinterpret_cast<const float4*>(Qg + (size_t)(qbase + row) * PD + col0 + d4);
    }
    __syncthreads();

    // ---- preload Q fragments (scale folded in, tf32-rounded once) ----
    const uint32_t a_lane_off = (uint32_t)((w * 16 + l15) * (ATS * 4) + (lane >> 4) * 16);
    uint32_t qh[8][4];
#pragma unroll
    for (int ks = 0; ks < 8; ks++) {
        uint32_t raw[4];
        ldm_x4(raw, sb + a_lane_off + ks * 32);
#pragma unroll
        for (int r = 0; r < 4; r++)
            qh[ks][r] = f2tf32(0.125f * __uint_as_float(raw[r]));
    }

    float m0 = -1e30f, m1 = -1e30f, l0 = 0.f, l1 = 0.f;
    float oacc[8][4];
#pragma unroll
    for (int nt = 0; nt < 8; nt++)
#pragma unroll
        for (int r = 0; r < 4; r++) oacc[nt][r] = 0.f;

    const uint32_t kb_lane = sb + (uint32_t)(ATT_TILE_F * 4) +
                             (uint32_t)((l15 & 7) * (ATS * 4) + ((l15 >> 3) & 1) * 16);

    for (int kt = 0; kt < 16; kt++) {
        __syncthreads();                   // prev tile fully consumed
        const int kbase = b * PS + kt * 64;
        // FULL 64-row tiles: 1024 float4s each for K and V.
#pragma unroll
        for (int t = 0; t < 8; t++) {
            int idx = tid + 128 * t;       // 0..1023 float4s
            int row = idx >> 4;            // 0..63
            int d4  = (idx & 15) << 2;
            *reinterpret_cast<float4*>(&Ks[row * ATS + d4]) =
                *reinterpret_cast<const float4*>(Kg + (size_t)(kbase + row) * PD + col0 + d4);
            *reinterpret_cast<float4*>(&Vs[row * ATS + d4]) =
                *reinterpret_cast<const float4*>(Vg + (size_t)(kbase + row) * PD + col0 + d4);
        }
        __syncthreads();

        // ---- S = (Q*scale) @ K^T, K split hi+lo ----
        float sacc[8][4];
#pragma unroll
        for (int nt = 0; nt < 8; nt++)
#pragma unroll
            for (int r = 0; r < 4; r++) sacc[nt][r] = 0.f;

#pragma unroll
        for (int ks = 0; ks < 8; ks++) {
#pragma unroll
            for (int nt = 0; nt < 8; nt++) {
                uint32_t braw[2];
                ldm_x2(braw, kb_lane + nt * (8 * ATS * 4) + ks * 32);
                uint32_t bhi[2], blo[2];
#pragma unroll
                for (int r = 0; r < 2; r++) {
                    float f = __uint_as_float(braw[r]);
                    bhi[r] = f2tf32(f);
                    blo[r] = f2tf32(f - __uint_as_float(bhi[r]));
                }
                mma_tf32(sacc[nt], qh[ks], bhi);
                mma_tf32(sacc[nt], qh[ks], blo);
            }
        }

        // ---- online softmax (rows g, g+8 of warp block) ----
        float mx0 = -1e30f, mx1 = -1e30f;
#pragma unroll
        for (int nt = 0; nt < 8; nt++) {
            mx0 = fmaxf(mx0, fmaxf(sacc[nt][0], sacc[nt][1]));
            mx1 = fmaxf(mx1, fmaxf(sacc[nt][2], sacc[nt][3]));
        }
        mx0 = fmaxf(mx0, __shfl_xor_sync(0xffffffffu, mx0, 1));
        mx0 = fmaxf(mx0, __shfl_xor_sync(0xffffffffu, mx0, 2));
        mx1 = fmaxf(mx1, __shfl_xor_sync(0xffffffffu, mx1, 1));
        mx1 = fmaxf(mx1, __shfl_xor_sync(0xffffffffu, mx1, 2));

        float nm0 = fmaxf(m0, mx0), nm1 = fmaxf(m1, mx1);
        float a0 = __expf(m0 - nm0), a1 = __expf(m1 - nm1);
        m0 = nm0;
        m1 = nm1;

        float rs0 = 0.f, rs1 = 0.f;
#pragma unroll
        for (int nt = 0; nt < 8; nt++) {
            sacc[nt][0] = __expf(sacc[nt][0] - m0);
            sacc[nt][1] = __expf(sacc[nt][1] - m0);
            sacc[nt][2] = __expf(sacc[nt][2] - m1);
            sacc[nt][3] = __expf(sacc[nt][3] - m1);
            rs0 += sacc[nt][0] + sacc[nt][1];
            rs1 += sacc[nt][2] + sacc[nt][3];
        }
        rs0 += __shfl_xor_sync(0xffffffffu, rs0, 1);
        rs0 += __shfl_xor_sync(0xffffffffu, rs0, 2);
        rs1 += __shfl_xor_sync(0xffffffffu, rs1, 1);
        rs1 += __shfl_xor_sync(0xffffffffu, rs1, 2);
        l0 = l0 * a0 + rs0;
        l1 = l1 * a1 + rs1;
#pragma unroll
        for (int nt = 0; nt < 8; nt++) {
            oacc[nt][0] *= a0;
            oacc[nt][1] *= a0;
            oacc[nt][2] *= a1;
            oacc[nt][3] *= a1;
        }

        // ---- write P to smem (own warp rows only) ----
        {
            float* pr0 = Ps + (w * 16 + g) * ATS;
            float* pr1 = pr0 + 8 * ATS;
#pragma unroll
            for (int nt = 0; nt < 8; nt++) {
                *reinterpret_cast<float2*>(pr0 + nt * 8 + 2 * t4) =
                    make_float2(sacc[nt][0], sacc[nt][1]);
                *reinterpret_cast<float2*>(pr1 + nt * 8 + 2 * t4) =
                    make_float2(sacc[nt][2], sacc[nt][3]);
            }
        }
        __syncwarp();

        // ---- O += P @ V, V split hi+lo ----
#pragma unroll
        for (int ks = 0; ks < 8; ks++) {
            uint32_t praw[4], ph[4];
            ldm_x4(praw, sb + a_lane_off + ks * 32);
#pragma unroll
            for (int r = 0; r < 4; r++) ph[r] = f2tf32(__uint_as_float(praw[r]));

            const float* vb = Vs + (ks * 8 + t4) * ATS + g;
#pragma unroll
            for (int nt = 0; nt < 8; nt++) {
                float v0 = vb[nt * 8];
                float v1 = vb[nt * 8 + 4 * ATS];
                uint32_t vhi[2], vlo[2];
                vhi[0] = f2tf32(v0);
                vlo[0] = f2tf32(v0 - __uint_as_float(vhi[0]));
                vhi[1] = f2tf32(v1);
                vlo[1] = f2tf32(v1 - __uint_as_float(vhi[1]));
                mma_tf32(oacc[nt], ph, vhi);
                mma_tf32(oacc[nt], ph, vlo);
            }
        }
    }

    // ---- normalize and store ----
    const float inv0 = 1.f / l0;
    const float inv1 = 1.f / l1;
    const int r0 = qbase + w * 16 + g;
#pragma unroll
    for (int nt = 0; nt < 8; nt++) {
        const int ccol = col0 + nt * 8 + 2 * t4;
        *reinterpret_cast<float2*>(Og + (size_t)r0 * PD + ccol) =
            make_float2(oacc[nt][0] * inv0, oacc[nt][1] * inv0);
        *reinterpret_cast<float2*>(Og + (size_t)(r0 + 8) * PD + ccol) =
            make_float2(oacc[nt][2] * inv1, oacc[nt][3] * inv1);
    }
}

// ---------------------------------------------------------------------------
// Launch: 5 kernels, default stream, graph-capturable.
// Inputs: query, value, Wq, bq, Wkv, bkv, Wo, bo
// ---------------------------------------------------------------------------
extern "C" void kernel_launch(void* const* d_in, const int* in_sizes, int n_in,
                              void* d_out, int out_size)
{
    const float* query = (const float*)d_in[0];
    const float* value = (const float*)d_in[1];
    const float* Wq    = (const float*)d_in[2];
    const float* bq    = (const float*)d_in[3];
    const float* Wkv   = (const float*)d_in[4];
    const float* bkv   = (const float*)d_in[5];
    const float* Wo    = (const float*)d_in[6];
    const float* bo    = (const float*)d_in[7];
    float* out = (float*)d_out;

    float *Qb, *Kb, *Vb, *Hb;
    cudaGetSymbolAddress((void**)&Qb, g_Q);
    cudaGetSymbolAddress((void**)&Kb, g_K);
    cudaGetSymbolAddress((void**)&Vb, g_V);
    cudaGetSymbolAddress((void**)&Hb, g_Hd);

    cudaFuncSetAttribute(gemm_mma_kernel,
                         cudaFuncAttributeMaxDynamicSharedMemorySize,
                         GEMM_SMEM_BYTES);
    cudaFuncSetAttribute(attn_mma_kernel,
                         cudaFuncAttributeMaxDynamicSharedMemorySize,
                         ATT_SMEM_BYTES);

    dim3 gemm_grid(PD / 128, PM / 128);   // (8, 64)
    dim3 attn_grid(PS / 64, PH, PB);      // (16, 16, 8)

    gemm_mma_kernel<<<gemm_grid, 256, GEMM_SMEM_BYTES>>>(
        query, PD, Wq, PD, bq, Qb, PD, PD);
    gemm_mma_kernel<<<gemm_grid, 256, GEMM_SMEM_BYTES>>>(
        value, PD, Wkv, 2 * PD, bkv, Kb, PD, PD);
    gemm_mma_kernel<<<gemm_grid, 256, GEMM_SMEM_BYTES>>>(
        value, PD, Wkv + PD, 2 * PD, bkv + PD, Vb, PD, PD);
    attn_mma_kernel<<<attn_grid, 128, ATT_SMEM_BYTES>>>(Qb, Kb, Vb, Hb);
    gemm_mma_kernel<<<gemm_grid, 256, GEMM_SMEM_BYTES>>>(
        Hb, PD, Wo, PD, bo, out, PD, PD);
}

// round 10
// speedup vs baseline: 3.3555x; 1.0547x over previous
#include <cuda_runtime.h>
#include <cstdint>

// Problem constants
#define PB 8
#define PS 1024
#define PD 1024
#define PH 16
#define PHD 64
#define PM (PB * PS)   // 8192 rows

// Scratch (device globals: no allocation allowed)
__device__ float g_Q[PM * PD];
__device__ float g_K[PM * PD];
__device__ float g_V[PM * PD];
__device__ float g_Hd[PM * PD];

// ---------------------------------------------------------------------------
// Helpers (compute_103-safe PTX only: mma.sync, ldmatrix)
// ---------------------------------------------------------------------------
__device__ __forceinline__ uint32_t smem_u32(const void* p) {
    uint32_t a;
    asm("{ .reg .u64 t; cvta.to.shared.u64 t, %1; cvt.u32.u64 %0, t; }"
        : "=r"(a) : "l"(p));
    return a;
}

__device__ __forceinline__ void ldm_x4(uint32_t* r, uint32_t addr) {
    asm volatile("ldmatrix.sync.aligned.m8n8.x4.shared.b16 {%0,%1,%2,%3}, [%4];"
                 : "=r"(r[0]), "=r"(r[1]), "=r"(r[2]), "=r"(r[3]) : "r"(addr));
}
__device__ __forceinline__ void ldm_x2(uint32_t* r, uint32_t addr) {
    asm volatile("ldmatrix.sync.aligned.m8n8.x2.shared.b16 {%0,%1}, [%2];"
                 : "=r"(r[0]), "=r"(r[1]) : "r"(addr));
}

// Round-to-nearest fp32 -> tf32 (bits usable directly as mma operand)
__device__ __forceinline__ uint32_t f2tf32(float f) {
    uint32_t r;
    asm("cvt.rna.tf32.f32 %0, %1;" : "=r"(r) : "f"(f));
    return r;
}

// Split f into hi (tf32-rounded) + lo (tf32 of residual); returns bit patterns.
__device__ __forceinline__ void tf32_split(float f, uint32_t& hi, uint32_t& lo) {
    hi = f2tf32(f);
    lo = f2tf32(f - __uint_as_float(hi));
}

__device__ __forceinline__ void mma_tf32(float* d, const uint32_t* a,
                                         const uint32_t* b) {
    asm volatile(
        "mma.sync.aligned.m16n8k8.row.col.f32.tf32.tf32.f32 "
        "{%0,%1,%2,%3}, {%4,%5,%6,%7}, {%8,%9}, {%0,%1,%2,%3};"
        : "+f"(d[0]), "+f"(d[1]), "+f"(d[2]), "+f"(d[3])
        : "r"(a[0]), "r"(a[1]), "r"(a[2]), "r"(a[3]), "r"(b[0]), "r"(b[1]));
}

// ---------------------------------------------------------------------------
// tf32 mma.sync GEMM, split-A hoisted to load time:
//   C[M x N] = A[M x K] @ W[K x N] + bias
// CTA tile 128x128, BK=32, 8 warps (2M x 4N), warp tile 64x32.
// Smem stage: Ahi [128x36], Alo [128x36], B(rounded) [128x36]; x2 stages.
// Mainloop is pure ldmatrix + mma (zero cvt); LDG->reg prefetch overlaps.
// ---------------------------------------------------------------------------
#define GTILE_F 4608                     // 128 * 36 floats
#define GTILE_B (GTILE_F * 4)            // 18432 bytes
#define GSTAGE_F (3 * GTILE_F)
#define GSTAGE_B (GSTAGE_F * 4)          // 55296 bytes
#define GEMM_SMEM_BYTES (2 * GSTAGE_B)   // 110592

__global__ __launch_bounds__(256, 1) void gemm_mma_kernel(
    const float* __restrict__ A, int lda,
    const float* __restrict__ W, int ldw,
    const float* __restrict__ bias,
    float* __restrict__ C, int ldc, int Kdim)
{
    extern __shared__ float smem[];
    const uint32_t sb = smem_u32(smem);
    const int tid = threadIdx.x;
    const int lane = tid & 31;
    const int wid = tid >> 5;
    const int wm = wid & 1;
    const int wn = wid >> 1;
    const int m0 = blockIdx.y * 128;
    const int n0 = blockIdx.x * 128;

    const int l15 = lane & 15;
    const uint32_t a_lane = (uint32_t)((wm * 64 + l15) * 144 + (lane >> 4) * 16);
    const uint32_t b_lane = (uint32_t)((wn * 32 + (l15 & 7)) * 144 +
                                       ((l15 >> 3) & 1) * 16);

    float acc[4][4][4];
#pragma unroll
    for (int mt = 0; mt < 4; mt++)
#pragma unroll
        for (int nt = 0; nt < 4; nt++)
#pragma unroll
            for (int r = 0; r < 4; r++) acc[mt][nt][r] = 0.f;

    const int niter = Kdim >> 5;

    // ---- prologue: tile 0 -> stage 0 (LDG -> cvt -> STS) ----
    {
        const int k0 = 0;
#pragma unroll
        for (int t = 0; t < 4; t++) {
            int c = tid + 256 * t;
            int row = c >> 3;
            int kc = c & 7;
            float4 v = *reinterpret_cast<const float4*>(
                A + (size_t)(m0 + row) * lda + k0 + kc * 4);
            uint32_t hx, lx, hy, ly, hz, lz, hw, lw;
            tf32_split(v.x, hx, lx);
            tf32_split(v.y, hy, ly);
            tf32_split(v.z, hz, lz);
            tf32_split(v.w, hw, lw);
            float* dh = smem + row * 36 + kc * 4;
            float* dl = dh + GTILE_F;
            *reinterpret_cast<uint4*>(dh) = make_uint4(hx, hy, hz, hw);
            *reinterpret_cast<uint4*>(dl) = make_uint4(lx, ly, lz, lw);
        }
#pragma unroll
        for (int t = 0; t < 4; t++) {
            int c = tid + 256 * t;
            int n = c & 127;
            int kq = (c >> 7) << 2;
            const float* wp = W + (size_t)(k0 + kq) * ldw + n0 + n;
            uint4 v;
            v.x = f2tf32(wp[0]);
            v.y = f2tf32(wp[ldw]);
            v.z = f2tf32(wp[2 * ldw]);
            v.w = f2tf32(wp[3 * ldw]);
            *reinterpret_cast<uint4*>(smem + 2 * GTILE_F + n * 36 + kq) = v;
        }
    }

    for (int i = 0; i < niter; i++) {
        const int s = i & 1;
        __syncthreads();   // stage s fully written

        float4 areg[4], breg[4];
        const bool more = (i + 1 < niter);
        if (more) {
            const int k0 = (i + 1) << 5;
#pragma unroll
            for (int t = 0; t < 4; t++) {
                int c = tid + 256 * t;
                int row = c >> 3;
                int kc = c & 7;
                areg[t] = *reinterpret_cast<const float4*>(
                    A + (size_t)(m0 + row) * lda + k0 + kc * 4);
            }
#pragma unroll
            for (int t = 0; t < 4; t++) {
                int c = tid + 256 * t;
                int n = c & 127;
                int kq = (c >> 7) << 2;
                const float* wp = W + (size_t)(k0 + kq) * ldw + n0 + n;
                breg[t].x = wp[0];
                breg[t].y = wp[ldw];
                breg[t].z = wp[2 * ldw];
                breg[t].w = wp[3 * ldw];
            }
        }

        // ---- compute stage s: pure ldmatrix + mma ----
        const uint32_t sbase = sb + (uint32_t)(s * GSTAGE_B);
        const uint32_t ahibase = sbase + a_lane;
        const uint32_t alobase = ahibase + (uint32_t)GTILE_B;
        const uint32_t bbase = sbase + 2u * GTILE_B + b_lane;
#pragma unroll
        for (int ks = 0; ks < 4; ks++) {
            uint32_t ahi[4][4], alo[4][4], bf[4][2];
#pragma unroll
            for (int mt = 0; mt < 4; mt++) {
                ldm_x4(ahi[mt], ahibase + mt * (16 * 144) + ks * 32);
                ldm_x4(alo[mt], alobase + mt * (16 * 144) + ks * 32);
            }
#pragma unroll
            for (int nt = 0; nt < 4; nt++)
                ldm_x2(bf[nt], bbase + nt * (8 * 144) + ks * 32);
#pragma unroll
            for (int mt = 0; mt < 4; mt++)
#pragma unroll
                for (int nt = 0; nt < 4; nt++) {
                    mma_tf32(acc[mt][nt], ahi[mt], bf[nt]);
                    mma_tf32(acc[mt][nt], alo[mt], bf[nt]);
                }
        }

        // ---- convert + store prefetched tile into stage s^1 ----
        if (more) {
            float* dst = smem + (s ^ 1) * GSTAGE_F;
#pragma unroll
            for (int t = 0; t < 4; t++) {
                int c = tid + 256 * t;
                int row = c >> 3;
                int kc = c & 7;
                uint32_t hx, lx, hy, ly, hz, lz, hw, lw;
                tf32_split(areg[t].x, hx, lx);
                tf32_split(areg[t].y, hy, ly);
                tf32_split(areg[t].z, hz, lz);
                tf32_split(areg[t].w, hw, lw);
                float* dh = dst + row * 36 + kc * 4;
                float* dl = dh + GTILE_F;
                *reinterpret_cast<uint4*>(dh) = make_uint4(hx, hy, hz, hw);
                *reinterpret_cast<uint4*>(dl) = make_uint4(lx, ly, lz, lw);
            }
#pragma unroll
            for (int t = 0; t < 4; t++) {
                int c = tid + 256 * t;
                int n = c & 127;
                int kq = (c >> 7) << 2;
                uint4 v;
                v.x = f2tf32(breg[t].x);
                v.y = f2tf32(breg[t].y);
                v.z = f2tf32(breg[t].z);
                v.w = f2tf32(breg[t].w);
                *reinterpret_cast<uint4*>(dst + 2 * GTILE_F + n * 36 + kq) = v;
            }
        }
    }

    // ---- epilogue: add bias, write C ----
    const int g = lane >> 2;
    const int tig = lane & 3;
    const int row0 = m0 + wm * 64;
    const int col0 = n0 + wn * 32;
#pragma unroll
    for (int nt = 0; nt < 4; nt++) {
        const int ccol = col0 + nt * 8 + 2 * tig;
        const float b0 = bias[ccol];
        const float b1 = bias[ccol + 1];
#pragma unroll
        for (int mt = 0; mt < 4; mt++) {
            const int r = row0 + mt * 16 + g;
            float2 lo = make_float2(acc[mt][nt][0] + b0, acc[mt][nt][1] + b1);
            float2 hi = make_float2(acc[mt][nt][2] + b0, acc[mt][nt][3] + b1);
            *reinterpret_cast<float2*>(C + (size_t)r * ldc + ccol) = lo;
            *reinterpret_cast<float2*>(C + (size_t)(r + 8) * ldc + ccol) = hi;
        }
    }
}

// ---------------------------------------------------------------------------
// Tensor-core flash attention, K/V splits hoisted to load time.
// Block = (b, h, 64-q tile), 128 threads / 4 warps; warp owns 16 q rows.
// Smem: Q/P tile + Khi + Klo + Vhi + Vlo (5 x 64x68 fp32 = 87040 B).
// Inner loops: pure ldmatrix/LDS + mma (P cvt only).
// ---------------------------------------------------------------------------
#define ATS 68                       // floats per padded attn smem row
#define ATT_TILE_F (64 * ATS)        // 4352 floats
#define ATT_SMEM_BYTES (5 * ATT_TILE_F * 4)   // 87040

__global__ __launch_bounds__(128, 2) void attn_mma_kernel(
    const float* __restrict__ Qg, const float* __restrict__ Kg,
    const float* __restrict__ Vg, float* __restrict__ Og)
{
    extern __shared__ float sm[];
    float* Ps  = sm;                       // Q tile first, then P tile
    float* Khi = sm + ATT_TILE_F;
    float* Klo = sm + 2 * ATT_TILE_F;
    float* Vhi = sm + 3 * ATT_TILE_F;
    float* Vlo = sm + 4 * ATT_TILE_F;
    const uint32_t sb = smem_u32(sm);

    const int tid = threadIdx.x;
    const int lane = tid & 31;
    const int w = tid >> 5;                // warp 0..3 -> q rows [16w,16w+16)
    const int l15 = lane & 15;
    const int g = lane >> 2;               // row group in quad
    const int t4 = lane & 3;

    const int qt = blockIdx.x;
    const int h  = blockIdx.y;
    const int b  = blockIdx.z;
    const int qbase = b * PS + qt * 64;
    const int col0  = h * PHD;

    // ---- load Q tile [64 q][64 d] into Ps region ----
#pragma unroll
    for (int t = 0; t < 8; t++) {
        int idx = tid + 128 * t;
        int row = idx >> 4;
        int d4  = (idx & 15) << 2;
        *reinterpret_cast<float4*>(&Ps[row * ATS + d4]) =
            *reinterpret_cast<const float4*>(Qg + (size_t)(qbase + row) * PD + col0 + d4);
    }
    __syncthreads();

    // ---- preload Q fragments (scale folded in, tf32-rounded once) ----
    const uint32_t a_lane_off = (uint32_t)((w * 16 + l15) * (ATS * 4) + (lane >> 4) * 16);
    uint32_t qh[8][4];
#pragma unroll
    for (int ks = 0; ks < 8; ks++) {
        uint32_t raw[4];
        ldm_x4(raw, sb + a_lane_off + ks * 32);
#pragma unroll
        for (int r = 0; r < 4; r++)
            qh[ks][r] = f2tf32(0.125f * __uint_as_float(raw[r]));
    }

    float m0 = -1e30f, m1 = -1e30f, l0 = 0.f, l1 = 0.f;
    float oacc[8][4];
#pragma unroll
    for (int nt = 0; nt < 8; nt++)
#pragma unroll
        for (int r = 0; r < 4; r++) oacc[nt][r] = 0.f;

    const uint32_t kb_off = (uint32_t)((l15 & 7) * (ATS * 4) + ((l15 >> 3) & 1) * 16);
    const uint32_t khibase = sb + (uint32_t)(ATT_TILE_F * 4) + kb_off;
    const uint32_t klobase = sb + (uint32_t)(2 * ATT_TILE_F * 4) + kb_off;

    for (int kt = 0; kt < 16; kt++) {
        __syncthreads();                   // prev tile fully consumed
        const int kbase = b * PS + kt * 64;
        // ---- load + split K and V tiles (converted ONCE per block) ----
#pragma unroll
        for (int t = 0; t < 8; t++) {
            int idx = tid + 128 * t;       // 0..1023 float4s
            int row = idx >> 4;
            int d4  = (idx & 15) << 2;
            float4 kv = *reinterpret_cast<const float4*>(
                Kg + (size_t)(kbase + row) * PD + col0 + d4);
            float4 vv = *reinterpret_cast<const float4*>(
                Vg + (size_t)(kbase + row) * PD + col0 + d4);
            uint32_t hx, lx, hy, ly, hz, lz, hw, lw;
            tf32_split(kv.x, hx, lx);
            tf32_split(kv.y, hy, ly);
            tf32_split(kv.z, hz, lz);
            tf32_split(kv.w, hw, lw);
            *reinterpret_cast<uint4*>(&Khi[row * ATS + d4]) = make_uint4(hx, hy, hz, hw);
            *reinterpret_cast<uint4*>(&Klo[row * ATS + d4]) = make_uint4(lx, ly, lz, lw);
            tf32_split(vv.x, hx, lx);
            tf32_split(vv.y, hy, ly);
            tf32_split(vv.z, hz, lz);
            tf32_split(vv.w, hw, lw);
            *reinterpret_cast<uint4*>(&Vhi[row * ATS + d4]) = make_uint4(hx, hy, hz, hw);
            *reinterpret_cast<uint4*>(&Vlo[row * ATS + d4]) = make_uint4(lx, ly, lz, lw);
        }
        __syncthreads();

        // ---- S = (Q*scale) @ K^T : pure ldmatrix + mma ----
        float sacc[8][4];
#pragma unroll
        for (int nt = 0; nt < 8; nt++)
#pragma unroll
            for (int r = 0; r < 4; r++) sacc[nt][r] = 0.f;

#pragma unroll
        for (int ks = 0; ks < 8; ks++) {
#pragma unroll
            for (int nt = 0; nt < 8; nt++) {
                uint32_t bhi[2], blo[2];
                ldm_x2(bhi, khibase + nt * (8 * ATS * 4) + ks * 32);
                ldm_x2(blo, klobase + nt * (8 * ATS * 4) + ks * 32);
                mma_tf32(sacc[nt], qh[ks], bhi);
                mma_tf32(sacc[nt], qh[ks], blo);
            }
        }

        // ---- online softmax (rows g, g+8 of warp block) ----
        float mx0 = -1e30f, mx1 = -1e30f;
#pragma unroll
        for (int nt = 0; nt < 8; nt++) {
            mx0 = fmaxf(mx0, fmaxf(sacc[nt][0], sacc[nt][1]));
            mx1 = fmaxf(mx1, fmaxf(sacc[nt][2], sacc[nt][3]));
        }
        mx0 = fmaxf(mx0, __shfl_xor_sync(0xffffffffu, mx0, 1));
        mx0 = fmaxf(mx0, __shfl_xor_sync(0xffffffffu, mx0, 2));
        mx1 = fmaxf(mx1, __shfl_xor_sync(0xffffffffu, mx1, 1));
        mx1 = fmaxf(mx1, __shfl_xor_sync(0xffffffffu, mx1, 2));

        float nm0 = fmaxf(m0, mx0), nm1 = fmaxf(m1, mx1);
        float a0 = __expf(m0 - nm0), a1 = __expf(m1 - nm1);
        m0 = nm0;
        m1 = nm1;

        float rs0 = 0.f, rs1 = 0.f;
#pragma unroll
        for (int nt = 0; nt < 8; nt++) {
            sacc[nt][0] = __expf(sacc[nt][0] - m0);
            sacc[nt][1] = __expf(sacc[nt][1] - m0);
            sacc[nt][2] = __expf(sacc[nt][2] - m1);
            sacc[nt][3] = __expf(sacc[nt][3] - m1);
            rs0 += sacc[nt][0] + sacc[nt][1];
            rs1 += sacc[nt][2] + sacc[nt][3];
        }
        rs0 += __shfl_xor_sync(0xffffffffu, rs0, 1);
        rs0 += __shfl_xor_sync(0xffffffffu, rs0, 2);
        rs1 += __shfl_xor_sync(0xffffffffu, rs1, 1);
        rs1 += __shfl_xor_sync(0xffffffffu, rs1, 2);
        l0 = l0 * a0 + rs0;
        l1 = l1 * a1 + rs1;
#pragma unroll
        for (int nt = 0; nt < 8; nt++) {
            oacc[nt][0] *= a0;
            oacc[nt][1] *= a0;
            oacc[nt][2] *= a1;
            oacc[nt][3] *= a1;
        }

        // ---- write P to smem (own warp rows only) ----
        {
            float* pr0 = Ps + (w * 16 + g) * ATS;
            float* pr1 = pr0 + 8 * ATS;
#pragma unroll
            for (int nt = 0; nt < 8; nt++) {
                *reinterpret_cast<float2*>(pr0 + nt * 8 + 2 * t4) =
                    make_float2(sacc[nt][0], sacc[nt][1]);
                *reinterpret_cast<float2*>(pr1 + nt * 8 + 2 * t4) =
                    make_float2(sacc[nt][2], sacc[nt][3]);
            }
        }
        __syncwarp();

        // ---- O += P @ V : P cvt (only remaining cvt) + direct V LDS ----
#pragma unroll
        for (int ks = 0; ks < 8; ks++) {
            uint32_t praw[4], ph[4];
            ldm_x4(praw, sb + a_lane_off + ks * 32);
#pragma unroll
            for (int r = 0; r < 4; r++) ph[r] = f2tf32(__uint_as_float(praw[r]));

            const float* vh = Vhi + (ks * 8 + t4) * ATS + g;
            const float* vl = Vlo + (ks * 8 + t4) * ATS + g;
#pragma unroll
            for (int nt = 0; nt < 8; nt++) {
                uint32_t vhi[2], vlo[2];
                vhi[0] = __float_as_uint(vh[nt * 8]);
                vhi[1] = __float_as_uint(vh[nt * 8 + 4 * ATS]);
                vlo[0] = __float_as_uint(vl[nt * 8]);
                vlo[1] = __float_as_uint(vl[nt * 8 + 4 * ATS]);
                mma_tf32(oacc[nt], ph, vhi);
                mma_tf32(oacc[nt], ph, vlo);
            }
        }
    }

    // ---- normalize and store ----
    const float inv0 = 1.f / l0;
    const float inv1 = 1.f / l1;
    const int r0 = qbase + w * 16 + g;
#pragma unroll
    for (int nt = 0; nt < 8; nt++) {
        const int ccol = col0 + nt * 8 + 2 * t4;
        *reinterpret_cast<float2*>(Og + (size_t)r0 * PD + ccol) =
            make_float2(oacc[nt][0] * inv0, oacc[nt][1] * inv0);
        *reinterpret_cast<float2*>(Og + (size_t)(r0 + 8) * PD + ccol) =
            make_float2(oacc[nt][2] * inv1, oacc[nt][3] * inv1);
    }
}

// ---------------------------------------------------------------------------
// Launch: 5 kernels, default stream, graph-capturable.
// Inputs: query, value, Wq, bq, Wkv, bkv, Wo, bo
// ---------------------------------------------------------------------------
extern "C" void kernel_launch(void* const* d_in, const int* in_sizes, int n_in,
                              void* d_out, int out_size)
{
    const float* query = (const float*)d_in[0];
    const float* value = (const float*)d_in[1];
    const float* Wq    = (const float*)d_in[2];
    const float* bq    = (const float*)d_in[3];
    const float* Wkv   = (const float*)d_in[4];
    const float* bkv   = (const float*)d_in[5];
    const float* Wo    = (const float*)d_in[6];
    const float* bo    = (const float*)d_in[7];
    float* out = (float*)d_out;

    float *Qb, *Kb, *Vb, *Hb;
    cudaGetSymbolAddress((void**)&Qb, g_Q);
    cudaGetSymbolAddress((void**)&Kb, g_K);
    cudaGetSymbolAddress((void**)&Vb, g_V);
    cudaGetSymbolAddress((void**)&Hb, g_Hd);

    cudaFuncSetAttribute(gemm_mma_kernel,
                         cudaFuncAttributeMaxDynamicSharedMemorySize,
                         GEMM_SMEM_BYTES);
    cudaFuncSetAttribute(attn_mma_kernel,
                         cudaFuncAttributeMaxDynamicSharedMemorySize,
                         ATT_SMEM_BYTES);

    dim3 gemm_grid(PD / 128, PM / 128);   // (8, 64)
    dim3 attn_grid(PS / 64, PH, PB);      // (16, 16, 8)

    gemm_mma_kernel<<<gemm_grid, 256, GEMM_SMEM_BYTES>>>(
        query, PD, Wq, PD, bq, Qb, PD, PD);
    gemm_mma_kernel<<<gemm_grid, 256, GEMM_SMEM_BYTES>>>(
        value, PD, Wkv, 2 * PD, bkv, Kb, PD, PD);
    gemm_mma_kernel<<<gemm_grid, 256, GEMM_SMEM_BYTES>>>(
        value, PD, Wkv + PD, 2 * PD, bkv + PD, Vb, PD, PD);
    attn_mma_kernel<<<attn_grid, 128, ATT_SMEM_BYTES>>>(Qb, Kb, Vb, Hb);
    gemm_mma_kernel<<<gemm_grid, 256, GEMM_SMEM_BYTES>>>(
        Hb, PD, Wo, PD, bo, out, PD, PD);
}

// round 11
// speedup vs baseline: 4.0075x; 1.1943x over previous
#include <cuda_runtime.h>
#include <cstdint>

// Problem constants
#define PB 8
#define PS 1024
#define PD 1024
#define PH 16
#define PHD 64
#define PM (PB * PS)   // 8192 rows

// Scratch (device globals: no allocation allowed)
__device__ float g_Q[PM * PD];
__device__ float g_K[PM * PD];
__device__ float g_V[PM * PD];
__device__ float g_Hd[PM * PD];

// ---------------------------------------------------------------------------
// Helpers (compute_103-safe PTX only: mma.sync, ldmatrix)
// ---------------------------------------------------------------------------
__device__ __forceinline__ uint32_t smem_u32(const void* p) {
    uint32_t a;
    asm("{ .reg .u64 t; cvta.to.shared.u64 t, %1; cvt.u32.u64 %0, t; }"
        : "=r"(a) : "l"(p));
    return a;
}

__device__ __forceinline__ void ldm_x4(uint32_t* r, uint32_t addr) {
    asm volatile("ldmatrix.sync.aligned.m8n8.x4.shared.b16 {%0,%1,%2,%3}, [%4];"
                 : "=r"(r[0]), "=r"(r[1]), "=r"(r[2]), "=r"(r[3]) : "r"(addr));
}
__device__ __forceinline__ void ldm_x2(uint32_t* r, uint32_t addr) {
    asm volatile("ldmatrix.sync.aligned.m8n8.x2.shared.b16 {%0,%1}, [%2];"
                 : "=r"(r[0]), "=r"(r[1]) : "r"(addr));
}

// Round-to-nearest fp32 -> tf32 (bits usable directly as mma operand)
__device__ __forceinline__ uint32_t f2tf32(float f) {
    uint32_t r;
    asm("cvt.rna.tf32.f32 %0, %1;" : "=r"(r) : "f"(f));
    return r;
}

// Split f into hi (tf32-rounded) + lo (tf32 of residual); returns bit patterns.
__device__ __forceinline__ void tf32_split(float f, uint32_t& hi, uint32_t& lo) {
    hi = f2tf32(f);
    lo = f2tf32(f - __uint_as_float(hi));
}

__device__ __forceinline__ void mma_tf32(float* d, const uint32_t* a,
                                         const uint32_t* b) {
    asm volatile(
        "mma.sync.aligned.m16n8k8.row.col.f32.tf32.tf32.f32 "
        "{%0,%1,%2,%3}, {%4,%5,%6,%7}, {%8,%9}, {%0,%1,%2,%3};"
        : "+f"(d[0]), "+f"(d[1]), "+f"(d[2]), "+f"(d[3])
        : "r"(a[0]), "r"(a[1]), "r"(a[2]), "r"(a[3]), "r"(b[0]), "r"(b[1]));
}

// ---------------------------------------------------------------------------
// tf32 mma.sync GEMM, split-A hoisted to load time (unchanged from round 10):
//   C[M x N] = A[M x K] @ W[K x N] + bias
// CTA tile 128x128, BK=32, 8 warps (2M x 4N), warp tile 64x32.
// ---------------------------------------------------------------------------
#define GTILE_F 4608                     // 128 * 36 floats
#define GTILE_B (GTILE_F * 4)            // 18432 bytes
#define GSTAGE_F (3 * GTILE_F)
#define GSTAGE_B (GSTAGE_F * 4)          // 55296 bytes
#define GEMM_SMEM_BYTES (2 * GSTAGE_B)   // 110592

__global__ __launch_bounds__(256, 1) void gemm_mma_kernel(
    const float* __restrict__ A, int lda,
    const float* __restrict__ W, int ldw,
    const float* __restrict__ bias,
    float* __restrict__ C, int ldc, int Kdim)
{
    extern __shared__ float smem[];
    const uint32_t sb = smem_u32(smem);
    const int tid = threadIdx.x;
    const int lane = tid & 31;
    const int wid = tid >> 5;
    const int wm = wid & 1;
    const int wn = wid >> 1;
    const int m0 = blockIdx.y * 128;
    const int n0 = blockIdx.x * 128;

    const int l15 = lane & 15;
    const uint32_t a_lane = (uint32_t)((wm * 64 + l15) * 144 + (lane >> 4) * 16);
    const uint32_t b_lane = (uint32_t)((wn * 32 + (l15 & 7)) * 144 +
                                       ((l15 >> 3) & 1) * 16);

    float acc[4][4][4];
#pragma unroll
    for (int mt = 0; mt < 4; mt++)
#pragma unroll
        for (int nt = 0; nt < 4; nt++)
#pragma unroll
            for (int r = 0; r < 4; r++) acc[mt][nt][r] = 0.f;

    const int niter = Kdim >> 5;

    // ---- prologue: tile 0 -> stage 0 (LDG -> cvt -> STS) ----
    {
        const int k0 = 0;
#pragma unroll
        for (int t = 0; t < 4; t++) {
            int c = tid + 256 * t;
            int row = c >> 3;
            int kc = c & 7;
            float4 v = *reinterpret_cast<const float4*>(
                A + (size_t)(m0 + row) * lda + k0 + kc * 4);
            uint32_t hx, lx, hy, ly, hz, lz, hw, lw;
            tf32_split(v.x, hx, lx);
            tf32_split(v.y, hy, ly);
            tf32_split(v.z, hz, lz);
            tf32_split(v.w, hw, lw);
            float* dh = smem + row * 36 + kc * 4;
            float* dl = dh + GTILE_F;
            *reinterpret_cast<uint4*>(dh) = make_uint4(hx, hy, hz, hw);
            *reinterpret_cast<uint4*>(dl) = make_uint4(lx, ly, lz, lw);
        }
#pragma unroll
        for (int t = 0; t < 4; t++) {
            int c = tid + 256 * t;
            int n = c & 127;
            int kq = (c >> 7) << 2;
            const float* wp = W + (size_t)(k0 + kq) * ldw + n0 + n;
            uint4 v;
            v.x = f2tf32(wp[0]);
            v.y = f2tf32(wp[ldw]);
            v.z = f2tf32(wp[2 * ldw]);
            v.w = f2tf32(wp[3 * ldw]);
            *reinterpret_cast<uint4*>(smem + 2 * GTILE_F + n * 36 + kq) = v;
        }
    }

    for (int i = 0; i < niter; i++) {
        const int s = i & 1;
        __syncthreads();   // stage s fully written

        float4 areg[4], breg[4];
        const bool more = (i + 1 < niter);
        if (more) {
            const int k0 = (i + 1) << 5;
#pragma unroll
            for (int t = 0; t < 4; t++) {
                int c = tid + 256 * t;
                int row = c >> 3;
                int kc = c & 7;
                areg[t] = *reinterpret_cast<const float4*>(
                    A + (size_t)(m0 + row) * lda + k0 + kc * 4);
            }
#pragma unroll
            for (int t = 0; t < 4; t++) {
                int c = tid + 256 * t;
                int n = c & 127;
                int kq = (c >> 7) << 2;
                const float* wp = W + (size_t)(k0 + kq) * ldw + n0 + n;
                breg[t].x = wp[0];
                breg[t].y = wp[ldw];
                breg[t].z = wp[2 * ldw];
                breg[t].w = wp[3 * ldw];
            }
        }

        // ---- compute stage s: pure ldmatrix + mma ----
        const uint32_t sbase = sb + (uint32_t)(s * GSTAGE_B);
        const uint32_t ahibase = sbase + a_lane;
        const uint32_t alobase = ahibase + (uint32_t)GTILE_B;
        const uint32_t bbase = sbase + 2u * GTILE_B + b_lane;
#pragma unroll
        for (int ks = 0; ks < 4; ks++) {
            uint32_t ahi[4][4], alo[4][4], bf[4][2];
#pragma unroll
            for (int mt = 0; mt < 4; mt++) {
                ldm_x4(ahi[mt], ahibase + mt * (16 * 144) + ks * 32);
                ldm_x4(alo[mt], alobase + mt * (16 * 144) + ks * 32);
            }
#pragma unroll
            for (int nt = 0; nt < 4; nt++)
                ldm_x2(bf[nt], bbase + nt * (8 * 144) + ks * 32);
#pragma unroll
            for (int mt = 0; mt < 4; mt++)
#pragma unroll
                for (int nt = 0; nt < 4; nt++) {
                    mma_tf32(acc[mt][nt], ahi[mt], bf[nt]);
                    mma_tf32(acc[mt][nt], alo[mt], bf[nt]);
                }
        }

        // ---- convert + store prefetched tile into stage s^1 ----
        if (more) {
            float* dst = smem + (s ^ 1) * GSTAGE_F;
#pragma unroll
            for (int t = 0; t < 4; t++) {
                int c = tid + 256 * t;
                int row = c >> 3;
                int kc = c & 7;
                uint32_t hx, lx, hy, ly, hz, lz, hw, lw;
                tf32_split(areg[t].x, hx, lx);
                tf32_split(areg[t].y, hy, ly);
                tf32_split(areg[t].z, hz, lz);
                tf32_split(areg[t].w, hw, lw);
                float* dh = dst + row * 36 + kc * 4;
                float* dl = dh + GTILE_F;
                *reinterpret_cast<uint4*>(dh) = make_uint4(hx, hy, hz, hw);
                *reinterpret_cast<uint4*>(dl) = make_uint4(lx, ly, lz, lw);
            }
#pragma unroll
            for (int t = 0; t < 4; t++) {
                int c = tid + 256 * t;
                int n = c & 127;
                int kq = (c >> 7) << 2;
                uint4 v;
                v.x = f2tf32(breg[t].x);
                v.y = f2tf32(breg[t].y);
                v.z = f2tf32(breg[t].z);
                v.w = f2tf32(breg[t].w);
                *reinterpret_cast<uint4*>(dst + 2 * GTILE_F + n * 36 + kq) = v;
            }
        }
    }

    // ---- epilogue: add bias, write C ----
    const int g = lane >> 2;
    const int tig = lane & 3;
    const int row0 = m0 + wm * 64;
    const int col0 = n0 + wn * 32;
#pragma unroll
    for (int nt = 0; nt < 4; nt++) {
        const int ccol = col0 + nt * 8 + 2 * tig;
        const float b0 = bias[ccol];
        const float b1 = bias[ccol + 1];
#pragma unroll
        for (int mt = 0; mt < 4; mt++) {
            const int r = row0 + mt * 16 + g;
            float2 lo = make_float2(acc[mt][nt][0] + b0, acc[mt][nt][1] + b1);
            float2 hi = make_float2(acc[mt][nt][2] + b0, acc[mt][nt][3] + b1);
            *reinterpret_cast<float2*>(C + (size_t)r * ldc + ccol) = lo;
            *reinterpret_cast<float2*>(C + (size_t)(r + 8) * ldc + ccol) = hi;
        }
    }
}

// ---------------------------------------------------------------------------
// Tensor-core flash attention, SINGLE-ROUNDED K/V (no hi/lo split).
// Spends rel_err budget (5.6e-4 predicted vs 1e-3) to halve both the smem
// traffic (round 10 was L1-bound at 85.9%) and the MMA count.
// Block = (b, h, 64-q tile), 128 threads / 4 warps; warp owns 16 q rows.
// Smem: Q/P tile + K(rounded) + V(rounded) = 3 x 64x68 fp32 = 52224 B.
// ---------------------------------------------------------------------------
#define ATS 68                       // floats per padded attn smem row
#define ATT_TILE_F (64 * ATS)        // 4352 floats
#define ATT_SMEM_BYTES (3 * ATT_TILE_F * 4)   // 52224

__global__ __launch_bounds__(128, 3) void attn_mma_kernel(
    const float* __restrict__ Qg, const float* __restrict__ Kg,
    const float* __restrict__ Vg, float* __restrict__ Og)
{
    extern __shared__ float sm[];
    float* Ps = sm;                        // Q tile first, then P tile
    float* Ks = sm + ATT_TILE_F;           // tf32-rounded K bits
    float* Vs = sm + 2 * ATT_TILE_F;       // tf32-rounded V bits
    const uint32_t sb = smem_u32(sm);

    const int tid = threadIdx.x;
    const int lane = tid & 31;
    const int w = tid >> 5;                // warp 0..3 -> q rows [16w,16w+16)
    const int l15 = lane & 15;
    const int g = lane >> 2;               // row group in quad
    const int t4 = lane & 3;

    const int qt = blockIdx.x;
    const int h  = blockIdx.y;
    const int b  = blockIdx.z;
    const int qbase = b * PS + qt * 64;
    const int col0  = h * PHD;

    // ---- load Q tile [64 q][64 d] into Ps region ----
#pragma unroll
    for (int t = 0; t < 8; t++) {
        int idx = tid + 128 * t;
        int row = idx >> 4;
        int d4  = (idx & 15) << 2;
        *reinterpret_cast<float4*>(&Ps[row * ATS + d4]) =
            *reinterpret_cast<const float4*>(Qg + (size_t)(qbase + row) * PD + col0 + d4);
    }
    __syncthreads();

    // ---- preload Q fragments (scale folded in, tf32-rounded once) ----
    const uint32_t a_lane_off = (uint32_t)((w * 16 + l15) * (ATS * 4) + (lane >> 4) * 16);
    uint32_t qh[8][4];
#pragma unroll
    for (int ks = 0; ks < 8; ks++) {
        uint32_t raw[4];
        ldm_x4(raw, sb + a_lane_off + ks * 32);
#pragma unroll
        for (int r = 0; r < 4; r++)
            qh[ks][r] = f2tf32(0.125f * __uint_as_float(raw[r]));
    }

    float m0 = -1e30f, m1 = -1e30f, l0 = 0.f, l1 = 0.f;
    float oacc[8][4];
#pragma unroll
    for (int nt = 0; nt < 8; nt++)
#pragma unroll
        for (int r = 0; r < 4; r++) oacc[nt][r] = 0.f;

    const uint32_t kb_lane = sb + (uint32_t)(ATT_TILE_F * 4) +
                             (uint32_t)((l15 & 7) * (ATS * 4) + ((l15 >> 3) & 1) * 16);

    for (int kt = 0; kt < 16; kt++) {
        __syncthreads();                   // prev tile fully consumed
        const int kbase = b * PS + kt * 64;
        // ---- load + round K and V tiles (cvt once per block, single copy) ----
#pragma unroll
        for (int t = 0; t < 8; t++) {
            int idx = tid + 128 * t;       // 0..1023 float4s
            int row = idx >> 4;
            int d4  = (idx & 15) << 2;
            float4 kv = *reinterpret_cast<const float4*>(
                Kg + (size_t)(kbase + row) * PD + col0 + d4);
            float4 vv = *reinterpret_cast<const float4*>(
                Vg + (size_t)(kbase + row) * PD + col0 + d4);
            *reinterpret_cast<uint4*>(&Ks[row * ATS + d4]) =
                make_uint4(f2tf32(kv.x), f2tf32(kv.y), f2tf32(kv.z), f2tf32(kv.w));
            *reinterpret_cast<uint4*>(&Vs[row * ATS + d4]) =
                make_uint4(f2tf32(vv.x), f2tf32(vv.y), f2tf32(vv.z), f2tf32(vv.w));
        }
        __syncthreads();

        // ---- S = (Q*scale) @ K^T : one MMA per fragment pair ----
        float sacc[8][4];
#pragma unroll
        for (int nt = 0; nt < 8; nt++)
#pragma unroll
            for (int r = 0; r < 4; r++) sacc[nt][r] = 0.f;

#pragma unroll
        for (int ks = 0; ks < 8; ks++) {
#pragma unroll
            for (int nt = 0; nt < 8; nt++) {
                uint32_t bf[2];
                ldm_x2(bf, kb_lane + nt * (8 * ATS * 4) + ks * 32);
                mma_tf32(sacc[nt], qh[ks], bf);
            }
        }

        // ---- online softmax (rows g, g+8 of warp block) ----
        float mx0 = -1e30f, mx1 = -1e30f;
#pragma unroll
        for (int nt = 0; nt < 8; nt++) {
            mx0 = fmaxf(mx0, fmaxf(sacc[nt][0], sacc[nt][1]));
            mx1 = fmaxf(mx1, fmaxf(sacc[nt][2], sacc[nt][3]));
        }
        mx0 = fmaxf(mx0, __shfl_xor_sync(0xffffffffu, mx0, 1));
        mx0 = fmaxf(mx0, __shfl_xor_sync(0xffffffffu, mx0, 2));
        mx1 = fmaxf(mx1, __shfl_xor_sync(0xffffffffu, mx1, 1));
        mx1 = fmaxf(mx1, __shfl_xor_sync(0xffffffffu, mx1, 2));

        float nm0 = fmaxf(m0, mx0), nm1 = fmaxf(m1, mx1);
        float a0 = __expf(m0 - nm0), a1 = __expf(m1 - nm1);
        m0 = nm0;
        m1 = nm1;

        float rs0 = 0.f, rs1 = 0.f;
#pragma unroll
        for (int nt = 0; nt < 8; nt++) {
            sacc[nt][0] = __expf(sacc[nt][0] - m0);
            sacc[nt][1] = __expf(sacc[nt][1] - m0);
            sacc[nt][2] = __expf(sacc[nt][2] - m1);
            sacc[nt][3] = __expf(sacc[nt][3] - m1);
            rs0 += sacc[nt][0] + sacc[nt][1];
            rs1 += sacc[nt][2] + sacc[nt][3];
        }
        rs0 += __shfl_xor_sync(0xffffffffu, rs0, 1);
        rs0 += __shfl_xor_sync(0xffffffffu, rs0, 2);
        rs1 += __shfl_xor_sync(0xffffffffu, rs1, 1);
        rs1 += __shfl_xor_sync(0xffffffffu, rs1, 2);
        l0 = l0 * a0 + rs0;
        l1 = l1 * a1 + rs1;
#pragma unroll
        for (int nt = 0; nt < 8; nt++) {
            oacc[nt][0] *= a0;
            oacc[nt][1] *= a0;
            oacc[nt][2] *= a1;
            oacc[nt][3] *= a1;
        }

        // ---- write P to smem (own warp rows only) ----
        {
            float* pr0 = Ps + (w * 16 + g) * ATS;
            float* pr1 = pr0 + 8 * ATS;
#pragma unroll
            for (int nt = 0; nt < 8; nt++) {
                *reinterpret_cast<float2*>(pr0 + nt * 8 + 2 * t4) =
                    make_float2(sacc[nt][0], sacc[nt][1]);
                *reinterpret_cast<float2*>(pr1 + nt * 8 + 2 * t4) =
                    make_float2(sacc[nt][2], sacc[nt][3]);
            }
        }
        __syncwarp();

        // ---- O += P @ V : P cvt + direct V LDS (pre-rounded), one MMA ----
#pragma unroll
        for (int ks = 0; ks < 8; ks++) {
            uint32_t praw[4], ph[4];
            ldm_x4(praw, sb + a_lane_off + ks * 32);
#pragma unroll
            for (int r = 0; r < 4; r++) ph[r] = f2tf32(__uint_as_float(praw[r]));

            const float* vb = Vs + (ks * 8 + t4) * ATS + g;
#pragma unroll
            for (int nt = 0; nt < 8; nt++) {
                uint32_t vf[2];
                vf[0] = __float_as_uint(vb[nt * 8]);
                vf[1] = __float_as_uint(vb[nt * 8 + 4 * ATS]);
                mma_tf32(oacc[nt], ph, vf);
            }
        }
    }

    // ---- normalize and store ----
    const float inv0 = 1.f / l0;
    const float inv1 = 1.f / l1;
    const int r0 = qbase + w * 16 + g;
#pragma unroll
    for (int nt = 0; nt < 8; nt++) {
        const int ccol = col0 + nt * 8 + 2 * t4;
        *reinterpret_cast<float2*>(Og + (size_t)r0 * PD + ccol) =
            make_float2(oacc[nt][0] * inv0, oacc[nt][1] * inv0);
        *reinterpret_cast<float2*>(Og + (size_t)(r0 + 8) * PD + ccol) =
            make_float2(oacc[nt][2] * inv1, oacc[nt][3] * inv1);
    }
}

// ---------------------------------------------------------------------------
// Launch: 5 kernels, default stream, graph-capturable.
// Inputs: query, value, Wq, bq, Wkv, bkv, Wo, bo
// ---------------------------------------------------------------------------
extern "C" void kernel_launch(void* const* d_in, const int* in_sizes, int n_in,
                              void* d_out, int out_size)
{
    const float* query = (const float*)d_in[0];
    const float* value = (const float*)d_in[1];
    const float* Wq    = (const float*)d_in[2];
    const float* bq    = (const float*)d_in[3];
    const float* Wkv   = (const float*)d_in[4];
    const float* bkv   = (const float*)d_in[5];
    const float* Wo    = (const float*)d_in[6];
    const float* bo    = (const float*)d_in[7];
    float* out = (float*)d_out;

    float *Qb, *Kb, *Vb, *Hb;
    cudaGetSymbolAddress((void**)&Qb, g_Q);
    cudaGetSymbolAddress((void**)&Kb, g_K);
    cudaGetSymbolAddress((void**)&Vb, g_V);
    cudaGetSymbolAddress((void**)&Hb, g_Hd);

    cudaFuncSetAttribute(gemm_mma_kernel,
                         cudaFuncAttributeMaxDynamicSharedMemorySize,
                         GEMM_SMEM_BYTES);
    cudaFuncSetAttribute(attn_mma_kernel,
                         cudaFuncAttributeMaxDynamicSharedMemorySize,
                         ATT_SMEM_BYTES);

    dim3 gemm_grid(PD / 128, PM / 128);   // (8, 64)
    dim3 attn_grid(PS / 64, PH, PB);      // (16, 16, 8)

    gemm_mma_kernel<<<gemm_grid, 256, GEMM_SMEM_BYTES>>>(
        query, PD, Wq, PD, bq, Qb, PD, PD);
    gemm_mma_kernel<<<gemm_grid, 256, GEMM_SMEM_BYTES>>>(
        value, PD, Wkv, 2 * PD, bkv, Kb, PD, PD);
    gemm_mma_kernel<<<gemm_grid, 256, GEMM_SMEM_BYTES>>>(
        value, PD, Wkv + PD, 2 * PD, bkv + PD, Vb, PD, PD);
    attn_mma_kernel<<<attn_grid, 128, ATT_SMEM_BYTES>>>(Qb, Kb, Vb, Hb);
    gemm_mma_kernel<<<gemm_grid, 256, GEMM_SMEM_BYTES>>>(
        Hb, PD, Wo, PD, bo, out, PD, PD);
}

// round 12
// speedup vs baseline: 5.2678x; 1.3145x over previous
#include <cuda_runtime.h>
#include <cstdint>

// Problem constants
#define PB 8
#define PS 1024
#define PD 1024
#define PH 16
#define PHD 64
#define PM (PB * PS)   // 8192 rows

// Scratch (device globals: no allocation allowed)
__device__ float g_Q[PM * PD];
__device__ float g_K[PM * PD];
__device__ float g_V[PM * PD];
__device__ float g_Hd[PM * PD];

// ---------------------------------------------------------------------------
// Helpers (compute_103-safe PTX only: mma.sync, ldmatrix)
// ---------------------------------------------------------------------------
__device__ __forceinline__ uint32_t smem_u32(const void* p) {
    uint32_t a;
    asm("{ .reg .u64 t; cvta.to.shared.u64 t, %1; cvt.u32.u64 %0, t; }"
        : "=r"(a) : "l"(p));
    return a;
}

__device__ __forceinline__ void ldm_x4(uint32_t* r, uint32_t addr) {
    asm volatile("ldmatrix.sync.aligned.m8n8.x4.shared.b16 {%0,%1,%2,%3}, [%4];"
                 : "=r"(r[0]), "=r"(r[1]), "=r"(r[2]), "=r"(r[3]) : "r"(addr));
}
__device__ __forceinline__ void ldm_x2(uint32_t* r, uint32_t addr) {
    asm volatile("ldmatrix.sync.aligned.m8n8.x2.shared.b16 {%0,%1}, [%2];"
                 : "=r"(r[0]), "=r"(r[1]) : "r"(addr));
}

// Round-to-nearest fp32 -> tf32 (bits usable directly as mma operand)
__device__ __forceinline__ uint32_t f2tf32(float f) {
    uint32_t r;
    asm("cvt.rna.tf32.f32 %0, %1;" : "=r"(r) : "f"(f));
    return r;
}

__device__ __forceinline__ void mma_tf32(float* d, const uint32_t* a,
                                         const uint32_t* b) {
    asm volatile(
        "mma.sync.aligned.m16n8k8.row.col.f32.tf32.tf32.f32 "
        "{%0,%1,%2,%3}, {%4,%5,%6,%7}, {%8,%9}, {%0,%1,%2,%3};"
        : "+f"(d[0]), "+f"(d[1]), "+f"(d[2]), "+f"(d[3])
        : "r"(a[0]), "r"(a[1]), "r"(a[2]), "r"(a[3]), "r"(b[0]), "r"(b[1]));
}

// ---------------------------------------------------------------------------
// tf32 mma.sync GEMM, single-rounded A and B (no split — round 12):
//   C[M x N] = A[M x K] @ W[K x N] + bias
// CTA tile 128x128, BK=32, 8 warps (2M x 4N), warp tile 64x32.
// Smem stage: A(rounded) [128x36] + B(rounded) [128x36]; x2 stages (72 KB).
// Mainloop: pure ldmatrix + mma, half the MMA count of the split version.
// ---------------------------------------------------------------------------
#define GTILE_F 4608                     // 128 * 36 floats
#define GTILE_B (GTILE_F * 4)            // 18432 bytes
#define GSTAGE_F (2 * GTILE_F)           // A + B per stage
#define GSTAGE_B (GSTAGE_F * 4)          // 36864 bytes
#define GEMM_SMEM_BYTES (2 * GSTAGE_B)   // 73728

__global__ __launch_bounds__(256, 1) void gemm_mma_kernel(
    const float* __restrict__ A, int lda,
    const float* __restrict__ W, int ldw,
    const float* __restrict__ bias,
    float* __restrict__ C, int ldc, int Kdim)
{
    extern __shared__ float smem[];
    const uint32_t sb = smem_u32(smem);
    const int tid = threadIdx.x;
    const int lane = tid & 31;
    const int wid = tid >> 5;
    const int wm = wid & 1;
    const int wn = wid >> 1;
    const int m0 = blockIdx.y * 128;
    const int n0 = blockIdx.x * 128;

    const int l15 = lane & 15;
    const uint32_t a_lane = (uint32_t)((wm * 64 + l15) * 144 + (lane >> 4) * 16);
    const uint32_t b_lane = (uint32_t)((wn * 32 + (l15 & 7)) * 144 +
                                       ((l15 >> 3) & 1) * 16);

    float acc[4][4][4];
#pragma unroll
    for (int mt = 0; mt < 4; mt++)
#pragma unroll
        for (int nt = 0; nt < 4; nt++)
#pragma unroll
            for (int r = 0; r < 4; r++) acc[mt][nt][r] = 0.f;

    const int niter = Kdim >> 5;

    // ---- prologue: tile 0 -> stage 0 (LDG -> cvt -> STS) ----
    {
        const int k0 = 0;
#pragma unroll
        for (int t = 0; t < 4; t++) {
            int c = tid + 256 * t;
            int row = c >> 3;
            int kc = c & 7;
            float4 v = *reinterpret_cast<const float4*>(
                A + (size_t)(m0 + row) * lda + k0 + kc * 4);
            *reinterpret_cast<uint4*>(smem + row * 36 + kc * 4) =
                make_uint4(f2tf32(v.x), f2tf32(v.y), f2tf32(v.z), f2tf32(v.w));
        }
#pragma unroll
        for (int t = 0; t < 4; t++) {
            int c = tid + 256 * t;
            int n = c & 127;
            int kq = (c >> 7) << 2;
            const float* wp = W + (size_t)(k0 + kq) * ldw + n0 + n;
            uint4 v;
            v.x = f2tf32(wp[0]);
            v.y = f2tf32(wp[ldw]);
            v.z = f2tf32(wp[2 * ldw]);
            v.w = f2tf32(wp[3 * ldw]);
            *reinterpret_cast<uint4*>(smem + GTILE_F + n * 36 + kq) = v;
        }
    }

    for (int i = 0; i < niter; i++) {
        const int s = i & 1;
        __syncthreads();   // stage s fully written

        float4 areg[4], breg[4];
        const bool more = (i + 1 < niter);
        if (more) {
            const int k0 = (i + 1) << 5;
#pragma unroll
            for (int t = 0; t < 4; t++) {
                int c = tid + 256 * t;
                int row = c >> 3;
                int kc = c & 7;
                areg[t] = *reinterpret_cast<const float4*>(
                    A + (size_t)(m0 + row) * lda + k0 + kc * 4);
            }
#pragma unroll
            for (int t = 0; t < 4; t++) {
                int c = tid + 256 * t;
                int n = c & 127;
                int kq = (c >> 7) << 2;
                const float* wp = W + (size_t)(k0 + kq) * ldw + n0 + n;
                breg[t].x = wp[0];
                breg[t].y = wp[ldw];
                breg[t].z = wp[2 * ldw];
                breg[t].w = wp[3 * ldw];
            }
        }

        // ---- compute stage s: pure ldmatrix + mma (single A term) ----
        const uint32_t sbase = sb + (uint32_t)(s * GSTAGE_B);
        const uint32_t abase = sbase + a_lane;
        const uint32_t bbase = sbase + (uint32_t)GTILE_B + b_lane;
#pragma unroll
        for (int ks = 0; ks < 4; ks++) {
            uint32_t af[4][4], bf[4][2];
#pragma unroll
            for (int mt = 0; mt < 4; mt++)
                ldm_x4(af[mt], abase + mt * (16 * 144) + ks * 32);
#pragma unroll
            for (int nt = 0; nt < 4; nt++)
                ldm_x2(bf[nt], bbase + nt * (8 * 144) + ks * 32);
#pragma unroll
            for (int mt = 0; mt < 4; mt++)
#pragma unroll
                for (int nt = 0; nt < 4; nt++)
                    mma_tf32(acc[mt][nt], af[mt], bf[nt]);
        }

        // ---- convert + store prefetched tile into stage s^1 ----
        if (more) {
            float* dst = smem + (s ^ 1) * GSTAGE_F;
#pragma unroll
            for (int t = 0; t < 4; t++) {
                int c = tid + 256 * t;
                int row = c >> 3;
                int kc = c & 7;
                *reinterpret_cast<uint4*>(dst + row * 36 + kc * 4) =
                    make_uint4(f2tf32(areg[t].x), f2tf32(areg[t].y),
                               f2tf32(areg[t].z), f2tf32(areg[t].w));
            }
#pragma unroll
            for (int t = 0; t < 4; t++) {
                int c = tid + 256 * t;
                int n = c & 127;
                int kq = (c >> 7) << 2;
                uint4 v;
                v.x = f2tf32(breg[t].x);
                v.y = f2tf32(breg[t].y);
                v.z = f2tf32(breg[t].z);
                v.w = f2tf32(breg[t].w);
                *reinterpret_cast<uint4*>(dst + GTILE_F + n * 36 + kq) = v;
            }
        }
    }

    // ---- epilogue: add bias, write C ----
    const int g = lane >> 2;
    const int tig = lane & 3;
    const int row0 = m0 + wm * 64;
    const int col0 = n0 + wn * 32;
#pragma unroll
    for (int nt = 0; nt < 4; nt++) {
        const int ccol = col0 + nt * 8 + 2 * tig;
        const float b0 = bias[ccol];
        const float b1 = bias[ccol + 1];
#pragma unroll
        for (int mt = 0; mt < 4; mt++) {
            const int r = row0 + mt * 16 + g;
            float2 lo = make_float2(acc[mt][nt][0] + b0, acc[mt][nt][1] + b1);
            float2 hi = make_float2(acc[mt][nt][2] + b0, acc[mt][nt][3] + b1);
            *reinterpret_cast<float2*>(C + (size_t)r * ldc + ccol) = lo;
            *reinterpret_cast<float2*>(C + (size_t)(r + 8) * ldc + ccol) = hi;
        }
    }
}

// ---------------------------------------------------------------------------
// Tensor-core flash attention, single-rounded K/V (FROZEN from round 11).
// Block = (b, h, 64-q tile), 128 threads / 4 warps; warp owns 16 q rows.
// Smem: Q/P tile + K(rounded) + V(rounded) = 3 x 64x68 fp32 = 52224 B.
// ---------------------------------------------------------------------------
#define ATS 68                       // floats per padded attn smem row
#define ATT_TILE_F (64 * ATS)        // 4352 floats
#define ATT_SMEM_BYTES (3 * ATT_TILE_F * 4)   // 52224

__global__ __launch_bounds__(128, 3) void attn_mma_kernel(
    const float* __restrict__ Qg, const float* __restrict__ Kg,
    const float* __restrict__ Vg, float* __restrict__ Og)
{
    extern __shared__ float sm[];
    float* Ps = sm;                        // Q tile first, then P tile
    float* Ks = sm + ATT_TILE_F;           // tf32-rounded K bits
    float* Vs = sm + 2 * ATT_TILE_F;       // tf32-rounded V bits
    const uint32_t sb = smem_u32(sm);

    const int tid = threadIdx.x;
    const int lane = tid & 31;
    const int w = tid >> 5;                // warp 0..3 -> q rows [16w,16w+16)
    const int l15 = lane & 15;
    const int g = lane >> 2;               // row group in quad
    const int t4 = lane & 3;

    const int qt = blockIdx.x;
    const int h  = blockIdx.y;
    const int b  = blockIdx.z;
    const int qbase = b * PS + qt * 64;
    const int col0  = h * PHD;

    // ---- load Q tile [64 q][64 d] into Ps region ----
#pragma unroll
    for (int t = 0; t < 8; t++) {
        int idx = tid + 128 * t;
        int row = idx >> 4;
        int d4  = (idx & 15) << 2;
        *reinterpret_cast<float4*>(&Ps[row * ATS + d4]) =
            *reinterpret_cast<const float4*>(Qg + (size_t)(qbase + row) * PD + col0 + d4);
    }
    __syncthreads();

    // ---- preload Q fragments (scale folded in, tf32-rounded once) ----
    const uint32_t a_lane_off = (uint32_t)((w * 16 + l15) * (ATS * 4) + (lane >> 4) * 16);
    uint32_t qh[8][4];
#pragma unroll
    for (int ks = 0; ks < 8; ks++) {
        uint32_t raw[4];
        ldm_x4(raw, sb + a_lane_off + ks * 32);
#pragma unroll
        for (int r = 0; r < 4; r++)
            qh[ks][r] = f2tf32(0.125f * __uint_as_float(raw[r]));
    }

    float m0 = -1e30f, m1 = -1e30f, l0 = 0.f, l1 = 0.f;
    float oacc[8][4];
#pragma unroll
    for (int nt = 0; nt < 8; nt++)
#pragma unroll
        for (int r = 0; r < 4; r++) oacc[nt][r] = 0.f;

    const uint32_t kb_lane = sb + (uint32_t)(ATT_TILE_F * 4) +
                             (uint32_t)((l15 & 7) * (ATS * 4) + ((l15 >> 3) & 1) * 16);

    for (int kt = 0; kt < 16; kt++) {
        __syncthreads();                   // prev tile fully consumed
        const int kbase = b * PS + kt * 64;
        // ---- load + round K and V tiles (cvt once per block, single copy) ----
#pragma unroll
        for (int t = 0; t < 8; t++) {
            int idx = tid + 128 * t;       // 0..1023 float4s
            int row = idx >> 4;
            int d4  = (idx & 15) << 2;
            float4 kv = *reinterpret_cast<const float4*>(
                Kg + (size_t)(kbase + row) * PD + col0 + d4);
            float4 vv = *reinterpret_cast<const float4*>(
                Vg + (size_t)(kbase + row) * PD + col0 + d4);
            *reinterpret_cast<uint4*>(&Ks[row * ATS + d4]) =
                make_uint4(f2tf32(kv.x), f2tf32(kv.y), f2tf32(kv.z), f2tf32(kv.w));
            *reinterpret_cast<uint4*>(&Vs[row * ATS + d4]) =
                make_uint4(f2tf32(vv.x), f2tf32(vv.y), f2tf32(vv.z), f2tf32(vv.w));
        }
        __syncthreads();

        // ---- S = (Q*scale) @ K^T : one MMA per fragment pair ----
        float sacc[8][4];
#pragma unroll
        for (int nt = 0; nt < 8; nt++)
#pragma unroll
            for (int r = 0; r < 4; r++) sacc[nt][r] = 0.f;

#pragma unroll
        for (int ks = 0; ks < 8; ks++) {
#pragma unroll
            for (int nt = 0; nt < 8; nt++) {
                uint32_t bf[2];
                ldm_x2(bf, kb_lane + nt * (8 * ATS * 4) + ks * 32);
                mma_tf32(sacc[nt], qh[ks], bf);
            }
        }

        // ---- online softmax (rows g, g+8 of warp block) ----
        float mx0 = -1e30f, mx1 = -1e30f;
#pragma unroll
        for (int nt = 0; nt < 8; nt++) {
            mx0 = fmaxf(mx0, fmaxf(sacc[nt][0], sacc[nt][1]));
            mx1 = fmaxf(mx1, fmaxf(sacc[nt][2], sacc[nt][3]));
        }
        mx0 = fmaxf(mx0, __shfl_xor_sync(0xffffffffu, mx0, 1));
        mx0 = fmaxf(mx0, __shfl_xor_sync(0xffffffffu, mx0, 2));
        mx1 = fmaxf(mx1, __shfl_xor_sync(0xffffffffu, mx1, 1));
        mx1 = fmaxf(mx1, __shfl_xor_sync(0xffffffffu, mx1, 2));

        float nm0 = fmaxf(m0, mx0), nm1 = fmaxf(m1, mx1);
        float a0 = __expf(m0 - nm0), a1 = __expf(m1 - nm1);
        m0 = nm0;
        m1 = nm1;

        float rs0 = 0.f, rs1 = 0.f;
#pragma unroll
        for (int nt = 0; nt < 8; nt++) {
            sacc[nt][0] = __expf(sacc[nt][0] - m0);
            sacc[nt][1] = __expf(sacc[nt][1] - m0);
            sacc[nt][2] = __expf(sacc[nt][2] - m1);
            sacc[nt][3] = __expf(sacc[nt][3] - m1);
            rs0 += sacc[nt][0] + sacc[nt][1];
            rs1 += sacc[nt][2] + sacc[nt][3];
        }
        rs0 += __shfl_xor_sync(0xffffffffu, rs0, 1);
        rs0 += __shfl_xor_sync(0xffffffffu, rs0, 2);
        rs1 += __shfl_xor_sync(0xffffffffu, rs1, 1);
        rs1 += __shfl_xor_sync(0xffffffffu, rs1, 2);
        l0 = l0 * a0 + rs0;
        l1 = l1 * a1 + rs1;
#pragma unroll
        for (int nt = 0; nt < 8; nt++) {
            oacc[nt][0] *= a0;
            oacc[nt][1] *= a0;
            oacc[nt][2] *= a1;
            oacc[nt][3] *= a1;
        }

        // ---- write P to smem (own warp rows only) ----
        {
            float* pr0 = Ps + (w * 16 + g) * ATS;
            float* pr1 = pr0 + 8 * ATS;
#pragma unroll
            for (int nt = 0; nt < 8; nt++) {
                *reinterpret_cast<float2*>(pr0 + nt * 8 + 2 * t4) =
                    make_float2(sacc[nt][0], sacc[nt][1]);
                *reinterpret_cast<float2*>(pr1 + nt * 8 + 2 * t4) =
                    make_float2(sacc[nt][2], sacc[nt][3]);
            }
        }
        __syncwarp();

        // ---- O += P @ V : P cvt + direct V LDS (pre-rounded), one MMA ----
#pragma unroll
        for (int ks = 0; ks < 8; ks++) {
            uint32_t praw[4], ph[4];
            ldm_x4(praw, sb + a_lane_off + ks * 32);
#pragma unroll
            for (int r = 0; r < 4; r++) ph[r] = f2tf32(__uint_as_float(praw[r]));

            const float* vb = Vs + (ks * 8 + t4) * ATS + g;
#pragma unroll
            for (int nt = 0; nt < 8; nt++) {
                uint32_t vf[2];
                vf[0] = __float_as_uint(vb[nt * 8]);
                vf[1] = __float_as_uint(vb[nt * 8 + 4 * ATS]);
                mma_tf32(oacc[nt], ph, vf);
            }
        }
    }

    // ---- normalize and store ----
    const float inv0 = 1.f / l0;
    const float inv1 = 1.f / l1;
    const int r0 = qbase + w * 16 + g;
#pragma unroll
    for (int nt = 0; nt < 8; nt++) {
        const int ccol = col0 + nt * 8 + 2 * t4;
        *reinterpret_cast<float2*>(Og + (size_t)r0 * PD + ccol) =
            make_float2(oacc[nt][0] * inv0, oacc[nt][1] * inv0);
        *reinterpret_cast<float2*>(Og + (size_t)(r0 + 8) * PD + ccol) =
            make_float2(oacc[nt][2] * inv1, oacc[nt][3] * inv1);
    }
}

// ---------------------------------------------------------------------------
// Launch: 5 kernels, default stream, graph-capturable.
// Inputs: query, value, Wq, bq, Wkv, bkv, Wo, bo
// ---------------------------------------------------------------------------
extern "C" void kernel_launch(void* const* d_in, const int* in_sizes, int n_in,
                              void* d_out, int out_size)
{
    const float* query = (const float*)d_in[0];
    const float* value = (const float*)d_in[1];
    const float* Wq    = (const float*)d_in[2];
    const float* bq    = (const float*)d_in[3];
    const float* Wkv   = (const float*)d_in[4];
    const float* bkv   = (const float*)d_in[5];
    const float* Wo    = (const float*)d_in[6];
    const float* bo    = (const float*)d_in[7];
    float* out = (float*)d_out;

    float *Qb, *Kb, *Vb, *Hb;
    cudaGetSymbolAddress((void**)&Qb, g_Q);
    cudaGetSymbolAddress((void**)&Kb, g_K);
    cudaGetSymbolAddress((void**)&Vb, g_V);
    cudaGetSymbolAddress((void**)&Hb, g_Hd);

    cudaFuncSetAttribute(gemm_mma_kernel,
                         cudaFuncAttributeMaxDynamicSharedMemorySize,
                         GEMM_SMEM_BYTES);
    cudaFuncSetAttribute(attn_mma_kernel,
                         cudaFuncAttributeMaxDynamicSharedMemorySize,
                         ATT_SMEM_BYTES);

    dim3 gemm_grid(PD / 128, PM / 128);   // (8, 64)
    dim3 attn_grid(PS / 64, PH, PB);      // (16, 16, 8)

    gemm_mma_kernel<<<gemm_grid, 256, GEMM_SMEM_BYTES>>>(
        query, PD, Wq, PD, bq, Qb, PD, PD);
    gemm_mma_kernel<<<gemm_grid, 256, GEMM_SMEM_BYTES>>>(
        value, PD, Wkv, 2 * PD, bkv, Kb, PD, PD);
    gemm_mma_kernel<<<gemm_grid, 256, GEMM_SMEM_BYTES>>>(
        value, PD, Wkv + PD, 2 * PD, bkv + PD, Vb, PD, PD);
    attn_mma_kernel<<<attn_grid, 128, ATT_SMEM_BYTES>>>(Qb, Kb, Vb, Hb);
    gemm_mma_kernel<<<gemm_grid, 256, GEMM_SMEM_BYTES>>>(
        Hb, PD, Wo, PD, bo, out, PD, PD);
}

// round 13
// speedup vs baseline: 5.6297x; 1.0687x over previous
#include <cuda_runtime.h>
#include <cstdint>

// Problem constants
#define PB 8
#define PS 1024
#define PD 1024
#define PH 16
#define PHD 64
#define PM (PB * PS)   // 8192 rows

// Scratch (device globals: no allocation allowed)
__device__ float g_Q[PM * PD];
__device__ float g_K[PM * PD];
__device__ float g_V[PM * PD];
__device__ float g_Hd[PM * PD];

// ---------------------------------------------------------------------------
// Helpers (compute_103-safe PTX only: mma.sync, ldmatrix)
// ---------------------------------------------------------------------------
__device__ __forceinline__ uint32_t smem_u32(const void* p) {
    uint32_t a;
    asm("{ .reg .u64 t; cvta.to.shared.u64 t, %1; cvt.u32.u64 %0, t; }"
        : "=r"(a) : "l"(p));
    return a;
}

__device__ __forceinline__ void ldm_x4(uint32_t* r, uint32_t addr) {
    asm volatile("ldmatrix.sync.aligned.m8n8.x4.shared.b16 {%0,%1,%2,%3}, [%4];"
                 : "=r"(r[0]), "=r"(r[1]), "=r"(r[2]), "=r"(r[3]) : "r"(addr));
}
__device__ __forceinline__ void ldm_x2(uint32_t* r, uint32_t addr) {
    asm volatile("ldmatrix.sync.aligned.m8n8.x2.shared.b16 {%0,%1}, [%2];"
                 : "=r"(r[0]), "=r"(r[1]) : "r"(addr));
}

// Round-to-nearest fp32 -> tf32 (bits usable directly as mma operand)
__device__ __forceinline__ uint32_t f2tf32(float f) {
    uint32_t r;
    asm("cvt.rna.tf32.f32 %0, %1;" : "=r"(r) : "f"(f));
    return r;
}

__device__ __forceinline__ void mma_tf32(float* d, const uint32_t* a,
                                         const uint32_t* b) {
    asm volatile(
        "mma.sync.aligned.m16n8k8.row.col.f32.tf32.tf32.f32 "
        "{%0,%1,%2,%3}, {%4,%5,%6,%7}, {%8,%9}, {%0,%1,%2,%3};"
        : "+f"(d[0]), "+f"(d[1]), "+f"(d[2]), "+f"(d[3])
        : "r"(a[0]), "r"(a[1]), "r"(a[2]), "r"(a[3]), "r"(b[0]), "r"(b[1]));
}

// ---------------------------------------------------------------------------
// tf32 mma.sync GEMM, single-rounded A and B; 2 CTAs/SM for pipeline overlap:
//   C[M x N] = A[M x K] @ W[K x N] + bias
// CTA tile 128x128, BK=32, 8 warps (2M x 4N), warp tile 64x32.
// Smem stage: A(rounded) [128x36] + B(rounded) [128x36]; x2 stages (72 KB).
// ---------------------------------------------------------------------------
#define GTILE_F 4608                     // 128 * 36 floats
#define GTILE_B (GTILE_F * 4)            // 18432 bytes
#define GSTAGE_F (2 * GTILE_F)           // A + B per stage
#define GSTAGE_B (GSTAGE_F * 4)          // 36864 bytes
#define GEMM_SMEM_BYTES (2 * GSTAGE_B)   // 73728

__global__ __launch_bounds__(256, 2) void gemm_mma_kernel(
    const float* __restrict__ A, int lda,
    const float* __restrict__ W, int ldw,
    const float* __restrict__ bias,
    float* __restrict__ C, int ldc, int Kdim)
{
    extern __shared__ float smem[];
    const uint32_t sb = smem_u32(smem);
    const int tid = threadIdx.x;
    const int lane = tid & 31;
    const int wid = tid >> 5;
    const int wm = wid & 1;
    const int wn = wid >> 1;
    const int m0 = blockIdx.y * 128;
    const int n0 = blockIdx.x * 128;

    const int l15 = lane & 15;
    const uint32_t a_lane = (uint32_t)((wm * 64 + l15) * 144 + (lane >> 4) * 16);
    const uint32_t b_lane = (uint32_t)((wn * 32 + (l15 & 7)) * 144 +
                                       ((l15 >> 3) & 1) * 16);

    float acc[4][4][4];
#pragma unroll
    for (int mt = 0; mt < 4; mt++)
#pragma unroll
        for (int nt = 0; nt < 4; nt++)
#pragma unroll
            for (int r = 0; r < 4; r++) acc[mt][nt][r] = 0.f;

    const int niter = Kdim >> 5;

    // ---- prologue: tile 0 -> stage 0 (LDG -> cvt -> STS) ----
    {
        const int k0 = 0;
#pragma unroll
        for (int t = 0; t < 4; t++) {
            int c = tid + 256 * t;
            int row = c >> 3;
            int kc = c & 7;
            float4 v = *reinterpret_cast<const float4*>(
                A + (size_t)(m0 + row) * lda + k0 + kc * 4);
            *reinterpret_cast<uint4*>(smem + row * 36 + kc * 4) =
                make_uint4(f2tf32(v.x), f2tf32(v.y), f2tf32(v.z), f2tf32(v.w));
        }
#pragma unroll
        for (int t = 0; t < 4; t++) {
            int c = tid + 256 * t;
            int n = c & 127;
            int kq = (c >> 7) << 2;
            const float* wp = W + (size_t)(k0 + kq) * ldw + n0 + n;
            uint4 v;
            v.x = f2tf32(wp[0]);
            v.y = f2tf32(wp[ldw]);
            v.z = f2tf32(wp[2 * ldw]);
            v.w = f2tf32(wp[3 * ldw]);
            *reinterpret_cast<uint4*>(smem + GTILE_F + n * 36 + kq) = v;
        }
    }

    for (int i = 0; i < niter; i++) {
        const int s = i & 1;
        __syncthreads();   // stage s fully written

        float4 areg[4], breg[4];
        const bool more = (i + 1 < niter);
        if (more) {
            const int k0 = (i + 1) << 5;
#pragma unroll
            for (int t = 0; t < 4; t++) {
                int c = tid + 256 * t;
                int row = c >> 3;
                int kc = c & 7;
                areg[t] = *reinterpret_cast<const float4*>(
                    A + (size_t)(m0 + row) * lda + k0 + kc * 4);
            }
#pragma unroll
            for (int t = 0; t < 4; t++) {
                int c = tid + 256 * t;
                int n = c & 127;
                int kq = (c >> 7) << 2;
                const float* wp = W + (size_t)(k0 + kq) * ldw + n0 + n;
                breg[t].x = wp[0];
                breg[t].y = wp[ldw];
                breg[t].z = wp[2 * ldw];
                breg[t].w = wp[3 * ldw];
            }
        }

        // ---- compute stage s: pure ldmatrix + mma (single A term) ----
        const uint32_t sbase = sb + (uint32_t)(s * GSTAGE_B);
        const uint32_t abase = sbase + a_lane;
        const uint32_t bbase = sbase + (uint32_t)GTILE_B + b_lane;
#pragma unroll
        for (int ks = 0; ks < 4; ks++) {
            uint32_t af[4][4], bf[4][2];
#pragma unroll
            for (int mt = 0; mt < 4; mt++)
                ldm_x4(af[mt], abase + mt * (16 * 144) + ks * 32);
#pragma unroll
            for (int nt = 0; nt < 4; nt++)
                ldm_x2(bf[nt], bbase + nt * (8 * 144) + ks * 32);
#pragma unroll
            for (int mt = 0; mt < 4; mt++)
#pragma unroll
                for (int nt = 0; nt < 4; nt++)
                    mma_tf32(acc[mt][nt], af[mt], bf[nt]);
        }

        // ---- convert + store prefetched tile into stage s^1 ----
        if (more) {
            float* dst = smem + (s ^ 1) * GSTAGE_F;
#pragma unroll
            for (int t = 0; t < 4; t++) {
                int c = tid + 256 * t;
                int row = c >> 3;
                int kc = c & 7;
                *reinterpret_cast<uint4*>(dst + row * 36 + kc * 4) =
                    make_uint4(f2tf32(areg[t].x), f2tf32(areg[t].y),
                               f2tf32(areg[t].z), f2tf32(areg[t].w));
            }
#pragma unroll
            for (int t = 0; t < 4; t++) {
                int c = tid + 256 * t;
                int n = c & 127;
                int kq = (c >> 7) << 2;
                uint4 v;
                v.x = f2tf32(breg[t].x);
                v.y = f2tf32(breg[t].y);
                v.z = f2tf32(breg[t].z);
                v.w = f2tf32(breg[t].w);
                *reinterpret_cast<uint4*>(dst + GTILE_F + n * 36 + kq) = v;
            }
        }
    }

    // ---- epilogue: add bias, write C ----
    const int g = lane >> 2;
    const int tig = lane & 3;
    const int row0 = m0 + wm * 64;
    const int col0 = n0 + wn * 32;
#pragma unroll
    for (int nt = 0; nt < 4; nt++) {
        const int ccol = col0 + nt * 8 + 2 * tig;
        const float b0 = bias[ccol];
        const float b1 = bias[ccol + 1];
#pragma unroll
        for (int mt = 0; mt < 4; mt++) {
            const int r = row0 + mt * 16 + g;
            float2 lo = make_float2(acc[mt][nt][0] + b0, acc[mt][nt][1] + b1);
            float2 hi = make_float2(acc[mt][nt][2] + b0, acc[mt][nt][3] + b1);
            *reinterpret_cast<float2*>(C + (size_t)r * ldc + ccol) = lo;
            *reinterpret_cast<float2*>(C + (size_t)(r + 8) * ldc + ccol) = hi;
        }
    }
}

// ---------------------------------------------------------------------------
// Tensor-core flash attention, single-rounded K/V.
// Round 13: Vs gets its own stride (72 floats) so the scalar V LDS in the PV
// loop is bank-conflict-free (bank = 8*t4 + g, all 32 lanes distinct).
// Ks/Ps keep stride 68 (ldmatrix-conflict-free). Numerics unchanged.
// Smem: Q/P (64x68) + K (64x68) + V (64x72) = 53248 B -> 3 blocks/SM.
// ---------------------------------------------------------------------------
#define ATS 68                       // floats per row: Q/P and K tiles
#define VTS 72                       // floats per row: V tile (scalar access)
#define ATT_TILE_F (64 * ATS)        // 4352 floats
#define VT_TILE_F (64 * VTS)         // 4608 floats
#define ATT_SMEM_BYTES ((2 * ATT_TILE_F + VT_TILE_F) * 4)   // 53248

__global__ __launch_bounds__(128, 3) void attn_mma_kernel(
    const float* __restrict__ Qg, const float* __restrict__ Kg,
    const float* __restrict__ Vg, float* __restrict__ Og)
{
    extern __shared__ float sm[];
    float* Ps = sm;                        // Q tile first, then P tile
    float* Ks = sm + ATT_TILE_F;           // tf32-rounded K bits (stride 68)
    float* Vs = sm + 2 * ATT_TILE_F;       // tf32-rounded V bits (stride 72)
    const uint32_t sb = smem_u32(sm);

    const int tid = threadIdx.x;
    const int lane = tid & 31;
    const int w = tid >> 5;                // warp 0..3 -> q rows [16w,16w+16)
    const int l15 = lane & 15;
    const int g = lane >> 2;               // row group in quad
    const int t4 = lane & 3;

    const int qt = blockIdx.x;
    const int h  = blockIdx.y;
    const int b  = blockIdx.z;
    const int qbase = b * PS + qt * 64;
    const int col0  = h * PHD;

    // ---- load Q tile [64 q][64 d] into Ps region ----
#pragma unroll
    for (int t = 0; t < 8; t++) {
        int idx = tid + 128 * t;
        int row = idx >> 4;
        int d4  = (idx & 15) << 2;
        *reinterpret_cast<float4*>(&Ps[row * ATS + d4]) =
            *reinterpret_cast<const float4*>(Qg + (size_t)(qbase + row) * PD + col0 + d4);
    }
    __syncthreads();

    // ---- preload Q fragments (scale folded in, tf32-rounded once) ----
    const uint32_t a_lane_off = (uint32_t)((w * 16 + l15) * (ATS * 4) + (lane >> 4) * 16);
    uint32_t qh[8][4];
#pragma unroll
    for (int ks = 0; ks < 8; ks++) {
        uint32_t raw[4];
        ldm_x4(raw, sb + a_lane_off + ks * 32);
#pragma unroll
        for (int r = 0; r < 4; r++)
            qh[ks][r] = f2tf32(0.125f * __uint_as_float(raw[r]));
    }

    float m0 = -1e30f, m1 = -1e30f, l0 = 0.f, l1 = 0.f;
    float oacc[8][4];
#pragma unroll
    for (int nt = 0; nt < 8; nt++)
#pragma unroll
        for (int r = 0; r < 4; r++) oacc[nt][r] = 0.f;

    const uint32_t kb_lane = sb + (uint32_t)(ATT_TILE_F * 4) +
                             (uint32_t)((l15 & 7) * (ATS * 4) + ((l15 >> 3) & 1) * 16);

    for (int kt = 0; kt < 16; kt++) {
        __syncthreads();                   // prev tile fully consumed
        const int kbase = b * PS + kt * 64;
        // ---- load + round K and V tiles (cvt once per block, single copy) ----
#pragma unroll
        for (int t = 0; t < 8; t++) {
            int idx = tid + 128 * t;       // 0..1023 float4s
            int row = idx >> 4;
            int d4  = (idx & 15) << 2;
            float4 kv = *reinterpret_cast<const float4*>(
                Kg + (size_t)(kbase + row) * PD + col0 + d4);
            float4 vv = *reinterpret_cast<const float4*>(
                Vg + (size_t)(kbase + row) * PD + col0 + d4);
            *reinterpret_cast<uint4*>(&Ks[row * ATS + d4]) =
                make_uint4(f2tf32(kv.x), f2tf32(kv.y), f2tf32(kv.z), f2tf32(kv.w));
            *reinterpret_cast<uint4*>(&Vs[row * VTS + d4]) =
                make_uint4(f2tf32(vv.x), f2tf32(vv.y), f2tf32(vv.z), f2tf32(vv.w));
        }
        __syncthreads();

        // ---- S = (Q*scale) @ K^T : one MMA per fragment pair ----
        float sacc[8][4];
#pragma unroll
        for (int nt = 0; nt < 8; nt++)
#pragma unroll
            for (int r = 0; r < 4; r++) sacc[nt][r] = 0.f;

#pragma unroll
        for (int ks = 0; ks < 8; ks++) {
#pragma unroll
            for (int nt = 0; nt < 8; nt++) {
                uint32_t bf[2];
                ldm_x2(bf, kb_lane + nt * (8 * ATS * 4) + ks * 32);
                mma_tf32(sacc[nt], qh[ks], bf);
            }
        }

        // ---- online softmax (rows g, g+8 of warp block) ----
        float mx0 = -1e30f, mx1 = -1e30f;
#pragma unroll
        for (int nt = 0; nt < 8; nt++) {
            mx0 = fmaxf(mx0, fmaxf(sacc[nt][0], sacc[nt][1]));
            mx1 = fmaxf(mx1, fmaxf(sacc[nt][2], sacc[nt][3]));
        }
        mx0 = fmaxf(mx0, __shfl_xor_sync(0xffffffffu, mx0, 1));
        mx0 = fmaxf(mx0, __shfl_xor_sync(0xffffffffu, mx0, 2));
        mx1 = fmaxf(mx1, __shfl_xor_sync(0xffffffffu, mx1, 1));
        mx1 = fmaxf(mx1, __shfl_xor_sync(0xffffffffu, mx1, 2));

        float nm0 = fmaxf(m0, mx0), nm1 = fmaxf(m1, mx1);
        float a0 = __expf(m0 - nm0), a1 = __expf(m1 - nm1);
        m0 = nm0;
        m1 = nm1;

        float rs0 = 0.f, rs1 = 0.f;
#pragma unroll
        for (int nt = 0; nt < 8; nt++) {
            sacc[nt][0] = __expf(sacc[nt][0] - m0);
            sacc[nt][1] = __expf(sacc[nt][1] - m0);
            sacc[nt][2] = __expf(sacc[nt][2] - m1);
            sacc[nt][3] = __expf(sacc[nt][3] - m1);
            rs0 += sacc[nt][0] + sacc[nt][1];
            rs1 += sacc[nt][2] + sacc[nt][3];
        }
        rs0 += __shfl_xor_sync(0xffffffffu, rs0, 1);
        rs0 += __shfl_xor_sync(0xffffffffu, rs0, 2);
        rs1 += __shfl_xor_sync(0xffffffffu, rs1, 1);
        rs1 += __shfl_xor_sync(0xffffffffu, rs1, 2);
        l0 = l0 * a0 + rs0;
        l1 = l1 * a1 + rs1;
#pragma unroll
        for (int nt = 0; nt < 8; nt++) {
            oacc[nt][0] *= a0;
            oacc[nt][1] *= a0;
            oacc[nt][2] *= a1;
            oacc[nt][3] *= a1;
        }

        // ---- write P to smem (own warp rows only) ----
        {
            float* pr0 = Ps + (w * 16 + g) * ATS;
            float* pr1 = pr0 + 8 * ATS;
#pragma unroll
            for (int nt = 0; nt < 8; nt++) {
                *reinterpret_cast<float2*>(pr0 + nt * 8 + 2 * t4) =
                    make_float2(sacc[nt][0], sacc[nt][1]);
                *reinterpret_cast<float2*>(pr1 + nt * 8 + 2 * t4) =
                    make_float2(sacc[nt][2], sacc[nt][3]);
            }
        }
        __syncwarp();

        // ---- O += P @ V : P cvt + conflict-free scalar V LDS, one MMA ----
#pragma unroll
        for (int ks = 0; ks < 8; ks++) {
            uint32_t praw[4], ph[4];
            ldm_x4(praw, sb + a_lane_off + ks * 32);
#pragma unroll
            for (int r = 0; r < 4; r++) ph[r] = f2tf32(__uint_as_float(praw[r]));

            const float* vb = Vs + (ks * 8 + t4) * VTS + g;
#pragma unroll
            for (int nt = 0; nt < 8; nt++) {
                uint32_t vf[2];
                vf[0] = __float_as_uint(vb[nt * 8]);
                vf[1] = __float_as_uint(vb[nt * 8 + 4 * VTS]);
                mma_tf32(oacc[nt], ph, vf);
            }
        }
    }

    // ---- normalize and store ----
    const float inv0 = 1.f / l0;
    const float inv1 = 1.f / l1;
    const int r0 = qbase + w * 16 + g;
#pragma unroll
    for (int nt = 0; nt < 8; nt++) {
        const int ccol = col0 + nt * 8 + 2 * t4;
        *reinterpret_cast<float2*>(Og + (size_t)r0 * PD + ccol) =
            make_float2(oacc[nt][0] * inv0, oacc[nt][1] * inv0);
        *reinterpret_cast<float2*>(Og + (size_t)(r0 + 8) * PD + ccol) =
            make_float2(oacc[nt][2] * inv1, oacc[nt][3] * inv1);
    }
}

// ---------------------------------------------------------------------------
// Launch: 5 kernels, default stream, graph-capturable.
// Inputs: query, value, Wq, bq, Wkv, bkv, Wo, bo
// ---------------------------------------------------------------------------
extern "C" void kernel_launch(void* const* d_in, const int* in_sizes, int n_in,
                              void* d_out, int out_size)
{
    const float* query = (const float*)d_in[0];
    const float* value = (const float*)d_in[1];
    const float* Wq    = (const float*)d_in[2];
    const float* bq    = (const float*)d_in[3];
    const float* Wkv   = (const float*)d_in[4];
    const float* bkv   = (const float*)d_in[5];
    const float* Wo    = (const float*)d_in[6];
    const float* bo    = (const float*)d_in[7];
    float* out = (float*)d_out;

    float *Qb, *Kb, *Vb, *Hb;
    cudaGetSymbolAddress((void**)&Qb, g_Q);
    cudaGetSymbolAddress((void**)&Kb, g_K);
    cudaGetSymbolAddress((void**)&Vb, g_V);
    cudaGetSymbolAddress((void**)&Hb, g_Hd);

    cudaFuncSetAttribute(gemm_mma_kernel,
                         cudaFuncAttributeMaxDynamicSharedMemorySize,
                         GEMM_SMEM_BYTES);
    cudaFuncSetAttribute(attn_mma_kernel,
                         cudaFuncAttributeMaxDynamicSharedMemorySize,
                         ATT_SMEM_BYTES);

    dim3 gemm_grid(PD / 128, PM / 128);   // (8, 64)
    dim3 attn_grid(PS / 64, PH, PB);      // (16, 16, 8)

    gemm_mma_kernel<<<gemm_grid, 256, GEMM_SMEM_BYTES>>>(
        query, PD, Wq, PD, bq, Qb, PD, PD);
    gemm_mma_kernel<<<gemm_grid, 256, GEMM_SMEM_BYTES>>>(
        value, PD, Wkv, 2 * PD, bkv, Kb, PD, PD);
    gemm_mma_kernel<<<gemm_grid, 256, GEMM_SMEM_BYTES>>>(
        value, PD, Wkv + PD, 2 * PD, bkv + PD, Vb, PD, PD);
    attn_mma_kernel<<<attn_grid, 128, ATT_SMEM_BYTES>>>(Qb, Kb, Vb, Hb);
    gemm_mma_kernel<<<gemm_grid, 256, GEMM_SMEM_BYTES>>>(
        Hb, PD, Wo, PD, bo, out, PD, PD);
}

// round 14
// speedup vs baseline: 5.9897x; 1.0639x over previous
#include <cuda_runtime.h>
#include <cstdint>

// Problem constants
#define PB 8
#define PS 1024
#define PD 1024
#define PH 16
#define PHD 64
#define PM (PB * PS)   // 8192 rows

// Scratch (device globals: no allocation allowed)
__device__ float g_Q[PM * PD];
__device__ float g_K[PM * PD];
__device__ float g_V[PM * PD];
__device__ float g_Hd[PM * PD];

// ---------------------------------------------------------------------------
// Helpers (compute_103-safe PTX only: mma.sync, ldmatrix)
// ---------------------------------------------------------------------------
__device__ __forceinline__ uint32_t smem_u32(const void* p) {
    uint32_t a;
    asm("{ .reg .u64 t; cvta.to.shared.u64 t, %1; cvt.u32.u64 %0, t; }"
        : "=r"(a) : "l"(p));
    return a;
}

__device__ __forceinline__ void ldm_x4(uint32_t* r, uint32_t addr) {
    asm volatile("ldmatrix.sync.aligned.m8n8.x4.shared.b16 {%0,%1,%2,%3}, [%4];"
                 : "=r"(r[0]), "=r"(r[1]), "=r"(r[2]), "=r"(r[3]) : "r"(addr));
}
__device__ __forceinline__ void ldm_x2(uint32_t* r, uint32_t addr) {
    asm volatile("ldmatrix.sync.aligned.m8n8.x2.shared.b16 {%0,%1}, [%2];"
                 : "=r"(r[0]), "=r"(r[1]) : "r"(addr));
}

// Round-to-nearest fp32 -> tf32 (bits usable directly as mma operand)
__device__ __forceinline__ uint32_t f2tf32(float f) {
    uint32_t r;
    asm("cvt.rna.tf32.f32 %0, %1;" : "=r"(r) : "f"(f));
    return r;
}

__device__ __forceinline__ void mma_tf32(float* d, const uint32_t* a,
                                         const uint32_t* b) {
    asm volatile(
        "mma.sync.aligned.m16n8k8.row.col.f32.tf32.tf32.f32 "
        "{%0,%1,%2,%3}, {%4,%5,%6,%7}, {%8,%9}, {%0,%1,%2,%3};"
        : "+f"(d[0]), "+f"(d[1]), "+f"(d[2]), "+f"(d[3])
        : "r"(a[0]), "r"(a[1]), "r"(a[2]), "r"(a[3]), "r"(b[0]), "r"(b[1]));
}

// ---------------------------------------------------------------------------
// tf32 mma.sync GEMM (FROZEN from round 13): single-rounded A/B, 2 CTAs/SM.
//   C[M x N] = A[M x K] @ W[K x N] + bias
// CTA tile 128x128, BK=32, 8 warps (2M x 4N), warp tile 64x32.
// ---------------------------------------------------------------------------
#define GTILE_F 4608                     // 128 * 36 floats
#define GTILE_B (GTILE_F * 4)            // 18432 bytes
#define GSTAGE_F (2 * GTILE_F)           // A + B per stage
#define GSTAGE_B (GSTAGE_F * 4)          // 36864 bytes
#define GEMM_SMEM_BYTES (2 * GSTAGE_B)   // 73728

__global__ __launch_bounds__(256, 2) void gemm_mma_kernel(
    const float* __restrict__ A, int lda,
    const float* __restrict__ W, int ldw,
    const float* __restrict__ bias,
    float* __restrict__ C, int ldc, int Kdim)
{
    extern __shared__ float smem[];
    const uint32_t sb = smem_u32(smem);
    const int tid = threadIdx.x;
    const int lane = tid & 31;
    const int wid = tid >> 5;
    const int wm = wid & 1;
    const int wn = wid >> 1;
    const int m0 = blockIdx.y * 128;
    const int n0 = blockIdx.x * 128;

    const int l15 = lane & 15;
    const uint32_t a_lane = (uint32_t)((wm * 64 + l15) * 144 + (lane >> 4) * 16);
    const uint32_t b_lane = (uint32_t)((wn * 32 + (l15 & 7)) * 144 +
                                       ((l15 >> 3) & 1) * 16);

    float acc[4][4][4];
#pragma unroll
    for (int mt = 0; mt < 4; mt++)
#pragma unroll
        for (int nt = 0; nt < 4; nt++)
#pragma unroll
            for (int r = 0; r < 4; r++) acc[mt][nt][r] = 0.f;

    const int niter = Kdim >> 5;

    // ---- prologue: tile 0 -> stage 0 (LDG -> cvt -> STS) ----
    {
        const int k0 = 0;
#pragma unroll
        for (int t = 0; t < 4; t++) {
            int c = tid + 256 * t;
            int row = c >> 3;
            int kc = c & 7;
            float4 v = *reinterpret_cast<const float4*>(
                A + (size_t)(m0 + row) * lda + k0 + kc * 4);
            *reinterpret_cast<uint4*>(smem + row * 36 + kc * 4) =
                make_uint4(f2tf32(v.x), f2tf32(v.y), f2tf32(v.z), f2tf32(v.w));
        }
#pragma unroll
        for (int t = 0; t < 4; t++) {
            int c = tid + 256 * t;
            int n = c & 127;
            int kq = (c >> 7) << 2;
            const float* wp = W + (size_t)(k0 + kq) * ldw + n0 + n;
            uint4 v;
            v.x = f2tf32(wp[0]);
            v.y = f2tf32(wp[ldw]);
            v.z = f2tf32(wp[2 * ldw]);
            v.w = f2tf32(wp[3 * ldw]);
            *reinterpret_cast<uint4*>(smem + GTILE_F + n * 36 + kq) = v;
        }
    }

    for (int i = 0; i < niter; i++) {
        const int s = i & 1;
        __syncthreads();   // stage s fully written

        float4 areg[4], breg[4];
        const bool more = (i + 1 < niter);
        if (more) {
            const int k0 = (i + 1) << 5;
#pragma unroll
            for (int t = 0; t < 4; t++) {
                int c = tid + 256 * t;
                int row = c >> 3;
                int kc = c & 7;
                areg[t] = *reinterpret_cast<const float4*>(
                    A + (size_t)(m0 + row) * lda + k0 + kc * 4);
            }
#pragma unroll
            for (int t = 0; t < 4; t++) {
                int c = tid + 256 * t;
                int n = c & 127;
                int kq = (c >> 7) << 2;
                const float* wp = W + (size_t)(k0 + kq) * ldw + n0 + n;
                breg[t].x = wp[0];
                breg[t].y = wp[ldw];
                breg[t].z = wp[2 * ldw];
                breg[t].w = wp[3 * ldw];
            }
        }

        // ---- compute stage s: pure ldmatrix + mma (single A term) ----
        const uint32_t sbase = sb + (uint32_t)(s * GSTAGE_B);
        const uint32_t abase = sbase + a_lane;
        const uint32_t bbase = sbase + (uint32_t)GTILE_B + b_lane;
#pragma unroll
        for (int ks = 0; ks < 4; ks++) {
            uint32_t af[4][4], bf[4][2];
#pragma unroll
            for (int mt = 0; mt < 4; mt++)
                ldm_x4(af[mt], abase + mt * (16 * 144) + ks * 32);
#pragma unroll
            for (int nt = 0; nt < 4; nt++)
                ldm_x2(bf[nt], bbase + nt * (8 * 144) + ks * 32);
#pragma unroll
            for (int mt = 0; mt < 4; mt++)
#pragma unroll
                for (int nt = 0; nt < 4; nt++)
                    mma_tf32(acc[mt][nt], af[mt], bf[nt]);
        }

        // ---- convert + store prefetched tile into stage s^1 ----
        if (more) {
            float* dst = smem + (s ^ 1) * GSTAGE_F;
#pragma unroll
            for (int t = 0; t < 4; t++) {
                int c = tid + 256 * t;
                int row = c >> 3;
                int kc = c & 7;
                *reinterpret_cast<uint4*>(dst + row * 36 + kc * 4) =
                    make_uint4(f2tf32(areg[t].x), f2tf32(areg[t].y),
                               f2tf32(areg[t].z), f2tf32(areg[t].w));
            }
#pragma unroll
            for (int t = 0; t < 4; t++) {
                int c = tid + 256 * t;
                int n = c & 127;
                int kq = (c >> 7) << 2;
                uint4 v;
                v.x = f2tf32(breg[t].x);
                v.y = f2tf32(breg[t].y);
                v.z = f2tf32(breg[t].z);
                v.w = f2tf32(breg[t].w);
                *reinterpret_cast<uint4*>(dst + GTILE_F + n * 36 + kq) = v;
            }
        }
    }

    // ---- epilogue: add bias, write C ----
    const int g = lane >> 2;
    const int tig = lane & 3;
    const int row0 = m0 + wm * 64;
    const int col0 = n0 + wn * 32;
#pragma unroll
    for (int nt = 0; nt < 4; nt++) {
        const int ccol = col0 + nt * 8 + 2 * tig;
        const float b0 = bias[ccol];
        const float b1 = bias[ccol + 1];
#pragma unroll
        for (int mt = 0; mt < 4; mt++) {
            const int r = row0 + mt * 16 + g;
            float2 lo = make_float2(acc[mt][nt][0] + b0, acc[mt][nt][1] + b1);
            float2 hi = make_float2(acc[mt][nt][2] + b0, acc[mt][nt][3] + b1);
            *reinterpret_cast<float2*>(C + (size_t)r * ldc + ccol) = lo;
            *reinterpret_cast<float2*>(C + (size_t)(r + 8) * ldc + ccol) = hi;
        }
    }
}

// ---------------------------------------------------------------------------
// Tensor-core flash attention — round 14 restructure.
// 256 threads / 8 warps, q-tile 128 rows (warp w owns rows 16w..16w+15).
// Q stored PRE-ROUNDED (tf32 bits) in a RESIDENT smem buffer -> per-kt Q
// fragment fetch is a bare ldmatrix (no reg array, no cvt). The 1/8 softmax
// scale is folded into the K loader (pow2 scale commutes exactly with
// rounding -> numerics identical to round 13).
// Smem: Qs(128x68) + Pp(128x68) + Ks(64x68) + Vs(64x72) = 105472 B.
// launch_bounds(256,2) -> 16 warps/SM.
// ---------------------------------------------------------------------------
#define ATS 68                       // floats per row: Q/P and K tiles
#define VTS 72                       // floats per row: V tile (scalar access)
#define AQ_TILE_F (128 * ATS)        // 8704 floats (Q and P buffers)
#define AK_TILE_F (64 * ATS)         // 4352 floats
#define AV_TILE_F (64 * VTS)         // 4608 floats
#define OFF_P (AQ_TILE_F)
#define OFF_K (2 * AQ_TILE_F)
#define OFF_V (2 * AQ_TILE_F + AK_TILE_F)
#define ATT_SMEM_BYTES ((2 * AQ_TILE_F + AK_TILE_F + AV_TILE_F) * 4)  // 105472

__global__ __launch_bounds__(256, 2) void attn_mma_kernel(
    const float* __restrict__ Qg, const float* __restrict__ Kg,
    const float* __restrict__ Vg, float* __restrict__ Og)
{
    extern __shared__ float sm[];
    float* Qs = sm;                        // tf32-rounded Q bits (resident)
    float* Pp = sm + OFF_P;                // P round-trip buffer
    float* Ks = sm + OFF_K;                // tf32-rounded scaled K bits
    float* Vs = sm + OFF_V;                // tf32-rounded V bits (stride 72)
    const uint32_t sb = smem_u32(sm);

    const int tid = threadIdx.x;
    const int lane = tid & 31;
    const int w = tid >> 5;                // warp 0..7 -> q rows [16w,16w+16)
    const int l15 = lane & 15;
    const int g = lane >> 2;               // row group in quad
    const int t4 = lane & 3;

    const int qt = blockIdx.x;             // 0..7 (128-row q tiles)
    const int h  = blockIdx.y;
    const int b  = blockIdx.z;
    const int qbase = b * PS + qt * 128;
    const int col0  = h * PHD;

    // ---- load Q tile [128 q][64 d], rounded to tf32 bits, RESIDENT ----
#pragma unroll
    for (int t = 0; t < 8; t++) {
        int idx = tid + 256 * t;           // 0..2047 float4s
        int row = idx >> 4;                // 0..127
        int d4  = (idx & 15) << 2;
        float4 q = *reinterpret_cast<const float4*>(
            Qg + (size_t)(qbase + row) * PD + col0 + d4);
        *reinterpret_cast<uint4*>(&Qs[row * ATS + d4]) =
            make_uint4(f2tf32(q.x), f2tf32(q.y), f2tf32(q.z), f2tf32(q.w));
    }

    float m0 = -1e30f, m1 = -1e30f, l0 = 0.f, l1 = 0.f;
    float oacc[8][4];
#pragma unroll
    for (int nt = 0; nt < 8; nt++)
#pragma unroll
        for (int r = 0; r < 4; r++) oacc[nt][r] = 0.f;

    // ldmatrix lane offsets
    const uint32_t a_lane_off = (uint32_t)((w * 16 + l15) * (ATS * 4) + (lane >> 4) * 16);
    const uint32_t q_lane = sb + a_lane_off;
    const uint32_t p_lane = sb + (uint32_t)(OFF_P * 4) + a_lane_off;
    const uint32_t kb_lane = sb + (uint32_t)(OFF_K * 4) +
                             (uint32_t)((l15 & 7) * (ATS * 4) + ((l15 >> 3) & 1) * 16);

    __syncthreads();   // Q resident before first kt (aliases nothing)

    for (int kt = 0; kt < 16; kt++) {
        const int kbase = b * PS + kt * 64;
        // ---- load + round K (scale folded) and V tiles ----
#pragma unroll
        for (int t = 0; t < 4; t++) {
            int idx = tid + 256 * t;       // 0..1023 float4s
            int row = idx >> 4;
            int d4  = (idx & 15) << 2;
            float4 kv = *reinterpret_cast<const float4*>(
                Kg + (size_t)(kbase + row) * PD + col0 + d4);
            float4 vv = *reinterpret_cast<const float4*>(
                Vg + (size_t)(kbase + row) * PD + col0 + d4);
            *reinterpret_cast<uint4*>(&Ks[row * ATS + d4]) =
                make_uint4(f2tf32(0.125f * kv.x), f2tf32(0.125f * kv.y),
                           f2tf32(0.125f * kv.z), f2tf32(0.125f * kv.w));
            *reinterpret_cast<uint4*>(&Vs[row * VTS + d4]) =
                make_uint4(f2tf32(vv.x), f2tf32(vv.y), f2tf32(vv.z), f2tf32(vv.w));
        }
        __syncthreads();

        // ---- S = Q @ (K*scale)^T : bare ldmatrix + mma ----
        float sacc[8][4];
#pragma unroll
        for (int nt = 0; nt < 8; nt++)
#pragma unroll
            for (int r = 0; r < 4; r++) sacc[nt][r] = 0.f;

#pragma unroll
        for (int ks = 0; ks < 8; ks++) {
            uint32_t qf[4];
            ldm_x4(qf, q_lane + ks * 32);
#pragma unroll
            for (int nt = 0; nt < 8; nt++) {
                uint32_t bf[2];
                ldm_x2(bf, kb_lane + nt * (8 * ATS * 4) + ks * 32);
                mma_tf32(sacc[nt], qf, bf);
            }
        }

        // ---- online softmax (rows g, g+8 of warp block) ----
        float mx0 = -1e30f, mx1 = -1e30f;
#pragma unroll
        for (int nt = 0; nt < 8; nt++) {
            mx0 = fmaxf(mx0, fmaxf(sacc[nt][0], sacc[nt][1]));
            mx1 = fmaxf(mx1, fmaxf(sacc[nt][2], sacc[nt][3]));
        }
        mx0 = fmaxf(mx0, __shfl_xor_sync(0xffffffffu, mx0, 1));
        mx0 = fmaxf(mx0, __shfl_xor_sync(0xffffffffu, mx0, 2));
        mx1 = fmaxf(mx1, __shfl_xor_sync(0xffffffffu, mx1, 1));
        mx1 = fmaxf(mx1, __shfl_xor_sync(0xffffffffu, mx1, 2));

        float nm0 = fmaxf(m0, mx0), nm1 = fmaxf(m1, mx1);
        float a0 = __expf(m0 - nm0), a1 = __expf(m1 - nm1);
        m0 = nm0;
        m1 = nm1;

        float rs0 = 0.f, rs1 = 0.f;
#pragma unroll
        for (int nt = 0; nt < 8; nt++) {
            sacc[nt][0] = __expf(sacc[nt][0] - m0);
            sacc[nt][1] = __expf(sacc[nt][1] - m0);
            sacc[nt][2] = __expf(sacc[nt][2] - m1);
            sacc[nt][3] = __expf(sacc[nt][3] - m1);
            rs0 += sacc[nt][0] + sacc[nt][1];
            rs1 += sacc[nt][2] + sacc[nt][3];
        }
        rs0 += __shfl_xor_sync(0xffffffffu, rs0, 1);
        rs0 += __shfl_xor_sync(0xffffffffu, rs0, 2);
        rs1 += __shfl_xor_sync(0xffffffffu, rs1, 1);
        rs1 += __shfl_xor_sync(0xffffffffu, rs1, 2);
        l0 = l0 * a0 + rs0;
        l1 = l1 * a1 + rs1;
#pragma unroll
        for (int nt = 0; nt < 8; nt++) {
            oacc[nt][0] *= a0;
            oacc[nt][1] *= a0;
            oacc[nt][2] *= a1;
            oacc[nt][3] *= a1;
        }

        // ---- write P to smem (own warp rows only) ----
        {
            float* pr0 = Pp + (w * 16 + g) * ATS;
            float* pr1 = pr0 + 8 * ATS;
#pragma unroll
            for (int nt = 0; nt < 8; nt++) {
                *reinterpret_cast<float2*>(pr0 + nt * 8 + 2 * t4) =
                    make_float2(sacc[nt][0], sacc[nt][1]);
                *reinterpret_cast<float2*>(pr1 + nt * 8 + 2 * t4) =
                    make_float2(sacc[nt][2], sacc[nt][3]);
            }
        }
        __syncwarp();

        // ---- O += P @ V : P cvt + conflict-free scalar V LDS ----
#pragma unroll
        for (int ks = 0; ks < 8; ks++) {
            uint32_t praw[4], ph[4];
            ldm_x4(praw, p_lane + ks * 32);
#pragma unroll
            for (int r = 0; r < 4; r++) ph[r] = f2tf32(__uint_as_float(praw[r]));

            const float* vb = Vs + (ks * 8 + t4) * VTS + g;
#pragma unroll
            for (int nt = 0; nt < 8; nt++) {
                uint32_t vf[2];
                vf[0] = __float_as_uint(vb[nt * 8]);
                vf[1] = __float_as_uint(vb[nt * 8 + 4 * VTS]);
                mma_tf32(oacc[nt], ph, vf);
            }
        }
        __syncthreads();   // all warps done with Ks/Vs before next load
    }

    // ---- normalize and store ----
    const float inv0 = 1.f / l0;
    const float inv1 = 1.f / l1;
    const int r0 = qbase + w * 16 + g;
#pragma unroll
    for (int nt = 0; nt < 8; nt++) {
        const int ccol = col0 + nt * 8 + 2 * t4;
        *reinterpret_cast<float2*>(Og + (size_t)r0 * PD + ccol) =
            make_float2(oacc[nt][0] * inv0, oacc[nt][1] * inv0);
        *reinterpret_cast<float2*>(Og + (size_t)(r0 + 8) * PD + ccol) =
            make_float2(oacc[nt][2] * inv1, oacc[nt][3] * inv1);
    }
}

// ---------------------------------------------------------------------------
// Launch: 5 kernels, default stream, graph-capturable.
// Inputs: query, value, Wq, bq, Wkv, bkv, Wo, bo
// ---------------------------------------------------------------------------
extern "C" void kernel_launch(void* const* d_in, const int* in_sizes, int n_in,
                              void* d_out, int out_size)
{
    const float* query = (const float*)d_in[0];
    const float* value = (const float*)d_in[1];
    const float* Wq    = (const float*)d_in[2];
    const float* bq    = (const float*)d_in[3];
    const float* Wkv   = (const float*)d_in[4];
    const float* bkv   = (const float*)d_in[5];
    const float* Wo    = (const float*)d_in[6];
    const float* bo    = (const float*)d_in[7];
    float* out = (float*)d_out;

    float *Qb, *Kb, *Vb, *Hb;
    cudaGetSymbolAddress((void**)&Qb, g_Q);
    cudaGetSymbolAddress((void**)&Kb, g_K);
    cudaGetSymbolAddress((void**)&Vb, g_V);
    cudaGetSymbolAddress((void**)&Hb, g_Hd);

    cudaFuncSetAttribute(gemm_mma_kernel,
                         cudaFuncAttributeMaxDynamicSharedMemorySize,
                         GEMM_SMEM_BYTES);
    cudaFuncSetAttribute(attn_mma_kernel,
                         cudaFuncAttributeMaxDynamicSharedMemorySize,
                         ATT_SMEM_BYTES);

    dim3 gemm_grid(PD / 128, PM / 128);   // (8, 64)
    dim3 attn_grid(PS / 128, PH, PB);     // (8, 16, 8)

    gemm_mma_kernel<<<gemm_grid, 256, GEMM_SMEM_BYTES>>>(
        query, PD, Wq, PD, bq, Qb, PD, PD);
    gemm_mma_kernel<<<gemm_grid, 256, GEMM_SMEM_BYTES>>>(
        value, PD, Wkv, 2 * PD, bkv, Kb, PD, PD);
    gemm_mma_kernel<<<gemm_grid, 256, GEMM_SMEM_BYTES>>>(
        value, PD, Wkv + PD, 2 * PD, bkv + PD, Vb, PD, PD);
    attn_mma_kernel<<<attn_grid, 256, ATT_SMEM_BYTES>>>(Qb, Kb, Vb, Hb);
    gemm_mma_kernel<<<gemm_grid, 256, GEMM_SMEM_BYTES>>>(
        Hb, PD, Wo, PD, bo, out, PD, PD);
}

// round 15
// speedup vs baseline: 9.7044x; 1.6202x over previous
#include <cuda_runtime.h>
#include <cuda_fp16.h>
#include <cstdint>

// Problem constants
#define PB 8
#define PS 1024
#define PD 1024
#define PH 16
#define PHD 64
#define PM (PB * PS)   // 8192 rows

// Scratch (device globals: no allocation allowed)
__device__ float g_Q[PM * PD];
__device__ float g_K[PM * PD];
__device__ float g_V[PM * PD];
__device__ float g_Hd[PM * PD];

// ---------------------------------------------------------------------------
// Helpers (compute_103-safe PTX only: mma.sync, ldmatrix)
// ---------------------------------------------------------------------------
__device__ __forceinline__ uint32_t smem_u32(const void* p) {
    uint32_t a;
    asm("{ .reg .u64 t; cvta.to.shared.u64 t, %1; cvt.u32.u64 %0, t; }"
        : "=r"(a) : "l"(p));
    return a;
}

__device__ __forceinline__ void ldm_x4(uint32_t* r, uint32_t addr) {
    asm volatile("ldmatrix.sync.aligned.m8n8.x4.shared.b16 {%0,%1,%2,%3}, [%4];"
                 : "=r"(r[0]), "=r"(r[1]), "=r"(r[2]), "=r"(r[3]) : "r"(addr));
}
__device__ __forceinline__ void ldm_x2(uint32_t* r, uint32_t addr) {
    asm volatile("ldmatrix.sync.aligned.m8n8.x2.shared.b16 {%0,%1}, [%2];"
                 : "=r"(r[0]), "=r"(r[1]) : "r"(addr));
}
__device__ __forceinline__ void ldm_x2t(uint32_t* r, uint32_t addr) {
    asm volatile("ldmatrix.sync.aligned.m8n8.x2.trans.shared.b16 {%0,%1}, [%2];"
                 : "=r"(r[0]), "=r"(r[1]) : "r"(addr));
}

// fp16 mma: m16n8k16, row.col, f32 accumulate
__device__ __forceinline__ void mma_f16(float* d, const uint32_t* a,
                                        const uint32_t* b) {
    asm volatile(
        "mma.sync.aligned.m16n8k16.row.col.f32.f16.f16.f32 "
        "{%0,%1,%2,%3}, {%4,%5,%6,%7}, {%8,%9}, {%0,%1,%2,%3};"
        : "+f"(d[0]), "+f"(d[1]), "+f"(d[2]), "+f"(d[3])
        : "r"(a[0]), "r"(a[1]), "r"(a[2]), "r"(a[3]), "r"(b[0]), "r"(b[1]));
}

__device__ __forceinline__ uint32_t pack_h2(float a, float b) {
    __half2 h = __floats2half2_rn(a, b);   // .x = a (low half)
    return *reinterpret_cast<uint32_t*>(&h);
}

// ---------------------------------------------------------------------------
// fp16 mma.sync GEMM: C[M x N] = A[M x K] @ W[K x N] + bias (f32 acc)
// CTA tile 128x128, BK=32, 8 warps (2M x 4N), warp tile 64x32.
// A tile: half [128 m][32 k], row stride 80 B (conflict-free ldmatrix).
// B tile: half [32 k][128 n] NATURAL, row stride 272 B; fragments via
//         ldmatrix.x2.trans (no transpose-on-load needed).
// Double-buffered; LDG->reg prefetch overlaps compute; cvt at store time.
// ---------------------------------------------------------------------------
#define GAS_B 80                         // A row stride bytes
#define GBS_B 272                        // B row stride bytes
#define GA_BYTES (128 * GAS_B)           // 10240
#define GB_BYTES (32 * GBS_B)            // 8704
#define GSTG_B (GA_BYTES + GB_BYTES)     // 18944
#define GEMM_SMEM_BYTES (2 * GSTG_B)     // 37888

__global__ __launch_bounds__(256, 2) void gemm_mma_kernel(
    const float* __restrict__ A, int lda,
    const float* __restrict__ W, int ldw,
    const float* __restrict__ bias,
    float* __restrict__ C, int ldc, int Kdim)
{
    extern __shared__ uint8_t gsm[];
    const uint32_t sb = smem_u32(gsm);
    const int tid = threadIdx.x;
    const int lane = tid & 31;
    const int wid = tid >> 5;
    const int wm = wid & 1;
    const int wn = wid >> 1;
    const int m0 = blockIdx.y * 128;
    const int n0 = blockIdx.x * 128;

    const int l15 = lane & 15;
    const uint32_t a_lane = (uint32_t)((wm * 64 + l15) * GAS_B + (lane >> 4) * 16);
    const uint32_t b_lane = (uint32_t)(l15 * GBS_B + wn * 64);   // wn*32 halves

    float acc[4][4][4];
#pragma unroll
    for (int mt = 0; mt < 4; mt++)
#pragma unroll
        for (int nt = 0; nt < 4; nt++)
#pragma unroll
            for (int r = 0; r < 4; r++) acc[mt][nt][r] = 0.f;

    const int niter = Kdim >> 5;

    // ---- prologue: tile 0 -> stage 0 (LDG -> cvt -> STS half) ----
    {
        const int k0 = 0;
#pragma unroll
        for (int t = 0; t < 4; t++) {
            int c = tid + 256 * t;          // 0..1023
            int row = c >> 3;               // 0..127
            int kc = c & 7;                 // float4 within 32 k
            float4 v = *reinterpret_cast<const float4*>(
                A + (size_t)(m0 + row) * lda + k0 + kc * 4);
            uint2 h = make_uint2(pack_h2(v.x, v.y), pack_h2(v.z, v.w));
            *reinterpret_cast<uint2*>(gsm + row * GAS_B + kc * 8) = h;
        }
#pragma unroll
        for (int t = 0; t < 4; t++) {
            int c = tid + 256 * t;
            int row = c >> 5;               // 0..31 (k)
            int nc = c & 31;                // float4 within 128 n
            float4 v = *reinterpret_cast<const float4*>(
                W + (size_t)(k0 + row) * ldw + n0 + nc * 4);
            uint2 h = make_uint2(pack_h2(v.x, v.y), pack_h2(v.z, v.w));
            *reinterpret_cast<uint2*>(gsm + GA_BYTES + row * GBS_B + nc * 8) = h;
        }
    }

    for (int i = 0; i < niter; i++) {
        const int s = i & 1;
        __syncthreads();   // stage s fully written

        float4 areg[4], breg[4];
        const bool more = (i + 1 < niter);
        if (more) {
            const int k0 = (i + 1) << 5;
#pragma unroll
            for (int t = 0; t < 4; t++) {
                int c = tid + 256 * t;
                int row = c >> 3;
                int kc = c & 7;
                areg[t] = *reinterpret_cast<const float4*>(
                    A + (size_t)(m0 + row) * lda + k0 + kc * 4);
            }
#pragma unroll
            for (int t = 0; t < 4; t++) {
                int c = tid + 256 * t;
                int row = c >> 5;
                int nc = c & 31;
                breg[t] = *reinterpret_cast<const float4*>(
                    W + (size_t)(k0 + row) * ldw + n0 + nc * 4);
            }
        }

        // ---- compute stage s: pure ldmatrix + fp16 mma ----
        const uint32_t sbase = sb + (uint32_t)(s * GSTG_B);
        const uint32_t abase = sbase + a_lane;
        const uint32_t bbase = sbase + (uint32_t)GA_BYTES + b_lane;
#pragma unroll
        for (int ks = 0; ks < 2; ks++) {    // 2 x k16 = BK 32
            uint32_t af[4][4], bf[4][2];
#pragma unroll
            for (int mt = 0; mt < 4; mt++)
                ldm_x4(af[mt], abase + mt * (16 * GAS_B) + ks * 32);
#pragma unroll
            for (int nt = 0; nt < 4; nt++)
                ldm_x2t(bf[nt], bbase + ks * (16 * GBS_B) + nt * 16);
#pragma unroll
            for (int mt = 0; mt < 4; mt++)
#pragma unroll
                for (int nt = 0; nt < 4; nt++)
                    mma_f16(acc[mt][nt], af[mt], bf[nt]);
        }

        // ---- convert + store prefetched tile into stage s^1 ----
        if (more) {
            uint8_t* dst = gsm + (s ^ 1) * GSTG_B;
#pragma unroll
            for (int t = 0; t < 4; t++) {
                int c = tid + 256 * t;
                int row = c >> 3;
                int kc = c & 7;
                uint2 h = make_uint2(pack_h2(areg[t].x, areg[t].y),
                                     pack_h2(areg[t].z, areg[t].w));
                *reinterpret_cast<uint2*>(dst + row * GAS_B + kc * 8) = h;
            }
#pragma unroll
            for (int t = 0; t < 4; t++) {
                int c = tid + 256 * t;
                int row = c >> 5;
                int nc = c & 31;
                uint2 h = make_uint2(pack_h2(breg[t].x, breg[t].y),
                                     pack_h2(breg[t].z, breg[t].w));
                *reinterpret_cast<uint2*>(dst + GA_BYTES + row * GBS_B + nc * 8) = h;
            }
        }
    }

    // ---- epilogue: add bias, write C ----
    const int g = lane >> 2;
    const int tig = lane & 3;
    const int row0 = m0 + wm * 64;
    const int col0 = n0 + wn * 32;
#pragma unroll
    for (int nt = 0; nt < 4; nt++) {
        const int ccol = col0 + nt * 8 + 2 * tig;
        const float b0 = bias[ccol];
        const float b1 = bias[ccol + 1];
#pragma unroll
        for (int mt = 0; mt < 4; mt++) {
            const int r = row0 + mt * 16 + g;
            float2 lo = make_float2(acc[mt][nt][0] + b0, acc[mt][nt][1] + b1);
            float2 hi = make_float2(acc[mt][nt][2] + b0, acc[mt][nt][3] + b1);
            *reinterpret_cast<float2*>(C + (size_t)r * ldc + ccol) = lo;
            *reinterpret_cast<float2*>(C + (size_t)(r + 8) * ldc + ccol) = hi;
        }
    }
}

// ---------------------------------------------------------------------------
// Tensor-core flash attention — fp16 m16n8k16 (round 15).
// 256 threads / 8 warps, q-tile 128 rows (warp w owns rows 16w..16w+15).
// Q resident as half (rounded once); 1/8 scale folded into K loader (pow2,
// exact). K natural [key][d] via non-trans x2; V natural via x2.trans
// (fragment = V^T, no scalar LDS). P stored as half2 (2^-11 rounding, same
// as the old tf32 P rounding).
// Smem: Qs(128x144B) + Pp(128x144B) + Ks(64x144B) + Vs(64x144B) = 55296 B.
// ---------------------------------------------------------------------------
#define ARS_B 144                        // row stride bytes (72 halves)
#define AQ_BYTES (128 * ARS_B)           // 18432
#define AK_BYTES (64 * ARS_B)            // 9216
#define OFFP_B AQ_BYTES
#define OFFK_B (2 * AQ_BYTES)
#define OFFV_B (2 * AQ_BYTES + AK_BYTES)
#define ATT_SMEM_BYTES (2 * AQ_BYTES + 2 * AK_BYTES)   // 55296

__global__ __launch_bounds__(256, 2) void attn_mma_kernel(
    const float* __restrict__ Qg, const float* __restrict__ Kg,
    const float* __restrict__ Vg, float* __restrict__ Og)
{
    extern __shared__ uint8_t asm_[];
    const uint32_t sb = smem_u32(asm_);

    const int tid = threadIdx.x;
    const int lane = tid & 31;
    const int w = tid >> 5;                // warp 0..7 -> q rows [16w,16w+16)
    const int l15 = lane & 15;
    const int g = lane >> 2;               // row group in quad
    const int t4 = lane & 3;

    const int qt = blockIdx.x;             // 0..7 (128-row q tiles)
    const int h  = blockIdx.y;
    const int b  = blockIdx.z;
    const int qbase = b * PS + qt * 128;
    const int col0  = h * PHD;

    // ---- load Q tile [128 q][64 d] as half, RESIDENT ----
#pragma unroll
    for (int t = 0; t < 8; t++) {
        int idx = tid + 256 * t;           // 0..2047 float4s
        int row = idx >> 4;                // 0..127
        int d4  = (idx & 15) << 2;
        float4 q = *reinterpret_cast<const float4*>(
            Qg + (size_t)(qbase + row) * PD + col0 + d4);
        uint2 hq = make_uint2(pack_h2(q.x, q.y), pack_h2(q.z, q.w));
        *reinterpret_cast<uint2*>(asm_ + row * ARS_B + d4 * 2) = hq;
    }

    float m0 = -1e30f, m1 = -1e30f, l0 = 0.f, l1 = 0.f;
    float oacc[8][4];
#pragma unroll
    for (int nt = 0; nt < 8; nt++)
#pragma unroll
        for (int r = 0; r < 4; r++) oacc[nt][r] = 0.f;

    // ldmatrix lane offsets
    const uint32_t a_lane_off = (uint32_t)((w * 16 + l15) * ARS_B + (lane >> 4) * 16);
    const uint32_t q_lane = sb + a_lane_off;
    const uint32_t p_lane = sb + (uint32_t)OFFP_B + a_lane_off;
    const uint32_t kb_lane = sb + (uint32_t)OFFK_B +
                             (uint32_t)((l15 & 7) * ARS_B + ((l15 >> 3) & 1) * 16);
    const uint32_t vb_lane = sb + (uint32_t)OFFV_B + (uint32_t)(l15 * ARS_B);

    __syncthreads();   // Q resident before first kt

    for (int kt = 0; kt < 16; kt++) {
        const int kbase = b * PS + kt * 64;
        // ---- load K (scale folded) and V tiles as half ----
#pragma unroll
        for (int t = 0; t < 4; t++) {
            int idx = tid + 256 * t;       // 0..1023 float4s
            int row = idx >> 4;            // 0..63
            int d4  = (idx & 15) << 2;
            float4 kv = *reinterpret_cast<const float4*>(
                Kg + (size_t)(kbase + row) * PD + col0 + d4);
            float4 vv = *reinterpret_cast<const float4*>(
                Vg + (size_t)(kbase + row) * PD + col0 + d4);
            uint2 hk = make_uint2(pack_h2(0.125f * kv.x, 0.125f * kv.y),
                                  pack_h2(0.125f * kv.z, 0.125f * kv.w));
            uint2 hv = make_uint2(pack_h2(vv.x, vv.y), pack_h2(vv.z, vv.w));
            *reinterpret_cast<uint2*>(asm_ + OFFK_B + row * ARS_B + d4 * 2) = hk;
            *reinterpret_cast<uint2*>(asm_ + OFFV_B + row * ARS_B + d4 * 2) = hv;
        }
        __syncthreads();

        // ---- S = Q @ (K*scale)^T : 4 x k16 over d ----
        float sacc[8][4];
#pragma unroll
        for (int nt = 0; nt < 8; nt++)
#pragma unroll
            for (int r = 0; r < 4; r++) sacc[nt][r] = 0.f;

#pragma unroll
        for (int ks = 0; ks < 4; ks++) {
            uint32_t qf[4];
            ldm_x4(qf, q_lane + ks * 32);
#pragma unroll
            for (int nt = 0; nt < 8; nt++) {
                uint32_t bf[2];
                ldm_x2(bf, kb_lane + nt * (8 * ARS_B) + ks * 32);
                mma_f16(sacc[nt], qf, bf);
            }
        }

        // ---- online softmax (rows g, g+8 of warp block) ----
        float mx0 = -1e30f, mx1 = -1e30f;
#pragma unroll
        for (int nt = 0; nt < 8; nt++) {
            mx0 = fmaxf(mx0, fmaxf(sacc[nt][0], sacc[nt][1]));
            mx1 = fmaxf(mx1, fmaxf(sacc[nt][2], sacc[nt][3]));
        }
        mx0 = fmaxf(mx0, __shfl_xor_sync(0xffffffffu, mx0, 1));
        mx0 = fmaxf(mx0, __shfl_xor_sync(0xffffffffu, mx0, 2));
        mx1 = fmaxf(mx1, __shfl_xor_sync(0xffffffffu, mx1, 1));
        mx1 = fmaxf(mx1, __shfl_xor_sync(0xffffffffu, mx1, 2));

        float nm0 = fmaxf(m0, mx0), nm1 = fmaxf(m1, mx1);
        float a0 = __expf(m0 - nm0), a1 = __expf(m1 - nm1);
        m0 = nm0;
        m1 = nm1;

        float rs0 = 0.f, rs1 = 0.f;
#pragma unroll
        for (int nt = 0; nt < 8; nt++) {
            sacc[nt][0] = __expf(sacc[nt][0] - m0);
            sacc[nt][1] = __expf(sacc[nt][1] - m0);
            sacc[nt][2] = __expf(sacc[nt][2] - m1);
            sacc[nt][3] = __expf(sacc[nt][3] - m1);
            rs0 += sacc[nt][0] + sacc[nt][1];
            rs1 += sacc[nt][2] + sacc[nt][3];
        }
        rs0 += __shfl_xor_sync(0xffffffffu, rs0, 1);
        rs0 += __shfl_xor_sync(0xffffffffu, rs0, 2);
        rs1 += __shfl_xor_sync(0xffffffffu, rs1, 1);
        rs1 += __shfl_xor_sync(0xffffffffu, rs1, 2);
        l0 = l0 * a0 + rs0;
        l1 = l1 * a1 + rs1;
#pragma unroll
        for (int nt = 0; nt < 8; nt++) {
            oacc[nt][0] *= a0;
            oacc[nt][1] *= a0;
            oacc[nt][2] *= a1;
            oacc[nt][3] *= a1;
        }

        // ---- write P as half2 (own warp rows only) ----
        {
            uint8_t* pr0 = asm_ + OFFP_B + (w * 16 + g) * ARS_B;
            uint8_t* pr1 = pr0 + 8 * ARS_B;
#pragma unroll
            for (int nt = 0; nt < 8; nt++) {
                int off = (nt * 8 + 2 * t4) * 2;
                *reinterpret_cast<uint32_t*>(pr0 + off) = pack_h2(sacc[nt][0], sacc[nt][1]);
                *reinterpret_cast<uint32_t*>(pr1 + off) = pack_h2(sacc[nt][2], sacc[nt][3]);
            }
        }
        __syncwarp();

        // ---- O += P @ V : P ldmatrix (half), V via trans-ldmatrix ----
#pragma unroll
        for (int ks = 0; ks < 4; ks++) {
            uint32_t pf[4];
            ldm_x4(pf, p_lane + ks * 32);
#pragma unroll
            for (int nt = 0; nt < 8; nt++) {
                uint32_t vf[2];
                ldm_x2t(vf, vb_lane + ks * (16 * ARS_B) + nt * 16);
                mma_f16(oacc[nt], pf, vf);
            }
        }
        __syncthreads();   // all warps done with Ks/Vs before next load
    }

    // ---- normalize and store ----
    const float inv0 = 1.f / l0;
    const float inv1 = 1.f / l1;
    const int r0 = qbase + w * 16 + g;
#pragma unroll
    for (int nt = 0; nt < 8; nt++) {
        const int ccol = col0 + nt * 8 + 2 * t4;
        *reinterpret_cast<float2*>(Og + (size_t)r0 * PD + ccol) =
            make_float2(oacc[nt][0] * inv0, oacc[nt][1] * inv0);
        *reinterpret_cast<float2*>(Og + (size_t)(r0 + 8) * PD + ccol) =
            make_float2(oacc[nt][2] * inv1, oacc[nt][3] * inv1);
    }
}

// ---------------------------------------------------------------------------
// Launch: 5 kernels, default stream, graph-capturable.
// Inputs: query, value, Wq, bq, Wkv, bkv, Wo, bo
// ---------------------------------------------------------------------------
extern "C" void kernel_launch(void* const* d_in, const int* in_sizes, int n_in,
                              void* d_out, int out_size)
{
    const float* query = (const float*)d_in[0];
    const float* value = (const float*)d_in[1];
    const float* Wq    = (const float*)d_in[2];
    const float* bq    = (const float*)d_in[3];
    const float* Wkv   = (const float*)d_in[4];
    const float* bkv   = (const float*)d_in[5];
    const float* Wo    = (const float*)d_in[6];
    const float* bo    = (const float*)d_in[7];
    float* out = (float*)d_out;

    float *Qb, *Kb, *Vb, *Hb;
    cudaGetSymbolAddress((void**)&Qb, g_Q);
    cudaGetSymbolAddress((void**)&Kb, g_K);
    cudaGetSymbolAddress((void**)&Vb, g_V);
    cudaGetSymbolAddress((void**)&Hb, g_Hd);

    cudaFuncSetAttribute(gemm_mma_kernel,
                         cudaFuncAttributeMaxDynamicSharedMemorySize,
                         GEMM_SMEM_BYTES);
    cudaFuncSetAttribute(attn_mma_kernel,
                         cudaFuncAttributeMaxDynamicSharedMemorySize,
                         ATT_SMEM_BYTES);

    dim3 gemm_grid(PD / 128, PM / 128);   // (8, 64)
    dim3 attn_grid(PS / 128, PH, PB);     // (8, 16, 8)

    gemm_mma_kernel<<<gemm_grid, 256, GEMM_SMEM_BYTES>>>(
        query, PD, Wq, PD, bq, Qb, PD, PD);
    gemm_mma_kernel<<<gemm_grid, 256, GEMM_SMEM_BYTES>>>(
        value, PD, Wkv, 2 * PD, bkv, Kb, PD, PD);
    gemm_mma_kernel<<<gemm_grid, 256, GEMM_SMEM_BYTES>>>(
        value, PD, Wkv + PD, 2 * PD, bkv + PD, Vb, PD, PD);
    attn_mma_kernel<<<attn_grid, 256, ATT_SMEM_BYTES>>>(Qb, Kb, Vb, Hb);
    gemm_mma_kernel<<<gemm_grid, 256, GEMM_SMEM_BYTES>>>(
        Hb, PD, Wo, PD, bo, out, PD, PD);
}

// round 16
// speedup vs baseline: 10.6174x; 1.0941x over previous
#include <cuda_runtime.h>
#include <cuda_fp16.h>
#include <cstdint>

// Problem constants
#define PB 8
#define PS 1024
#define PD 1024
#define PH 16
#define PHD 64
#define PM (PB * PS)   // 8192 rows

// Scratch (device globals, fp16: no allocation allowed)
__device__ __half g_Qh[PM * PD];
__device__ __half g_Kh[PM * PD];
__device__ __half g_Vh[PM * PD];
__device__ __half g_Hh[PM * PD];

// ---------------------------------------------------------------------------
// Helpers (compute_103-safe PTX only: mma.sync, ldmatrix)
// ---------------------------------------------------------------------------
__device__ __forceinline__ uint32_t smem_u32(const void* p) {
    uint32_t a;
    asm("{ .reg .u64 t; cvta.to.shared.u64 t, %1; cvt.u32.u64 %0, t; }"
        : "=r"(a) : "l"(p));
    return a;
}

__device__ __forceinline__ void ldm_x4(uint32_t* r, uint32_t addr) {
    asm volatile("ldmatrix.sync.aligned.m8n8.x4.shared.b16 {%0,%1,%2,%3}, [%4];"
                 : "=r"(r[0]), "=r"(r[1]), "=r"(r[2]), "=r"(r[3]) : "r"(addr));
}
__device__ __forceinline__ void ldm_x2(uint32_t* r, uint32_t addr) {
    asm volatile("ldmatrix.sync.aligned.m8n8.x2.shared.b16 {%0,%1}, [%2];"
                 : "=r"(r[0]), "=r"(r[1]) : "r"(addr));
}
__device__ __forceinline__ void ldm_x2t(uint32_t* r, uint32_t addr) {
    asm volatile("ldmatrix.sync.aligned.m8n8.x2.trans.shared.b16 {%0,%1}, [%2];"
                 : "=r"(r[0]), "=r"(r[1]) : "r"(addr));
}

// fp16 mma: m16n8k16, row.col, f32 accumulate
__device__ __forceinline__ void mma_f16(float* d, const uint32_t* a,
                                        const uint32_t* b) {
    asm volatile(
        "mma.sync.aligned.m16n8k16.row.col.f32.f16.f16.f32 "
        "{%0,%1,%2,%3}, {%4,%5,%6,%7}, {%8,%9}, {%0,%1,%2,%3};"
        : "+f"(d[0]), "+f"(d[1]), "+f"(d[2]), "+f"(d[3])
        : "r"(a[0]), "r"(a[1]), "r"(a[2]), "r"(a[3]), "r"(b[0]), "r"(b[1]));
}

__device__ __forceinline__ uint32_t pack_h2(float a, float b) {
    __half2 h = __floats2half2_rn(a, b);   // .x = a (low half)
    return *reinterpret_cast<uint32_t*>(&h);
}

// ---------------------------------------------------------------------------
// Shared fp16 GEMM body: C[128x128 tile] = A[.,1024] @ W[1024,.] + bias
// (optionally * cscale before the C rounding). BK=32, 8 warps (2M x 4N).
// A tile half [128 m][32 k] stride 80 B; B tile half [32 k][128 n] natural,
// stride 272 B, fragments via ldmatrix.x2.trans. Double-buffered.
// A_HALF: A is __half (pure copy into smem). C_HALF: C stored as __half.
// ---------------------------------------------------------------------------
#define GAS_B 80                         // A row stride bytes
#define GBS_B 272                        // B row stride bytes
#define GA_BYTES (128 * GAS_B)           // 10240
#define GB_BYTES (32 * GBS_B)            // 8704
#define GSTG_B (GA_BYTES + GB_BYTES)     // 18944
#define GEMM_SMEM_BYTES (2 * GSTG_B)     // 37888
#define GNITER 32                        // K = 1024 fixed

template<bool A_HALF, bool C_HALF>
__device__ __forceinline__ void gemm_body(
    const void* __restrict__ Ap, int lda,
    const float* __restrict__ W, int ldw,
    const float* __restrict__ bias,
    void* __restrict__ Cp, int ldc, float cscale,
    uint8_t* gsm, int m0, int n0)
{
    const uint32_t sb = smem_u32(gsm);
    const int tid = threadIdx.x;
    const int lane = tid & 31;
    const int wid = tid >> 5;
    const int wm = wid & 1;
    const int wn = wid >> 1;

    const int l15 = lane & 15;
    const uint32_t a_lane = (uint32_t)((wm * 64 + l15) * GAS_B + (lane >> 4) * 16);
    const uint32_t b_lane = (uint32_t)(l15 * GBS_B + wn * 64);

    float acc[4][4][4];
#pragma unroll
    for (int mt = 0; mt < 4; mt++)
#pragma unroll
        for (int nt = 0; nt < 4; nt++)
#pragma unroll
            for (int r = 0; r < 4; r++) acc[mt][nt][r] = 0.f;

    // ---- prologue: tile 0 -> stage 0 ----
    {
#pragma unroll
        for (int t = 0; t < 4; t++) {
            int c = tid + 256 * t;
            int row = c >> 3;
            int kc = c & 7;                 // 4-k chunk
            if (A_HALF) {
                const __half* A = (const __half*)Ap;
                uint2 h = *reinterpret_cast<const uint2*>(
                    A + (size_t)(m0 + row) * lda + kc * 4);
                *reinterpret_cast<uint2*>(gsm + row * GAS_B + kc * 8) = h;
            } else {
                const float* A = (const float*)Ap;
                float4 v = *reinterpret_cast<const float4*>(
                    A + (size_t)(m0 + row) * lda + kc * 4);
                *reinterpret_cast<uint2*>(gsm + row * GAS_B + kc * 8) =
                    make_uint2(pack_h2(v.x, v.y), pack_h2(v.z, v.w));
            }
        }
#pragma unroll
        for (int t = 0; t < 4; t++) {
            int c = tid + 256 * t;
            int row = c >> 5;
            int nc = c & 31;
            float4 v = *reinterpret_cast<const float4*>(
                W + (size_t)row * ldw + n0 + nc * 4);
            *reinterpret_cast<uint2*>(gsm + GA_BYTES + row * GBS_B + nc * 8) =
                make_uint2(pack_h2(v.x, v.y), pack_h2(v.z, v.w));
        }
    }

    for (int i = 0; i < GNITER; i++) {
        const int s = i & 1;
        __syncthreads();   // stage s fully written

        float4 aregf[4];
        uint2  aregh[4];
        float4 breg[4];
        const bool more = (i + 1 < GNITER);
        if (more) {
            const int k0 = (i + 1) << 5;
#pragma unroll
            for (int t = 0; t < 4; t++) {
                int c = tid + 256 * t;
                int row = c >> 3;
                int kc = c & 7;
                if (A_HALF) {
                    const __half* A = (const __half*)Ap;
                    aregh[t] = *reinterpret_cast<const uint2*>(
                        A + (size_t)(m0 + row) * lda + k0 + kc * 4);
                } else {
                    const float* A = (const float*)Ap;
                    aregf[t] = *reinterpret_cast<const float4*>(
                        A + (size_t)(m0 + row) * lda + k0 + kc * 4);
                }
            }
#pragma unroll
            for (int t = 0; t < 4; t++) {
                int c = tid + 256 * t;
                int row = c >> 5;
                int nc = c & 31;
                breg[t] = *reinterpret_cast<const float4*>(
                    W + (size_t)(k0 + row) * ldw + n0 + nc * 4);
            }
        }

        // ---- compute stage s ----
        const uint32_t sbase = sb + (uint32_t)(s * GSTG_B);
        const uint32_t abase = sbase + a_lane;
        const uint32_t bbase = sbase + (uint32_t)GA_BYTES + b_lane;
#pragma unroll
        for (int ks = 0; ks < 2; ks++) {
            uint32_t af[4][4], bf[4][2];
#pragma unroll
            for (int mt = 0; mt < 4; mt++)
                ldm_x4(af[mt], abase + mt * (16 * GAS_B) + ks * 32);
#pragma unroll
            for (int nt = 0; nt < 4; nt++)
                ldm_x2t(bf[nt], bbase + ks * (16 * GBS_B) + nt * 16);
#pragma unroll
            for (int mt = 0; mt < 4; mt++)
#pragma unroll
                for (int nt = 0; nt < 4; nt++)
                    mma_f16(acc[mt][nt], af[mt], bf[nt]);
        }

        // ---- store prefetched tile into stage s^1 ----
        if (more) {
            uint8_t* dst = gsm + (s ^ 1) * GSTG_B;
#pragma unroll
            for (int t = 0; t < 4; t++) {
                int c = tid + 256 * t;
                int row = c >> 3;
                int kc = c & 7;
                if (A_HALF) {
                    *reinterpret_cast<uint2*>(dst + row * GAS_B + kc * 8) = aregh[t];
                } else {
                    *reinterpret_cast<uint2*>(dst + row * GAS_B + kc * 8) =
                        make_uint2(pack_h2(aregf[t].x, aregf[t].y),
                                   pack_h2(aregf[t].z, aregf[t].w));
                }
            }
#pragma unroll
            for (int t = 0; t < 4; t++) {
                int c = tid + 256 * t;
                int row = c >> 5;
                int nc = c & 31;
                *reinterpret_cast<uint2*>(dst + GA_BYTES + row * GBS_B + nc * 8) =
                    make_uint2(pack_h2(breg[t].x, breg[t].y),
                               pack_h2(breg[t].z, breg[t].w));
            }
        }
    }

    // ---- epilogue ----
    const int g = lane >> 2;
    const int tig = lane & 3;
    const int row0 = m0 + wm * 64;
    const int col0 = n0 + wn * 32;
#pragma unroll
    for (int nt = 0; nt < 4; nt++) {
        const int ccol = col0 + nt * 8 + 2 * tig;
        const float b0 = bias[ccol];
        const float b1 = bias[ccol + 1];
#pragma unroll
        for (int mt = 0; mt < 4; mt++) {
            const int r = row0 + mt * 16 + g;
            float v0 = (acc[mt][nt][0] + b0) * cscale;
            float v1 = (acc[mt][nt][1] + b1) * cscale;
            float v2 = (acc[mt][nt][2] + b0) * cscale;
            float v3 = (acc[mt][nt][3] + b1) * cscale;
            if (C_HALF) {
                __half* C = (__half*)Cp;
                *reinterpret_cast<uint32_t*>(C + (size_t)r * ldc + ccol) =
                    pack_h2(v0, v1);
                *reinterpret_cast<uint32_t*>(C + (size_t)(r + 8) * ldc + ccol) =
                    pack_h2(v2, v3);
            } else {
                float* C = (float*)Cp;
                *reinterpret_cast<float2*>(C + (size_t)r * ldc + ccol) =
                    make_float2(v0, v1);
                *reinterpret_cast<float2*>(C + (size_t)(r + 8) * ldc + ccol) =
                    make_float2(v2, v3);
            }
        }
    }
}

// Merged projection GEMM: grid (24, 64). Segment 0: Q (scale 0.125 folded),
// 1: K, 2: V. All write fp16 scratch.
__global__ __launch_bounds__(256, 2) void proj_gemm_kernel(
    const float* __restrict__ query, const float* __restrict__ value,
    const float* __restrict__ Wq, const float* __restrict__ bq,
    const float* __restrict__ Wkv, const float* __restrict__ bkv,
    __half* Qh, __half* Kh, __half* Vh)
{
    extern __shared__ uint8_t gsm[];
    const int seg = blockIdx.x >> 3;
    const int nx = blockIdx.x & 7;
    const float* A;
    const float* W;
    const float* bias;
    __half* C;
    int ldw;
    float cs;
    if (seg == 0)      { A = query; W = Wq;        bias = bq;        C = Qh; ldw = PD;     cs = 0.125f; }
    else if (seg == 1) { A = value; W = Wkv;       bias = bkv;       C = Kh; ldw = 2 * PD; cs = 1.f; }
    else               { A = value; W = Wkv + PD;  bias = bkv + PD;  C = Vh; ldw = 2 * PD; cs = 1.f; }
    gemm_body<false, true>(A, PD, W, ldw, bias, C, PD, cs,
                           gsm, blockIdx.y * 128, nx * 128);
}

// Output GEMM: A = heads (fp16), C = fp32 out.
__global__ __launch_bounds__(256, 2) void out_gemm_kernel(
    const __half* __restrict__ Hd, const float* __restrict__ Wo,
    const float* __restrict__ bo, float* __restrict__ out)
{
    extern __shared__ uint8_t gsm[];
    gemm_body<true, false>(Hd, PD, Wo, PD, bo, out, PD, 1.f,
                           gsm, blockIdx.y * 128, blockIdx.x * 128);
}

// ---------------------------------------------------------------------------
// Tensor-core flash attention — fp16 in / fp16 out (round 16).
// 256 threads / 8 warps, q-tile 128 rows. All gmem tiles are fp16 already:
// loaders are pure uint4 copies (no cvt). Q carries the 0.125 scale (folded
// at the Q GEMM). K non-trans x2; V x2.trans; P stored half2.
// Smem: Qs(128x144B) + Pp(128x144B) + Ks(64x144B) + Vs(64x144B) = 55296 B.
// ---------------------------------------------------------------------------
#define ARS_B 144                        // row stride bytes (72 halves)
#define AQ_BYTES (128 * ARS_B)           // 18432
#define AK_BYTES (64 * ARS_B)            // 9216
#define OFFP_B AQ_BYTES
#define OFFK_B (2 * AQ_BYTES)
#define OFFV_B (2 * AQ_BYTES + AK_BYTES)
#define ATT_SMEM_BYTES (2 * AQ_BYTES + 2 * AK_BYTES)   // 55296

__global__ __launch_bounds__(256, 2) void attn_mma_kernel(
    const __half* __restrict__ Qg, const __half* __restrict__ Kg,
    const __half* __restrict__ Vg, __half* __restrict__ Og)
{
    extern __shared__ uint8_t asm_[];
    const uint32_t sb = smem_u32(asm_);

    const int tid = threadIdx.x;
    const int lane = tid & 31;
    const int w = tid >> 5;                // warp 0..7 -> q rows [16w,16w+16)
    const int l15 = lane & 15;
    const int g = lane >> 2;
    const int t4 = lane & 3;

    const int qt = blockIdx.x;             // 0..7
    const int h  = blockIdx.y;
    const int b  = blockIdx.z;
    const int qbase = b * PS + qt * 128;
    const int col0  = h * PHD;

    // ---- copy Q tile [128 q][64 d] (half), RESIDENT ----
#pragma unroll
    for (int t = 0; t < 4; t++) {
        int idx = tid + 256 * t;           // 0..1023 uint4s
        int row = idx >> 3;                // 0..127
        int c8  = idx & 7;                 // 8-half chunk
        *reinterpret_cast<uint4*>(asm_ + row * ARS_B + c8 * 16) =
            *reinterpret_cast<const uint4*>(
                Qg + (size_t)(qbase + row) * PD + col0 + c8 * 8);
    }

    float m0 = -1e30f, m1 = -1e30f, l0 = 0.f, l1 = 0.f;
    float oacc[8][4];
#pragma unroll
    for (int nt = 0; nt < 8; nt++)
#pragma unroll
        for (int r = 0; r < 4; r++) oacc[nt][r] = 0.f;

    const uint32_t a_lane_off = (uint32_t)((w * 16 + l15) * ARS_B + (lane >> 4) * 16);
    const uint32_t q_lane = sb + a_lane_off;
    const uint32_t p_lane = sb + (uint32_t)OFFP_B + a_lane_off;
    const uint32_t kb_lane = sb + (uint32_t)OFFK_B +
                             (uint32_t)((l15 & 7) * ARS_B + ((l15 >> 3) & 1) * 16);
    const uint32_t vb_lane = sb + (uint32_t)OFFV_B + (uint32_t)(l15 * ARS_B);

    __syncthreads();   // Q resident before first kt

    for (int kt = 0; kt < 16; kt++) {
        const int kbase = b * PS + kt * 64;
        // ---- copy K and V tiles (half, no cvt) ----
#pragma unroll
        for (int t = 0; t < 2; t++) {
            int idx = tid + 256 * t;       // 0..511 uint4s
            int row = idx >> 3;            // 0..63
            int c8  = idx & 7;
            *reinterpret_cast<uint4*>(asm_ + OFFK_B + row * ARS_B + c8 * 16) =
                *reinterpret_cast<const uint4*>(
                    Kg + (size_t)(kbase + row) * PD + col0 + c8 * 8);
        }
#pragma unroll
        for (int t = 0; t < 2; t++) {
            int idx = tid + 256 * t;
            int row = idx >> 3;
            int c8  = idx & 7;
            *reinterpret_cast<uint4*>(asm_ + OFFV_B + row * ARS_B + c8 * 16) =
                *reinterpret_cast<const uint4*>(
                    Vg + (size_t)(kbase + row) * PD + col0 + c8 * 8);
        }
        __syncthreads();

        // ---- S = (Q*scale) @ K^T ----
        float sacc[8][4];
#pragma unroll
        for (int nt = 0; nt < 8; nt++)
#pragma unroll
            for (int r = 0; r < 4; r++) sacc[nt][r] = 0.f;

#pragma unroll
        for (int ks = 0; ks < 4; ks++) {
            uint32_t qf[4];
            ldm_x4(qf, q_lane + ks * 32);
#pragma unroll
            for (int nt = 0; nt < 8; nt++) {
                uint32_t bf[2];
                ldm_x2(bf, kb_lane + nt * (8 * ARS_B) + ks * 32);
                mma_f16(sacc[nt], qf, bf);
            }
        }

        // ---- online softmax ----
        float mx0 = -1e30f, mx1 = -1e30f;
#pragma unroll
        for (int nt = 0; nt < 8; nt++) {
            mx0 = fmaxf(mx0, fmaxf(sacc[nt][0], sacc[nt][1]));
            mx1 = fmaxf(mx1, fmaxf(sacc[nt][2], sacc[nt][3]));
        }
        mx0 = fmaxf(mx0, __shfl_xor_sync(0xffffffffu, mx0, 1));
        mx0 = fmaxf(mx0, __shfl_xor_sync(0xffffffffu, mx0, 2));
        mx1 = fmaxf(mx1, __shfl_xor_sync(0xffffffffu, mx1, 1));
        mx1 = fmaxf(mx1, __shfl_xor_sync(0xffffffffu, mx1, 2));

        float nm0 = fmaxf(m0, mx0), nm1 = fmaxf(m1, mx1);
        float a0 = __expf(m0 - nm0), a1 = __expf(m1 - nm1);
        m0 = nm0;
        m1 = nm1;

        float rs0 = 0.f, rs1 = 0.f;
#pragma unroll
        for (int nt = 0; nt < 8; nt++) {
            sacc[nt][0] = __expf(sacc[nt][0] - m0);
            sacc[nt][1] = __expf(sacc[nt][1] - m0);
            sacc[nt][2] = __expf(sacc[nt][2] - m1);
            sacc[nt][3] = __expf(sacc[nt][3] - m1);
            rs0 += sacc[nt][0] + sacc[nt][1];
            rs1 += sacc[nt][2] + sacc[nt][3];
        }
        rs0 += __shfl_xor_sync(0xffffffffu, rs0, 1);
        rs0 += __shfl_xor_sync(0xffffffffu, rs0, 2);
        rs1 += __shfl_xor_sync(0xffffffffu, rs1, 1);
        rs1 += __shfl_xor_sync(0xffffffffu, rs1, 2);
        l0 = l0 * a0 + rs0;
        l1 = l1 * a1 + rs1;
#pragma unroll
        for (int nt = 0; nt < 8; nt++) {
            oacc[nt][0] *= a0;
            oacc[nt][1] *= a0;
            oacc[nt][2] *= a1;
            oacc[nt][3] *= a1;
        }

        // ---- write P as half2 (own warp rows only) ----
        {
            uint8_t* pr0 = asm_ + OFFP_B + (w * 16 + g) * ARS_B;
            uint8_t* pr1 = pr0 + 8 * ARS_B;
#pragma unroll
            for (int nt = 0; nt < 8; nt++) {
                int off = (nt * 8 + 2 * t4) * 2;
                *reinterpret_cast<uint32_t*>(pr0 + off) = pack_h2(sacc[nt][0], sacc[nt][1]);
                *reinterpret_cast<uint32_t*>(pr1 + off) = pack_h2(sacc[nt][2], sacc[nt][3]);
            }
        }
        __syncwarp();

        // ---- O += P @ V ----
#pragma unroll
        for (int ks = 0; ks < 4; ks++) {
            uint32_t pf[4];
            ldm_x4(pf, p_lane + ks * 32);
#pragma unroll
            for (int nt = 0; nt < 8; nt++) {
                uint32_t vf[2];
                ldm_x2t(vf, vb_lane + ks * (16 * ARS_B) + nt * 16);
                mma_f16(oacc[nt], pf, vf);
            }
        }
        __syncthreads();   // all warps done with Ks/Vs before next load
    }

    // ---- normalize and store as half ----
    const float inv0 = 1.f / l0;
    const float inv1 = 1.f / l1;
    const int r0 = qbase + w * 16 + g;
#pragma unroll
    for (int nt = 0; nt < 8; nt++) {
        const int ccol = col0 + nt * 8 + 2 * t4;
        *reinterpret_cast<uint32_t*>(Og + (size_t)r0 * PD + ccol) =
            pack_h2(oacc[nt][0] * inv0, oacc[nt][1] * inv0);
        *reinterpret_cast<uint32_t*>(Og + (size_t)(r0 + 8) * PD + ccol) =
            pack_h2(oacc[nt][2] * inv1, oacc[nt][3] * inv1);
    }
}

// ---------------------------------------------------------------------------
// Launch: 3 kernels, default stream, graph-capturable.
// Inputs: query, value, Wq, bq, Wkv, bkv, Wo, bo
// ---------------------------------------------------------------------------
extern "C" void kernel_launch(void* const* d_in, const int* in_sizes, int n_in,
                              void* d_out, int out_size)
{
    const float* query = (const float*)d_in[0];
    const float* value = (const float*)d_in[1];
    const float* Wq    = (const float*)d_in[2];
    const float* bq    = (const float*)d_in[3];
    const float* Wkv   = (const float*)d_in[4];
    const float* bkv   = (const float*)d_in[5];
    const float* Wo    = (const float*)d_in[6];
    const float* bo    = (const float*)d_in[7];
    float* out = (float*)d_out;

    __half *Qh, *Kh, *Vh, *Hh;
    cudaGetSymbolAddress((void**)&Qh, g_Qh);
    cudaGetSymbolAddress((void**)&Kh, g_Kh);
    cudaGetSymbolAddress((void**)&Vh, g_Vh);
    cudaGetSymbolAddress((void**)&Hh, g_Hh);

    cudaFuncSetAttribute(proj_gemm_kernel,
                         cudaFuncAttributeMaxDynamicSharedMemorySize,
                         GEMM_SMEM_BYTES);
    cudaFuncSetAttribute(out_gemm_kernel,
                         cudaFuncAttributeMaxDynamicSharedMemorySize,
                         GEMM_SMEM_BYTES);
    cudaFuncSetAttribute(attn_mma_kernel,
                         cudaFuncAttributeMaxDynamicSharedMemorySize,
                         ATT_SMEM_BYTES);

    dim3 proj_grid(24, PM / 128);         // (24, 64): Q|K|V segments
    dim3 attn_grid(PS / 128, PH, PB);     // (8, 16, 8)
    dim3 out_grid(PD / 128, PM / 128);    // (8, 64)

    proj_gemm_kernel<<<proj_grid, 256, GEMM_SMEM_BYTES>>>(
        query, value, Wq, bq, Wkv, bkv, Qh, Kh, Vh);
    attn_mma_kernel<<<attn_grid, 256, ATT_SMEM_BYTES>>>(Qh, Kh, Vh, Hh);
    out_gemm_kernel<<<out_grid, 256, GEMM_SMEM_BYTES>>>(Hh, Wo, bo, out);
}

// round 17
// speedup vs baseline: 13.4258x; 1.2645x over previous
#include <cuda_runtime.h>
#include <cuda_fp16.h>
#include <cstdint>

// Problem constants
#define PB 8
#define PS 1024
#define PD 1024
#define PH 16
#define PHD 64
#define PM (PB * PS)   // 8192 rows

// Scratch (device globals, fp16: no allocation allowed)
__device__ __half g_qin[PM * PD];       // query as half
__device__ __half g_vin[PM * PD];       // value as half
__device__ __half g_Wqh[PD * PD];
__device__ __half g_Wkvh[PD * 2 * PD];
__device__ __half g_Woh[PD * PD];
__device__ __half g_Qh[PM * PD];
__device__ __half g_Kh[PM * PD];
__device__ __half g_Vh[PM * PD];
__device__ __half g_Hh[PM * PD];

// ---------------------------------------------------------------------------
// Helpers (compute_103-safe PTX only: mma.sync, ldmatrix, cp.async)
// ---------------------------------------------------------------------------
__device__ __forceinline__ uint32_t smem_u32(const void* p) {
    uint32_t a;
    asm("{ .reg .u64 t; cvta.to.shared.u64 t, %1; cvt.u32.u64 %0, t; }"
        : "=r"(a) : "l"(p));
    return a;
}

__device__ __forceinline__ void cp_async16(uint32_t saddr, const void* gaddr) {
    asm volatile("cp.async.cg.shared.global [%0], [%1], 16;"
                 :: "r"(saddr), "l"(gaddr));
}
#define CP_COMMIT() asm volatile("cp.async.commit_group;" ::: "memory")
#define CP_WAIT0()  asm volatile("cp.async.wait_group 0;" ::: "memory")
#define CP_WAIT1()  asm volatile("cp.async.wait_group 1;" ::: "memory")

__device__ __forceinline__ void ldm_x4(uint32_t* r, uint32_t addr) {
    asm volatile("ldmatrix.sync.aligned.m8n8.x4.shared.b16 {%0,%1,%2,%3}, [%4];"
                 : "=r"(r[0]), "=r"(r[1]), "=r"(r[2]), "=r"(r[3]) : "r"(addr));
}
__device__ __forceinline__ void ldm_x2(uint32_t* r, uint32_t addr) {
    asm volatile("ldmatrix.sync.aligned.m8n8.x2.shared.b16 {%0,%1}, [%2];"
                 : "=r"(r[0]), "=r"(r[1]) : "r"(addr));
}
__device__ __forceinline__ void ldm_x2t(uint32_t* r, uint32_t addr) {
    asm volatile("ldmatrix.sync.aligned.m8n8.x2.trans.shared.b16 {%0,%1}, [%2];"
                 : "=r"(r[0]), "=r"(r[1]) : "r"(addr));
}

// fp16 mma: m16n8k16, row.col, f32 accumulate
__device__ __forceinline__ void mma_f16(float* d, const uint32_t* a,
                                        const uint32_t* b) {
    asm volatile(
        "mma.sync.aligned.m16n8k16.row.col.f32.f16.f16.f32 "
        "{%0,%1,%2,%3}, {%4,%5,%6,%7}, {%8,%9}, {%0,%1,%2,%3};"
        : "+f"(d[0]), "+f"(d[1]), "+f"(d[2]), "+f"(d[3])
        : "r"(a[0]), "r"(a[1]), "r"(a[2]), "r"(a[3]), "r"(b[0]), "r"(b[1]));
}

__device__ __forceinline__ uint32_t pack_h2(float a, float b) {
    __half2 h = __floats2half2_rn(a, b);
    return *reinterpret_cast<uint32_t*>(&h);
}

// ---------------------------------------------------------------------------
// 5-way fp32 -> fp16 convert (round-to-nearest; identical rounding to the
// loader-side cvt it replaces). grid (1024, 5).
// ---------------------------------------------------------------------------
__global__ __launch_bounds__(256) void cvt5_kernel(
    const float* __restrict__ q, const float* __restrict__ v,
    const float* __restrict__ wq, const float* __restrict__ wkv,
    const float* __restrict__ wo,
    __half* qh, __half* vh, __half* wqh, __half* wkvh, __half* woh)
{
    const float* src;
    __half* dst;
    int n4;
    switch (blockIdx.y) {
        case 0: src = q;   dst = qh;   n4 = PM * PD / 4;     break;
        case 1: src = v;   dst = vh;   n4 = PM * PD / 4;     break;
        case 2: src = wq;  dst = wqh;  n4 = PD * PD / 4;     break;
        case 3: src = wkv; dst = wkvh; n4 = PD * 2 * PD / 4; break;
        default: src = wo; dst = woh;  n4 = PD * PD / 4;     break;
    }
    int i = blockIdx.x * 256 + threadIdx.x;
    const int stride = gridDim.x * 256;
    for (; i < n4; i += stride) {
        float4 x = reinterpret_cast<const float4*>(src)[i];
        reinterpret_cast<uint2*>(dst)[i] =
            make_uint2(pack_h2(x.x, x.y), pack_h2(x.z, x.w));
    }
}

// ---------------------------------------------------------------------------
// fp16 GEMM, all-half operands, 3-stage cp.async pipeline:
//   C[128x128 tile] = A[.,1024](half) @ W[1024,.](half) + bias, *cscale
// BK=32, 8 warps (2M x 4N). A tile [128 m][32 k] stride 80 B; B tile
// [32 k][128 n] natural stride 272 B (ldmatrix.x2.trans). 1 sync/iter.
// ---------------------------------------------------------------------------
#define GAS_B 80
#define GBS_B 272
#define GA_BYTES (128 * GAS_B)           // 10240
#define GB_BYTES (32 * GBS_B)            // 8704
#define GSTG_B (GA_BYTES + GB_BYTES)     // 18944
#define GEMM_SMEM_BYTES (3 * GSTG_B)     // 56832
#define GNITER 32                        // K = 1024

template<bool C_HALF>
__device__ __forceinline__ void gemm_body(
    const __half* __restrict__ A, int lda,
    const __half* __restrict__ W, int ldw,
    const float* __restrict__ bias,
    void* __restrict__ Cp, int ldc, float cscale,
    uint8_t* gsm, int m0, int n0)
{
    const uint32_t sb = smem_u32(gsm);
    const int tid = threadIdx.x;
    const int lane = tid & 31;
    const int wid = tid >> 5;
    const int wm = wid & 1;
    const int wn = wid >> 1;

    const int l15 = lane & 15;
    const uint32_t a_lane = (uint32_t)((wm * 64 + l15) * GAS_B + (lane >> 4) * 16);
    const uint32_t b_lane = (uint32_t)(l15 * GBS_B + wn * 64);

    float acc[4][4][4];
#pragma unroll
    for (int mt = 0; mt < 4; mt++)
#pragma unroll
        for (int nt = 0; nt < 4; nt++)
#pragma unroll
            for (int r = 0; r < 4; r++) acc[mt][nt][r] = 0.f;

    auto load_stage = [&](int st, int k0) {
        const uint32_t dst = sb + (uint32_t)(st * GSTG_B);
#pragma unroll
        for (int t = 0; t < 2; t++) {
            int idx = tid + 256 * t;       // 0..511
            int row = idx >> 2;            // 0..127
            int kc  = idx & 3;             // 8-half chunk
            cp_async16(dst + row * GAS_B + kc * 16,
                       A + (size_t)(m0 + row) * lda + k0 + kc * 8);
        }
#pragma unroll
        for (int t = 0; t < 2; t++) {
            int idx = tid + 256 * t;
            int row = idx >> 4;            // 0..31
            int nc  = idx & 15;
            cp_async16(dst + GA_BYTES + row * GBS_B + nc * 16,
                       W + (size_t)(k0 + row) * ldw + n0 + nc * 8);
        }
        CP_COMMIT();
    };

    load_stage(0, 0);
    load_stage(1, 32);

    for (int i = 0; i < GNITER; i++) {
        const int s = i % 3;
        if (i == GNITER - 1) CP_WAIT0(); else CP_WAIT1();
        __syncthreads();

        const uint32_t sbase = sb + (uint32_t)(s * GSTG_B);
        const uint32_t abase = sbase + a_lane;
        const uint32_t bbase = sbase + (uint32_t)GA_BYTES + b_lane;
#pragma unroll
        for (int ks = 0; ks < 2; ks++) {
            uint32_t af[4][4], bf[4][2];
#pragma unroll
            for (int mt = 0; mt < 4; mt++)
                ldm_x4(af[mt], abase + mt * (16 * GAS_B) + ks * 32);
#pragma unroll
            for (int nt = 0; nt < 4; nt++)
                ldm_x2t(bf[nt], bbase + ks * (16 * GBS_B) + nt * 16);
#pragma unroll
            for (int mt = 0; mt < 4; mt++)
#pragma unroll
                for (int nt = 0; nt < 4; nt++)
                    mma_f16(acc[mt][nt], af[mt], bf[nt]);
        }

        // Issue stage i+2 (stage (i+2)%3 != i%3; consumed at iter i-1, and
        // the top barrier of this iter guarantees those reads completed).
        if (i + 2 < GNITER) load_stage((i + 2) % 3, (i + 2) * 32);
    }

    // ---- epilogue ----
    const int g = lane >> 2;
    const int tig = lane & 3;
    const int row0 = m0 + wm * 64;
    const int col0 = n0 + wn * 32;
#pragma unroll
    for (int nt = 0; nt < 4; nt++) {
        const int ccol = col0 + nt * 8 + 2 * tig;
        const float b0 = bias[ccol];
        const float b1 = bias[ccol + 1];
#pragma unroll
        for (int mt = 0; mt < 4; mt++) {
            const int r = row0 + mt * 16 + g;
            float v0 = (acc[mt][nt][0] + b0) * cscale;
            float v1 = (acc[mt][nt][1] + b1) * cscale;
            float v2 = (acc[mt][nt][2] + b0) * cscale;
            float v3 = (acc[mt][nt][3] + b1) * cscale;
            if (C_HALF) {
                __half* C = (__half*)Cp;
                *reinterpret_cast<uint32_t*>(C + (size_t)r * ldc + ccol) =
                    pack_h2(v0, v1);
                *reinterpret_cast<uint32_t*>(C + (size_t)(r + 8) * ldc + ccol) =
                    pack_h2(v2, v3);
            } else {
                float* C = (float*)Cp;
                *reinterpret_cast<float2*>(C + (size_t)r * ldc + ccol) =
                    make_float2(v0, v1);
                *reinterpret_cast<float2*>(C + (size_t)(r + 8) * ldc + ccol) =
                    make_float2(v2, v3);
            }
        }
    }
}

// Merged projection GEMM: grid (24, 64). Seg 0: Q (0.125 folded), 1: K, 2: V.
__global__ __launch_bounds__(256, 2) void proj_gemm_kernel(
    const float* __restrict__ bq, const float* __restrict__ bkv,
    __half* Qh, __half* Kh, __half* Vh)
{
    extern __shared__ uint8_t gsm[];
    const int seg = blockIdx.x >> 3;
    const int nx = blockIdx.x & 7;
    const __half* A;
    const __half* W;
    const float* bias;
    __half* C;
    int ldw;
    float cs;
    if (seg == 0)      { A = g_qin; W = g_Wqh;       bias = bq;       C = Qh; ldw = PD;     cs = 0.125f; }
    else if (seg == 1) { A = g_vin; W = g_Wkvh;      bias = bkv;      C = Kh; ldw = 2 * PD; cs = 1.f; }
    else               { A = g_vin; W = g_Wkvh + PD; bias = bkv + PD; C = Vh; ldw = 2 * PD; cs = 1.f; }
    gemm_body<true>(A, PD, W, ldw, bias, C, PD, cs,
                    gsm, blockIdx.y * 128, nx * 128);
}

__global__ __launch_bounds__(256, 2) void out_gemm_kernel(
    const float* __restrict__ bo, float* __restrict__ out)
{
    extern __shared__ uint8_t gsm[];
    gemm_body<false>(g_Hh, PD, g_Woh, PD, bo, out, PD, 1.f,
                     gsm, blockIdx.y * 128, blockIdx.x * 128);
}

// ---------------------------------------------------------------------------
// Tensor-core flash attention — fp16, 3-buffer cp.async K/V ring (round 17).
// 256 threads / 8 warps, q-tile 128 rows. Q resident copy; Q carries the
// 0.125 scale. K non-trans x2; V x2.trans; P stored half2. 1 sync/iter.
// Smem: Qs(18432) + Pp(18432) + 3 x [K(9216)+V(9216)] = 92160 B.
// ---------------------------------------------------------------------------
#define ARS_B 144
#define AQ_BYTES (128 * ARS_B)           // 18432
#define AKV_BYTES (2 * 64 * ARS_B)       // 18432 per ring slot (K + V)
#define OFFP_B AQ_BYTES
#define OFFKV_B (2 * AQ_BYTES)
#define ATT_SMEM_BYTES (2 * AQ_BYTES + 3 * AKV_BYTES)   // 92160

__global__ __launch_bounds__(256, 2) void attn_mma_kernel(
    const __half* __restrict__ Qg, const __half* __restrict__ Kg,
    const __half* __restrict__ Vg, __half* __restrict__ Og)
{
    extern __shared__ uint8_t asm_[];
    const uint32_t sb = smem_u32(asm_);

    const int tid = threadIdx.x;
    const int lane = tid & 31;
    const int w = tid >> 5;
    const int l15 = lane & 15;
    const int g = lane >> 2;
    const int t4 = lane & 3;

    const int qt = blockIdx.x;             // 0..7
    const int h  = blockIdx.y;
    const int b  = blockIdx.z;
    const int qbase = b * PS + qt * 128;
    const int col0  = h * PHD;

    auto load_kv = [&](int slot, int kbase) {
        const uint32_t dst = sb + (uint32_t)(OFFKV_B + slot * AKV_BYTES);
#pragma unroll
        for (int t = 0; t < 2; t++) {
            int idx = tid + 256 * t;       // 0..511
            int row = idx >> 3;            // 0..63
            int c8  = idx & 7;
            cp_async16(dst + row * ARS_B + c8 * 16,
                       Kg + (size_t)(kbase + row) * PD + col0 + c8 * 8);
        }
#pragma unroll
        for (int t = 0; t < 2; t++) {
            int idx = tid + 256 * t;
            int row = idx >> 3;
            int c8  = idx & 7;
            cp_async16(dst + 64 * ARS_B + row * ARS_B + c8 * 16,
                       Vg + (size_t)(kbase + row) * PD + col0 + c8 * 8);
        }
        CP_COMMIT();
    };

    // prologue: K/V tiles 0 and 1 in flight; Q resident copy meanwhile
    load_kv(0, b * PS);
    load_kv(1, b * PS + 64);
#pragma unroll
    for (int t = 0; t < 4; t++) {
        int idx = tid + 256 * t;           // 0..1023 uint4s
        int row = idx >> 3;                // 0..127
        int c8  = idx & 7;
        *reinterpret_cast<uint4*>(asm_ + row * ARS_B + c8 * 16) =
            *reinterpret_cast<const uint4*>(
                Qg + (size_t)(qbase + row) * PD + col0 + c8 * 8);
    }

    float m0 = -1e30f, m1 = -1e30f, l0 = 0.f, l1 = 0.f;
    float oacc[8][4];
#pragma unroll
    for (int nt = 0; nt < 8; nt++)
#pragma unroll
        for (int r = 0; r < 4; r++) oacc[nt][r] = 0.f;

    const uint32_t a_lane_off = (uint32_t)((w * 16 + l15) * ARS_B + (lane >> 4) * 16);
    const uint32_t q_lane = sb + a_lane_off;
    const uint32_t p_lane = sb + (uint32_t)OFFP_B + a_lane_off;
    const uint32_t kb_off = (uint32_t)((l15 & 7) * ARS_B + ((l15 >> 3) & 1) * 16);
    const uint32_t vb_off = (uint32_t)(64 * ARS_B + l15 * ARS_B);

    for (int kt = 0; kt < 16; kt++) {
        if (kt == 15) CP_WAIT0(); else CP_WAIT1();
        __syncthreads();   // tile kt ready; prior-iter reads of slot (kt+2)%3 done

        const uint32_t kvbase = sb + (uint32_t)(OFFKV_B + (kt % 3) * AKV_BYTES);
        const uint32_t kb_lane = kvbase + kb_off;
        const uint32_t vb_lane = kvbase + vb_off;

        // ---- S = (Q*scale) @ K^T ----
        float sacc[8][4];
#pragma unroll
        for (int nt = 0; nt < 8; nt++)
#pragma unroll
            for (int r = 0; r < 4; r++) sacc[nt][r] = 0.f;

#pragma unroll
        for (int ks = 0; ks < 4; ks++) {
            uint32_t qf[4];
            ldm_x4(qf, q_lane + ks * 32);
#pragma unroll
            for (int nt = 0; nt < 8; nt++) {
                uint32_t bf[2];
                ldm_x2(bf, kb_lane + nt * (8 * ARS_B) + ks * 32);
                mma_f16(sacc[nt], qf, bf);
            }
        }

        // issue K/V tile kt+2 into slot (kt+2)%3 (!= kt%3; reads finished)
        if (kt + 2 < 16) load_kv((kt + 2) % 3, b * PS + (kt + 2) * 64);

        // ---- online softmax ----
        float mx0 = -1e30f, mx1 = -1e30f;
#pragma unroll
        for (int nt = 0; nt < 8; nt++) {
            mx0 = fmaxf(mx0, fmaxf(sacc[nt][0], sacc[nt][1]));
            mx1 = fmaxf(mx1, fmaxf(sacc[nt][2], sacc[nt][3]));
        }
        mx0 = fmaxf(mx0, __shfl_xor_sync(0xffffffffu, mx0, 1));
        mx0 = fmaxf(mx0, __shfl_xor_sync(0xffffffffu, mx0, 2));
        mx1 = fmaxf(mx1, __shfl_xor_sync(0xffffffffu, mx1, 1));
        mx1 = fmaxf(mx1, __shfl_xor_sync(0xffffffffu, mx1, 2));

        float nm0 = fmaxf(m0, mx0), nm1 = fmaxf(m1, mx1);
        float a0 = __expf(m0 - nm0), a1 = __expf(m1 - nm1);
        m0 = nm0;
        m1 = nm1;

        float rs0 = 0.f, rs1 = 0.f;
#pragma unroll
        for (int nt = 0; nt < 8; nt++) {
            sacc[nt][0] = __expf(sacc[nt][0] - m0);
            sacc[nt][1] = __expf(sacc[nt][1] - m0);
            sacc[nt][2] = __expf(sacc[nt][2] - m1);
            sacc[nt][3] = __expf(sacc[nt][3] - m1);
            rs0 += sacc[nt][0] + sacc[nt][1];
            rs1 += sacc[nt][2] + sacc[nt][3];
        }
        rs0 += __shfl_xor_sync(0xffffffffu, rs0, 1);
        rs0 += __shfl_xor_sync(0xffffffffu, rs0, 2);
        rs1 += __shfl_xor_sync(0xffffffffu, rs1, 1);
        rs1 += __shfl_xor_sync(0xffffffffu, rs1, 2);
        l0 = l0 * a0 + rs0;
        l1 = l1 * a1 + rs1;
#pragma unroll
        for (int nt = 0; nt < 8; nt++) {
            oacc[nt][0] *= a0;
            oacc[nt][1] *= a0;
            oacc[nt][2] *= a1;
            oacc[nt][3] *= a1;
        }

        // ---- write P as half2 (own warp rows only) ----
        {
            uint8_t* pr0 = asm_ + OFFP_B + (w * 16 + g) * ARS_B;
            uint8_t* pr1 = pr0 + 8 * ARS_B;
#pragma unroll
            for (int nt = 0; nt < 8; nt++) {
                int off = (nt * 8 + 2 * t4) * 2;
                *reinterpret_cast<uint32_t*>(pr0 + off) = pack_h2(sacc[nt][0], sacc[nt][1]);
                *reinterpret_cast<uint32_t*>(pr1 + off) = pack_h2(sacc[nt][2], sacc[nt][3]);
            }
        }
        __syncwarp();

        // ---- O += P @ V ----
#pragma unroll
        for (int ks = 0; ks < 4; ks++) {
            uint32_t pf[4];
            ldm_x4(pf, p_lane + ks * 32);
#pragma unroll
            for (int nt = 0; nt < 8; nt++) {
                uint32_t vf[2];
                ldm_x2t(vf, vb_lane + ks * (16 * ARS_B) + nt * 16);
                mma_f16(oacc[nt], pf, vf);
            }
        }
    }

    // ---- normalize and store as half ----
    const float inv0 = 1.f / l0;
    const float inv1 = 1.f / l1;
    const int r0 = qbase + w * 16 + g;
#pragma unroll
    for (int nt = 0; nt < 8; nt++) {
        const int ccol = col0 + nt * 8 + 2 * t4;
        *reinterpret_cast<uint32_t*>(Og + (size_t)r0 * PD + ccol) =
            pack_h2(oacc[nt][0] * inv0, oacc[nt][1] * inv0);
        *reinterpret_cast<uint32_t*>(Og + (size_t)(r0 + 8) * PD + ccol) =
            pack_h2(oacc[nt][2] * inv1, oacc[nt][3] * inv1);
    }
}

// ---------------------------------------------------------------------------
// Launch: 4 kernels, default stream, graph-capturable.
// Inputs: query, value, Wq, bq, Wkv, bkv, Wo, bo
// ---------------------------------------------------------------------------
extern "C" void kernel_launch(void* const* d_in, const int* in_sizes, int n_in,
                              void* d_out, int out_size)
{
    const float* query = (const float*)d_in[0];
    const float* value = (const float*)d_in[1];
    const float* Wq    = (const float*)d_in[2];
    const float* bq    = (const float*)d_in[3];
    const float* Wkv   = (const float*)d_in[4];
    const float* bkv   = (const float*)d_in[5];
    const float* Wo    = (const float*)d_in[6];
    const float* bo    = (const float*)d_in[7];
    float* out = (float*)d_out;

    __half *qin, *vin, *Wqh, *Wkvh, *Woh, *Qh, *Kh, *Vh, *Hh;
    cudaGetSymbolAddress((void**)&qin, g_qin);
    cudaGetSymbolAddress((void**)&vin, g_vin);
    cudaGetSymbolAddress((void**)&Wqh, g_Wqh);
    cudaGetSymbolAddress((void**)&Wkvh, g_Wkvh);
    cudaGetSymbolAddress((void**)&Woh, g_Woh);
    cudaGetSymbolAddress((void**)&Qh, g_Qh);
    cudaGetSymbolAddress((void**)&Kh, g_Kh);
    cudaGetSymbolAddress((void**)&Vh, g_Vh);
    cudaGetSymbolAddress((void**)&Hh, g_Hh);

    cudaFuncSetAttribute(proj_gemm_kernel,
                         cudaFuncAttributeMaxDynamicSharedMemorySize,
                         GEMM_SMEM_BYTES);
    cudaFuncSetAttribute(out_gemm_kernel,
                         cudaFuncAttributeMaxDynamicSharedMemorySize,
                         GEMM_SMEM_BYTES);
    cudaFuncSetAttribute(attn_mma_kernel,
                         cudaFuncAttributeMaxDynamicSharedMemorySize,
                         ATT_SMEM_BYTES);

    dim3 cvt_grid(1024, 5);
    dim3 proj_grid(24, PM / 128);         // (24, 64)
    dim3 attn_grid(PS / 128, PH, PB);     // (8, 16, 8)
    dim3 out_grid(PD / 128, PM / 128);    // (8, 64)

    cvt5_kernel<<<cvt_grid, 256>>>(query, value, Wq, Wkv, Wo,
                                   qin, vin, Wqh, Wkvh, Woh);
    proj_gemm_kernel<<<proj_grid, 256, GEMM_SMEM_BYTES>>>(bq, bkv, Qh, Kh, Vh);
    attn_mma_kernel<<<attn_grid, 256, ATT_SMEM_BYTES>>>(Qh, Kh, Vh, Hh);
    out_gemm_kernel<<<out_grid, 256, GEMM_SMEM_BYTES>>>(bo, out);
}